// round 5
// baseline (speedup 1.0000x reference)
#include <cuda_runtime.h>

// Problem constants
#define S_    2048
#define B_    2
#define E_    1024
#define H_    16
#define D_    64
#define HD_   1024
#define Q3_   3072
#define NROWS (S_ * B_)   // 4096 rows, row index = s*B + b

// ---------------------------------------------------------------------------
// Scratch (device globals: cudaMalloc is forbidden by the harness)
// ---------------------------------------------------------------------------
__device__ __align__(16) float g_ln [(size_t)NROWS * E_];    // 16 MB
__device__ __align__(16) float g_qkv[(size_t)NROWS * Q3_];   // 48 MB
__device__ __align__(16) float g_ctx[(size_t)NROWS * HD_];   // 16 MB

// ---------------------------------------------------------------------------
// Kernel 1: LayerNorm (scale-only), one block per row of E=1024
// ---------------------------------------------------------------------------
__global__ void ln_kernel(const float* __restrict__ x,
                          const float* __restrict__ scale,
                          float* __restrict__ out) {
    __shared__ float red_s[8];
    __shared__ float red_ss[8];
    const int row = blockIdx.x;            // 4096 rows
    const int t   = threadIdx.x;           // 256 threads, 4 elems each
    const float* xr = x + (size_t)row * E_;

    float4 v = *(const float4*)&xr[t * 4];
    float s  = v.x + v.y + v.z + v.w;
    float ss = v.x * v.x + v.y * v.y + v.z * v.z + v.w * v.w;

    #pragma unroll
    for (int o = 16; o; o >>= 1) {
        s  += __shfl_xor_sync(0xFFFFFFFFu, s,  o);
        ss += __shfl_xor_sync(0xFFFFFFFFu, ss, o);
    }
    if ((t & 31) == 0) { red_s[t >> 5] = s; red_ss[t >> 5] = ss; }
    __syncthreads();
    if (t < 32) {
        float s2  = (t < 8) ? red_s[t]  : 0.f;
        float ss2 = (t < 8) ? red_ss[t] : 0.f;
        #pragma unroll
        for (int o = 4; o; o >>= 1) {
            s2  += __shfl_xor_sync(0xFFFFFFFFu, s2,  o);
            ss2 += __shfl_xor_sync(0xFFFFFFFFu, ss2, o);
        }
        if (t == 0) { red_s[0] = s2; red_ss[0] = ss2; }
    }
    __syncthreads();

    const float inv_e = 1.f / (float)E_;
    float mu  = red_s[0] * inv_e;
    float var = red_ss[0] * inv_e - mu * mu;
    float r   = rsqrtf(var + 1e-6f);

    float4 sc = *(const float4*)&scale[t * 4];
    float4 o;
    o.x = (v.x - mu) * r * sc.x;
    o.y = (v.y - mu) * r * sc.y;
    o.z = (v.z - mu) * r * sc.z;
    o.w = (v.w - mu) * r * sc.w;
    *(float4*)&out[(size_t)row * E_ + t * 4] = o;
}

// ---------------------------------------------------------------------------
// Kernel 2/4: tiled SGEMM  C[M,N] = A[M,K] * B[K,N]   (row-major, all dims
// multiples of the tile sizes for this problem: M=4096, N in {3072,1024}, K=1024)
// BM=BN=128, BK=16, 256 threads, 8x8 per-thread micro-tile.
// ---------------------------------------------------------------------------
#define BM 128
#define BN 128
#define BK 16
#define TM 8
#define TN 8

__global__ __launch_bounds__(256)
void sgemm_kernel(const float* __restrict__ A, const float* __restrict__ B,
                  float* __restrict__ C, int M, int N, int K) {
    __shared__ float As[BK][BM];     // stored transposed for conflict-free reads
    __shared__ float Bs[BK][BN];

    const int tid = threadIdx.x;               // 256
    const int tx  = tid & 15;                  // 16 cols of threads
    const int ty  = tid >> 4;                  // 16 rows of threads
    const int blockRow = blockIdx.y * BM;
    const int blockCol = blockIdx.x * BN;

    float acc[TM][TN] = {};

    for (int k0 = 0; k0 < K; k0 += BK) {
        // Load A tile (BM x BK = 512 float4) and B tile (BK x BN = 512 float4)
        #pragma unroll
        for (int it = 0; it < 2; it++) {
            int i4 = tid + it * 256;
            // A: row = i4/4 (4 float4 per 16-wide row), col = (i4%4)*4
            int ar = i4 >> 2, ac = (i4 & 3) << 2;
            float4 av = *(const float4*)&A[(size_t)(blockRow + ar) * K + k0 + ac];
            As[ac + 0][ar] = av.x;
            As[ac + 1][ar] = av.y;
            As[ac + 2][ar] = av.z;
            As[ac + 3][ar] = av.w;
            // B: row = i4/32 (32 float4 per 128-wide row), col = (i4%32)*4
            int br = i4 >> 5, bc = (i4 & 31) << 2;
            *(float4*)&Bs[br][bc] =
                *(const float4*)&B[(size_t)(k0 + br) * N + blockCol + bc];
        }
        __syncthreads();

        #pragma unroll
        for (int k = 0; k < BK; k++) {
            float af[TM], bf[TN];
            float4 a0 = *(const float4*)&As[k][ty * TM];
            float4 a1 = *(const float4*)&As[k][ty * TM + 4];
            af[0]=a0.x; af[1]=a0.y; af[2]=a0.z; af[3]=a0.w;
            af[4]=a1.x; af[5]=a1.y; af[6]=a1.z; af[7]=a1.w;
            float4 b0 = *(const float4*)&Bs[k][tx * TN];
            float4 b1 = *(const float4*)&Bs[k][tx * TN + 4];
            bf[0]=b0.x; bf[1]=b0.y; bf[2]=b0.z; bf[3]=b0.w;
            bf[4]=b1.x; bf[5]=b1.y; bf[6]=b1.z; bf[7]=b1.w;
            #pragma unroll
            for (int i = 0; i < TM; i++)
                #pragma unroll
                for (int j = 0; j < TN; j++)
                    acc[i][j] += af[i] * bf[j];
        }
        __syncthreads();
    }

    #pragma unroll
    for (int i = 0; i < TM; i++) {
        int row = blockRow + ty * TM + i;
        #pragma unroll
        for (int j = 0; j < TN; j += 4) {
            float4 v = make_float4(acc[i][j], acc[i][j+1], acc[i][j+2], acc[i][j+3]);
            *(float4*)&C[(size_t)row * N + blockCol + tx * TN + j] = v;
        }
    }
}

// ---------------------------------------------------------------------------
// Kernel 3: flash attention.
// Grid: (S/128, B*H). 128 threads, one query row per thread.
// Online softmax over key tiles of 64, K/V staged in shared memory.
// q[64] and acc[64] live in registers; scores chunked by 16 to bound regs.
// ---------------------------------------------------------------------------
#define BR 128
#define BC 64

__global__ __launch_bounds__(BR)
void attn_kernel(const float* __restrict__ qkv, float* __restrict__ ctx) {
    __shared__ float Ks[BC][D_];   // 16 KB
    __shared__ float Vs[BC][D_];   // 16 KB

    const int t  = threadIdx.x;                 // 0..127
    const int qr = blockIdx.x * BR + t;         // query position s
    const int bh = blockIdx.y;                  // 0..31
    const int b  = bh & (B_ - 1);
    const int h  = bh >> 1;

    // Load this thread's query row into registers
    float q[D_];
    {
        const size_t qoff = ((size_t)qr * B_ + b) * Q3_ + h * D_;
        #pragma unroll
        for (int d = 0; d < D_; d += 4) {
            float4 v = *(const float4*)&qkv[qoff + d];
            q[d] = v.x; q[d+1] = v.y; q[d+2] = v.z; q[d+3] = v.w;
        }
    }

    float m = -1e30f, l = 0.f;
    float acc[D_] = {};

    for (int kc = 0; kc < S_; kc += BC) {
        __syncthreads();
        // Cooperative K/V tile load: 64 rows x 16 float4 each.
        // idx over float4s: consecutive threads cover consecutive float4s
        // within a row (coalesced per 64B chunk).
        for (int i4 = t; i4 < BC * (D_ / 4); i4 += BR) {
            int r = i4 >> 4;                 // key row in tile
            int c = (i4 & 15) << 2;          // float offset
            size_t koff = ((size_t)(kc + r) * B_ + b) * Q3_ + HD_ + h * D_ + c;
            *(float4*)&Ks[r][c] = *(const float4*)&qkv[koff];
            *(float4*)&Vs[r][c] = *(const float4*)&qkv[koff + HD_];
        }
        __syncthreads();

        #pragma unroll
        for (int jc = 0; jc < BC; jc += 16) {
            float sc[16];
            #pragma unroll
            for (int j = 0; j < 16; j++) {
                float sum = 0.f;
                #pragma unroll
                for (int d = 0; d < D_; d += 4) {
                    float4 kv = *(const float4*)&Ks[jc + j][d];   // broadcast LDS
                    sum += q[d]   * kv.x;
                    sum += q[d+1] * kv.y;
                    sum += q[d+2] * kv.z;
                    sum += q[d+3] * kv.w;
                }
                sc[j] = sum;
            }
            float cmax = sc[0];
            #pragma unroll
            for (int j = 1; j < 16; j++) cmax = fmaxf(cmax, sc[j]);
            float m_new = fmaxf(m, cmax);
            float alpha = __expf(m - m_new);
            m = m_new;
            l *= alpha;
            #pragma unroll
            for (int d = 0; d < D_; d++) acc[d] *= alpha;
            #pragma unroll
            for (int j = 0; j < 16; j++) {
                float p = __expf(sc[j] - m);
                l += p;
                #pragma unroll
                for (int d = 0; d < D_; d += 4) {
                    float4 vv = *(const float4*)&Vs[jc + j][d];   // broadcast LDS
                    acc[d]   += p * vv.x;
                    acc[d+1] += p * vv.y;
                    acc[d+2] += p * vv.z;
                    acc[d+3] += p * vv.w;
                }
            }
        }
    }

    const float inv = 1.f / l;
    const size_t coff = ((size_t)qr * B_ + b) * HD_ + h * D_;
    #pragma unroll
    for (int d = 0; d < D_; d += 4) {
        float4 o = make_float4(acc[d] * inv, acc[d+1] * inv,
                               acc[d+2] * inv, acc[d+3] * inv);
        *(float4*)&ctx[coff + d] = o;
    }
}

// ---------------------------------------------------------------------------
// kernel_launch: LN -> QKV GEMM -> flash attention -> output GEMM
// ---------------------------------------------------------------------------
extern "C" void kernel_launch(void* const* d_in, const int* in_sizes, int n_in,
                              void* d_out, int out_size) {
    const float* x        = (const float*)d_in[0];   // [S,B,E]
    const float* ln_scale = (const float*)d_in[1];   // [E]
    const float* w_qkv    = (const float*)d_in[2];   // [E, 3*H*D]
    const float* w_out    = (const float*)d_in[3];   // [H*D, E]
    float* out = (float*)d_out;                      // [S,B,E]

    float *p_ln, *p_qkv, *p_ctx;
    cudaGetSymbolAddress((void**)&p_ln,  g_ln);
    cudaGetSymbolAddress((void**)&p_qkv, g_qkv);
    cudaGetSymbolAddress((void**)&p_ctx, g_ctx);

    // 1. LayerNorm
    ln_kernel<<<NROWS, 256>>>(x, ln_scale, p_ln);

    // 2. QKV projection: [4096,1024] x [1024,3072]
    {
        dim3 grid(Q3_ / BN, NROWS / BM);
        sgemm_kernel<<<grid, 256>>>(p_ln, w_qkv, p_qkv, NROWS, Q3_, E_);
    }

    // 3. Flash attention: (S/128) x (B*H) blocks
    {
        dim3 grid(S_ / BR, B_ * H_);
        attn_kernel<<<grid, BR>>>(p_qkv, p_ctx);
    }

    // 4. Output projection: [4096,1024] x [1024,1024]
    {
        dim3 grid(E_ / BN, NROWS / BM);
        sgemm_kernel<<<grid, 256>>>(p_ctx, w_out, out, NROWS, E_, HD_);
    }
}

// round 6
// speedup vs baseline: 1.6206x; 1.6206x over previous
#include <cuda_runtime.h>

// Problem constants
#define S_    2048
#define B_    2
#define E_    1024
#define H_    16
#define D_    64
#define HD_   1024
#define Q3_   3072
#define NROWS (S_ * B_)   // 4096 rows, row index = s*B + b

// ---------------------------------------------------------------------------
// Scratch (device globals: cudaMalloc is forbidden by the harness)
// ---------------------------------------------------------------------------
__device__ __align__(16) float g_ln [(size_t)NROWS * E_];    // 16 MB
__device__ __align__(16) float g_qkv[(size_t)NROWS * Q3_];   // 48 MB
__device__ __align__(16) float g_ctx[(size_t)NROWS * HD_];   // 16 MB

// ---------------------------------------------------------------------------
// Kernel 1: LayerNorm (scale-only), one block per row of E=1024
// ---------------------------------------------------------------------------
__global__ void ln_kernel(const float* __restrict__ x,
                          const float* __restrict__ scale,
                          float* __restrict__ out) {
    __shared__ float red_s[8];
    __shared__ float red_ss[8];
    const int row = blockIdx.x;            // 4096 rows
    const int t   = threadIdx.x;           // 256 threads, 4 elems each
    const float* xr = x + (size_t)row * E_;

    float4 v = *(const float4*)&xr[t * 4];
    float s  = v.x + v.y + v.z + v.w;
    float ss = v.x * v.x + v.y * v.y + v.z * v.z + v.w * v.w;

    #pragma unroll
    for (int o = 16; o; o >>= 1) {
        s  += __shfl_xor_sync(0xFFFFFFFFu, s,  o);
        ss += __shfl_xor_sync(0xFFFFFFFFu, ss, o);
    }
    if ((t & 31) == 0) { red_s[t >> 5] = s; red_ss[t >> 5] = ss; }
    __syncthreads();
    if (t < 32) {
        float s2  = (t < 8) ? red_s[t]  : 0.f;
        float ss2 = (t < 8) ? red_ss[t] : 0.f;
        #pragma unroll
        for (int o = 4; o; o >>= 1) {
            s2  += __shfl_xor_sync(0xFFFFFFFFu, s2,  o);
            ss2 += __shfl_xor_sync(0xFFFFFFFFu, ss2, o);
        }
        if (t == 0) { red_s[0] = s2; red_ss[0] = ss2; }
    }
    __syncthreads();

    const float inv_e = 1.f / (float)E_;
    float mu  = red_s[0] * inv_e;
    float var = red_ss[0] * inv_e - mu * mu;
    float r   = rsqrtf(var + 1e-6f);

    float4 sc = *(const float4*)&scale[t * 4];
    float4 o;
    o.x = (v.x - mu) * r * sc.x;
    o.y = (v.y - mu) * r * sc.y;
    o.z = (v.z - mu) * r * sc.z;
    o.w = (v.w - mu) * r * sc.w;
    *(float4*)&out[(size_t)row * E_ + t * 4] = o;
}

// ---------------------------------------------------------------------------
// Kernel 2/4: tiled SGEMM  C[M,N] = A[M,K] * B[K,N]
// BM=BN=128, BK=16, 256 threads, 8x8 per-thread micro-tile. (unchanged)
// ---------------------------------------------------------------------------
#define BM 128
#define BN 128
#define BK 16
#define TM 8
#define TN 8

__global__ __launch_bounds__(256)
void sgemm_kernel(const float* __restrict__ A, const float* __restrict__ B,
                  float* __restrict__ C, int M, int N, int K) {
    __shared__ float As[BK][BM];     // stored transposed for conflict-free reads
    __shared__ float Bs[BK][BN];

    const int tid = threadIdx.x;               // 256
    const int tx  = tid & 15;                  // 16 cols of threads
    const int ty  = tid >> 4;                  // 16 rows of threads
    const int blockRow = blockIdx.y * BM;
    const int blockCol = blockIdx.x * BN;

    float acc[TM][TN] = {};

    for (int k0 = 0; k0 < K; k0 += BK) {
        #pragma unroll
        for (int it = 0; it < 2; it++) {
            int i4 = tid + it * 256;
            int ar = i4 >> 2, ac = (i4 & 3) << 2;
            float4 av = *(const float4*)&A[(size_t)(blockRow + ar) * K + k0 + ac];
            As[ac + 0][ar] = av.x;
            As[ac + 1][ar] = av.y;
            As[ac + 2][ar] = av.z;
            As[ac + 3][ar] = av.w;
            int br = i4 >> 5, bc = (i4 & 31) << 2;
            *(float4*)&Bs[br][bc] =
                *(const float4*)&B[(size_t)(k0 + br) * N + blockCol + bc];
        }
        __syncthreads();

        #pragma unroll
        for (int k = 0; k < BK; k++) {
            float af[TM], bf[TN];
            float4 a0 = *(const float4*)&As[k][ty * TM];
            float4 a1 = *(const float4*)&As[k][ty * TM + 4];
            af[0]=a0.x; af[1]=a0.y; af[2]=a0.z; af[3]=a0.w;
            af[4]=a1.x; af[5]=a1.y; af[6]=a1.z; af[7]=a1.w;
            float4 b0 = *(const float4*)&Bs[k][tx * TN];
            float4 b1 = *(const float4*)&Bs[k][tx * TN + 4];
            bf[0]=b0.x; bf[1]=b0.y; bf[2]=b0.z; bf[3]=b0.w;
            bf[4]=b1.x; bf[5]=b1.y; bf[6]=b1.z; bf[7]=b1.w;
            #pragma unroll
            for (int i = 0; i < TM; i++)
                #pragma unroll
                for (int j = 0; j < TN; j++)
                    acc[i][j] += af[i] * bf[j];
        }
        __syncthreads();
    }

    #pragma unroll
    for (int i = 0; i < TM; i++) {
        int row = blockRow + ty * TM + i;
        #pragma unroll
        for (int j = 0; j < TN; j += 4) {
            float4 v = make_float4(acc[i][j], acc[i][j+1], acc[i][j+2], acc[i][j+3]);
            *(float4*)&C[(size_t)row * N + blockCol + tx * TN + j] = v;
        }
    }
}

// ---------------------------------------------------------------------------
// Kernel 3: register-tiled flash attention (flash-2 style).
// Block: 128 queries x full D, key tiles of 64. 128 threads = 16x8 grid,
// each thread owns an 8x8 micro-tile (8 queries x 8 keys in score phase,
// 8 queries x 8 d-dims in PV phase; same 8 queries both phases).
// Smem: Qt[d][q] (transposed, loaded once), Kt[d][k] (transposed per tile),
// Vs[k][d] (row-major per tile), Pt[k][q] (probs round-trip, vectorized).
// Row softmax stats reduced across the 8 key-lanes via shfl_xor(1,2,4).
// ---------------------------------------------------------------------------
#define BQA 128
#define BKA 64

__global__ __launch_bounds__(128)
void attn_kernel(const float* __restrict__ qkv, float* __restrict__ ctx) {
    extern __shared__ float smf[];
    float* Qt = smf;                          // [64][128]  32 KB
    float* Kt = Qt + 64 * 128;                // [64][64]   16 KB
    float* Vs = Kt + 64 * 64;                 // [64][64]   16 KB
    float* Pt = Vs + 64 * 64;                 // [64][128]  32 KB

    const int tid  = threadIdx.x;
    const int trow = tid >> 3;                // 0..15  -> queries 8*trow..+8
    const int tcol = tid & 7;                 // 0..7   -> keys/d 8*tcol..+8
    const int bh   = blockIdx.y;              // 0..31
    const int b    = bh & (B_ - 1);
    const int h    = bh >> 1;
    const int q0   = blockIdx.x * BQA;

    // Load Q tile transposed: Qt[d][q]. Lane-per-row assignment ->
    // conflict-free scalar STS (bank = q % 32 = lane).
    #pragma unroll
    for (int it = 0; it < 16; it++) {
        int idx = tid + it * 128;             // 0..2047
        int q   = idx & 127;
        int c4  = idx >> 7;                   // 0..15
        float4 v = *(const float4*)&qkv[(size_t)((q0 + q) * B_ + b) * Q3_ +
                                        h * D_ + c4 * 4];
        Qt[(c4 * 4 + 0) * 128 + q] = v.x;
        Qt[(c4 * 4 + 1) * 128 + q] = v.y;
        Qt[(c4 * 4 + 2) * 128 + q] = v.z;
        Qt[(c4 * 4 + 3) * 128 + q] = v.w;
    }

    float acc[8][8];
    float m[8], l[8];
    #pragma unroll
    for (int i = 0; i < 8; i++) {
        m[i] = -1e30f; l[i] = 0.f;
        #pragma unroll
        for (int j = 0; j < 8; j++) acc[i][j] = 0.f;
    }

    for (int kc = 0; kc < S_; kc += BKA) {
        // Separates prev-tile PV reads (Pt,Vs) and first-iter Qt writes
        // from this tile's smem writes.
        __syncthreads();

        // K tile transposed: Kt[d][k]. bank = row%32 = lane -> conflict-free.
        #pragma unroll
        for (int it = 0; it < 8; it++) {
            int idx = tid + it * 128;         // 0..1023
            int r   = idx & 63;               // key row
            int c4  = idx >> 6;               // 0..15
            float4 v = *(const float4*)&qkv[(size_t)((kc + r) * B_ + b) * Q3_ +
                                            HD_ + h * D_ + c4 * 4];
            Kt[(c4 * 4 + 0) * 64 + r] = v.x;
            Kt[(c4 * 4 + 1) * 64 + r] = v.y;
            Kt[(c4 * 4 + 2) * 64 + r] = v.z;
            Kt[(c4 * 4 + 3) * 64 + r] = v.w;
        }
        // V tile row-major: Vs[k][d], coalesced loads + vector stores.
        #pragma unroll
        for (int it = 0; it < 8; it++) {
            int idx = tid + it * 128;
            int r   = idx >> 4;               // 0..63
            int c   = (idx & 15) << 2;
            *(float4*)&Vs[r * 64 + c] =
                *(const float4*)&qkv[(size_t)((kc + r) * B_ + b) * Q3_ +
                                     2 * HD_ + h * D_ + c];
        }
        __syncthreads();

        // ---- Score GEMM: s[8q][8k] = Q(8q,:) . K(8k,:)^T ----
        float s[8][8];
        #pragma unroll
        for (int i = 0; i < 8; i++)
            #pragma unroll
            for (int j = 0; j < 8; j++) s[i][j] = 0.f;

        #pragma unroll 8
        for (int d = 0; d < D_; d++) {
            float av[8], bv[8];
            float4 a0 = *(const float4*)&Qt[d * 128 + trow * 8];
            float4 a1 = *(const float4*)&Qt[d * 128 + trow * 8 + 4];
            av[0]=a0.x; av[1]=a0.y; av[2]=a0.z; av[3]=a0.w;
            av[4]=a1.x; av[5]=a1.y; av[6]=a1.z; av[7]=a1.w;
            float4 b0 = *(const float4*)&Kt[d * 64 + tcol * 8];
            float4 b1 = *(const float4*)&Kt[d * 64 + tcol * 8 + 4];
            bv[0]=b0.x; bv[1]=b0.y; bv[2]=b0.z; bv[3]=b0.w;
            bv[4]=b1.x; bv[5]=b1.y; bv[6]=b1.z; bv[7]=b1.w;
            #pragma unroll
            for (int i = 0; i < 8; i++)
                #pragma unroll
                for (int j = 0; j < 8; j++)
                    s[i][j] += av[i] * bv[j];
        }

        // ---- Online softmax (row stats across the 8 key-lanes) ----
        #pragma unroll
        for (int i = 0; i < 8; i++) {
            float rm = s[i][0];
            #pragma unroll
            for (int j = 1; j < 8; j++) rm = fmaxf(rm, s[i][j]);
            rm = fmaxf(rm, __shfl_xor_sync(0xFFFFFFFFu, rm, 1));
            rm = fmaxf(rm, __shfl_xor_sync(0xFFFFFFFFu, rm, 2));
            rm = fmaxf(rm, __shfl_xor_sync(0xFFFFFFFFu, rm, 4));
            float mnew = fmaxf(m[i], rm);
            float al   = __expf(m[i] - mnew);
            m[i] = mnew;
            float rs = 0.f;
            #pragma unroll
            for (int j = 0; j < 8; j++) {
                float p = __expf(s[i][j] - mnew);
                s[i][j] = p;
                rs += p;
            }
            rs += __shfl_xor_sync(0xFFFFFFFFu, rs, 1);
            rs += __shfl_xor_sync(0xFFFFFFFFu, rs, 2);
            rs += __shfl_xor_sync(0xFFFFFFFFu, rs, 4);
            l[i] = l[i] * al + rs;
            #pragma unroll
            for (int j = 0; j < 8; j++) acc[i][j] *= al;
        }

        // ---- Write P transposed: Pt[k][q], vectorized along q ----
        #pragma unroll
        for (int j = 0; j < 8; j++) {
            int k = tcol * 8 + j;
            *(float4*)&Pt[k * 128 + trow * 8] =
                make_float4(s[0][j], s[1][j], s[2][j], s[3][j]);
            *(float4*)&Pt[k * 128 + trow * 8 + 4] =
                make_float4(s[4][j], s[5][j], s[6][j], s[7][j]);
        }
        __syncthreads();

        // ---- PV GEMM: acc[8q][8d] += P(8q,:) . V(:,8d) ----
        #pragma unroll 8
        for (int k = 0; k < BKA; k++) {
            float pv[8], vv[8];
            float4 p0 = *(const float4*)&Pt[k * 128 + trow * 8];
            float4 p1 = *(const float4*)&Pt[k * 128 + trow * 8 + 4];
            pv[0]=p0.x; pv[1]=p0.y; pv[2]=p0.z; pv[3]=p0.w;
            pv[4]=p1.x; pv[5]=p1.y; pv[6]=p1.z; pv[7]=p1.w;
            float4 v0 = *(const float4*)&Vs[k * 64 + tcol * 8];
            float4 v1 = *(const float4*)&Vs[k * 64 + tcol * 8 + 4];
            vv[0]=v0.x; vv[1]=v0.y; vv[2]=v0.z; vv[3]=v0.w;
            vv[4]=v1.x; vv[5]=v1.y; vv[6]=v1.z; vv[7]=v1.w;
            #pragma unroll
            for (int i = 0; i < 8; i++)
                #pragma unroll
                for (int j = 0; j < 8; j++)
                    acc[i][j] += pv[i] * vv[j];
        }
    }

    // ---- Epilogue: normalize and store ctx ----
    #pragma unroll
    for (int i = 0; i < 8; i++) {
        float inv = 1.f / l[i];
        int q = q0 + trow * 8 + i;
        float* dst = &ctx[(size_t)(q * B_ + b) * HD_ + h * D_ + tcol * 8];
        *(float4*)dst =
            make_float4(acc[i][0]*inv, acc[i][1]*inv, acc[i][2]*inv, acc[i][3]*inv);
        *(float4*)(dst + 4) =
            make_float4(acc[i][4]*inv, acc[i][5]*inv, acc[i][6]*inv, acc[i][7]*inv);
    }
}

// ---------------------------------------------------------------------------
// kernel_launch: LN -> QKV GEMM -> flash attention -> output GEMM
// ---------------------------------------------------------------------------
extern "C" void kernel_launch(void* const* d_in, const int* in_sizes, int n_in,
                              void* d_out, int out_size) {
    const float* x        = (const float*)d_in[0];   // [S,B,E]
    const float* ln_scale = (const float*)d_in[1];   // [E]
    const float* w_qkv    = (const float*)d_in[2];   // [E, 3*H*D]
    const float* w_out    = (const float*)d_in[3];   // [H*D, E]
    float* out = (float*)d_out;                      // [S,B,E]

    float *p_ln, *p_qkv, *p_ctx;
    cudaGetSymbolAddress((void**)&p_ln,  g_ln);
    cudaGetSymbolAddress((void**)&p_qkv, g_qkv);
    cudaGetSymbolAddress((void**)&p_ctx, g_ctx);

    // 1. LayerNorm
    ln_kernel<<<NROWS, 256>>>(x, ln_scale, p_ln);

    // 2. QKV projection: [4096,1024] x [1024,3072]
    {
        dim3 grid(Q3_ / BN, NROWS / BM);
        sgemm_kernel<<<grid, 256>>>(p_ln, w_qkv, p_qkv, NROWS, Q3_, E_);
    }

    // 3. Flash attention: (S/128) x (B*H) blocks, 96 KB dynamic smem
    {
        const int smem_bytes = (64 * 128 + 64 * 64 + 64 * 64 + 64 * 128) * 4;
        cudaFuncSetAttribute(attn_kernel,
                             cudaFuncAttributeMaxDynamicSharedMemorySize,
                             smem_bytes);
        dim3 grid(S_ / BQA, B_ * H_);
        attn_kernel<<<grid, 128, smem_bytes>>>(p_qkv, p_ctx);
    }

    // 4. Output projection: [4096,1024] x [1024,1024]
    {
        dim3 grid(E_ / BN, NROWS / BM);
        sgemm_kernel<<<grid, 256>>>(p_ctx, w_out, out, NROWS, E_, HD_);
    }
}

// round 8
// speedup vs baseline: 2.2942x; 1.4156x over previous
#include <cuda_runtime.h>
#include <cuda_bf16.h>
#include <cstdint>

// Problem constants
#define S_    2048
#define B_    2
#define E_    1024
#define H_    16
#define D_    64
#define HD_   1024
#define Q3_   3072
#define NROWS (S_ * B_)   // 4096 rows, row index = s*B + b

// ---------------------------------------------------------------------------
// Scratch (device globals: cudaMalloc is forbidden by the harness)
// ---------------------------------------------------------------------------
__device__ __align__(16) float g_qkv[(size_t)NROWS * Q3_];              // 48 MB
__device__ __align__(16) __nv_bfloat16 g_a0[(size_t)NROWS * E_];        // LN out hi
__device__ __align__(16) __nv_bfloat16 g_a1[(size_t)NROWS * E_];        // LN out lo
__device__ __align__(16) __nv_bfloat16 g_wq0[(size_t)Q3_ * E_];         // w_qkv^T hi [3072,1024]
__device__ __align__(16) __nv_bfloat16 g_wq1[(size_t)Q3_ * E_];
__device__ __align__(16) __nv_bfloat16 g_wo0[(size_t)E_ * HD_];         // w_out^T hi [1024,1024]
__device__ __align__(16) __nv_bfloat16 g_wo1[(size_t)E_ * HD_];
__device__ __align__(16) __nv_bfloat16 g_c0[(size_t)NROWS * HD_];       // ctx hi
__device__ __align__(16) __nv_bfloat16 g_c1[(size_t)NROWS * HD_];       // ctx lo

// ---------------------------------------------------------------------------
// PTX helpers: arch-agnostic tensor path (mma.sync / ldmatrix / cp.async).
// tcgen05 is NOT usable here: the harness PTX stage targets compute_103
// (no 'a'), which rejects all tcgen05 instructions.
// ---------------------------------------------------------------------------
__device__ __forceinline__ uint32_t smem_u32(const void* p) {
    return (uint32_t)__cvta_generic_to_shared(p);
}

__device__ __forceinline__ void cp16(uint32_t saddr, const void* g) {
    asm volatile("cp.async.cg.shared.global [%0], [%1], 16;"
                 :: "r"(saddr), "l"(g));
}
#define CP_COMMIT() asm volatile("cp.async.commit_group;" ::: "memory")
#define CP_WAIT(n)  asm volatile("cp.async.wait_group %0;" :: "n"(n) : "memory")

__device__ __forceinline__ void ldsm4(uint32_t* r, uint32_t addr) {
    asm volatile("ldmatrix.sync.aligned.m8n8.x4.shared.b16 {%0,%1,%2,%3}, [%4];"
                 : "=r"(r[0]), "=r"(r[1]), "=r"(r[2]), "=r"(r[3]) : "r"(addr));
}

__device__ __forceinline__ void mma_bf16(float* c, const uint32_t* a,
                                         const uint32_t* b) {
    asm volatile(
        "mma.sync.aligned.m16n8k16.row.col.f32.bf16.bf16.f32 "
        "{%0,%1,%2,%3}, {%4,%5,%6,%7}, {%8,%9}, {%0,%1,%2,%3};"
        : "+f"(c[0]), "+f"(c[1]), "+f"(c[2]), "+f"(c[3])
        : "r"(a[0]), "r"(a[1]), "r"(a[2]), "r"(a[3]), "r"(b[0]), "r"(b[1]));
}

// Swizzled smem offset for a [128 x 32] bf16 tile stored as 64-byte rows of
// four 16B chunks: chunk' = c ^ ((r>>1)&3). Conflict-free for cp.async fill
// and ldmatrix reads (bank group = (r%2)*4 + chunk', 8 distinct per 8 rows).
__device__ __forceinline__ uint32_t soff(int r, int c) {
    return (uint32_t)(r * 64 + ((c ^ ((r >> 1) & 3)) << 4));
}

// ---------------------------------------------------------------------------
// Kernel 1: LayerNorm (scale-only) fused with bf16 hi/lo split
// ---------------------------------------------------------------------------
__global__ void ln_split_kernel(const float* __restrict__ x,
                                const float* __restrict__ scale,
                                __nv_bfloat16* __restrict__ a0,
                                __nv_bfloat16* __restrict__ a1) {
    __shared__ float red_s[8];
    __shared__ float red_ss[8];
    const int row = blockIdx.x;            // 4096 rows
    const int t   = threadIdx.x;           // 256 threads, 4 elems each
    const float* xr = x + (size_t)row * E_;

    float4 v = *(const float4*)&xr[t * 4];
    float s  = v.x + v.y + v.z + v.w;
    float ss = v.x * v.x + v.y * v.y + v.z * v.z + v.w * v.w;

    #pragma unroll
    for (int o = 16; o; o >>= 1) {
        s  += __shfl_xor_sync(0xFFFFFFFFu, s,  o);
        ss += __shfl_xor_sync(0xFFFFFFFFu, ss, o);
    }
    if ((t & 31) == 0) { red_s[t >> 5] = s; red_ss[t >> 5] = ss; }
    __syncthreads();
    if (t < 32) {
        float s2  = (t < 8) ? red_s[t]  : 0.f;
        float ss2 = (t < 8) ? red_ss[t] : 0.f;
        #pragma unroll
        for (int o = 4; o; o >>= 1) {
            s2  += __shfl_xor_sync(0xFFFFFFFFu, s2,  o);
            ss2 += __shfl_xor_sync(0xFFFFFFFFu, ss2, o);
        }
        if (t == 0) { red_s[0] = s2; red_ss[0] = ss2; }
    }
    __syncthreads();

    const float inv_e = 1.f / (float)E_;
    float mu  = red_s[0] * inv_e;
    float var = red_ss[0] * inv_e - mu * mu;
    float r   = rsqrtf(var + 1e-6f);

    float4 sc = *(const float4*)&scale[t * 4];
    float ov[4];
    ov[0] = (v.x - mu) * r * sc.x;
    ov[1] = (v.y - mu) * r * sc.y;
    ov[2] = (v.z - mu) * r * sc.z;
    ov[3] = (v.w - mu) * r * sc.w;

    const size_t base = (size_t)row * E_ + t * 4;
    #pragma unroll
    for (int p = 0; p < 2; p++) {
        __nv_bfloat162 h, l;
        h.x = __float2bfloat16(ov[p * 2 + 0]);
        h.y = __float2bfloat16(ov[p * 2 + 1]);
        l.x = __float2bfloat16(ov[p * 2 + 0] - __bfloat162float(h.x));
        l.y = __float2bfloat16(ov[p * 2 + 1] - __bfloat162float(h.y));
        *(__nv_bfloat162*)&a0[base + p * 2] = h;
        *(__nv_bfloat162*)&a1[base + p * 2] = l;
    }
}

// ---------------------------------------------------------------------------
// Kernel 2: weight transpose + bf16 hi/lo split.
// W [K,N] row-major (fp32) -> hi/lo [N,K] row-major (K-major for MMA B operand)
// ---------------------------------------------------------------------------
__global__ __launch_bounds__(256)
void wsplit_kernel(const float* __restrict__ W,
                   __nv_bfloat16* __restrict__ hi,
                   __nv_bfloat16* __restrict__ lo, int K, int N) {
    __shared__ float tile[32][33];
    const int bx = blockIdx.x * 32;        // n base
    const int by = blockIdx.y * 32;        // k base
    const int tx = threadIdx.x & 31;
    const int ty = threadIdx.x >> 5;       // 0..7

    #pragma unroll
    for (int i = 0; i < 32; i += 8)
        tile[ty + i][tx] = W[(size_t)(by + ty + i) * N + bx + tx];
    __syncthreads();
    #pragma unroll
    for (int i = 0; i < 32; i += 8) {
        float v = tile[tx][ty + i];        // value at k = by+tx, n = bx+ty+i
        __nv_bfloat16 h = __float2bfloat16(v);
        __nv_bfloat16 l = __float2bfloat16(v - __bfloat162float(h));
        size_t off = (size_t)(bx + ty + i) * K + by + tx;
        hi[off] = h;
        lo[off] = l;
    }
}

// ---------------------------------------------------------------------------
// Kernel 3: HMMA (mma.sync bf16) GEMM with bf16x3 split:
//   C[M,N] = A0*B0 + A0*B1 + A1*B0   (A[M,K], B stored [N,K]; fp32 C)
// Tile 128x128, BK=32, 256 threads = 8 warps (4 x 2), warp tile 32x64.
// cp.async double-buffered smem: 2 stages x 4 tiles x 8KB = 64 KB.
// ---------------------------------------------------------------------------
#define GBM 128
#define GBN 128
#define GBK 32
#define TILE_B   8192                 // one 128x32 bf16 tile
#define STAGE_B  (4 * TILE_B)         // A0,A1,B0,B1
#define GSM_TOTAL (2 * STAGE_B)       // 64 KB

__global__ __launch_bounds__(256, 2)
void mma_gemm_kernel(const __nv_bfloat16* __restrict__ A0,
                     const __nv_bfloat16* __restrict__ A1,
                     const __nv_bfloat16* __restrict__ B0,
                     const __nv_bfloat16* __restrict__ B1,
                     float* __restrict__ C, int N, int K) {
    extern __shared__ char sm[];
    const uint32_t smb = smem_u32(sm);

    const int tid  = threadIdx.x;
    const int lane = tid & 31;
    const int wid  = tid >> 5;             // 0..7
    const int wm   = wid & 3;              // warp row: 32 rows each
    const int wn   = wid >> 2;             // warp col: 64 cols each
    const int blockRow = blockIdx.y * GBM;
    const int blockCol = blockIdx.x * GBN;

    float acc[2][8][4];
    #pragma unroll
    for (int i = 0; i < 2; i++)
        #pragma unroll
        for (int j = 0; j < 8; j++)
            #pragma unroll
            for (int q = 0; q < 4; q++) acc[i][j][q] = 0.f;

    // Per-thread load coords (2 chunks per tile per stage)
    const int r0 = (tid + 0)   >> 2, c0 = (tid + 0)   & 3;
    const int r1 = (tid + 256) >> 2, c1 = (tid + 256) & 3;
    const uint32_t so0 = soff(r0, c0), so1 = soff(r1, c1);

    const int NCH = K / GBK;

    // Prologue: stage 0
    {
        const uint32_t sb = smb;
        const __nv_bfloat16* ga = A0 + (size_t)(blockRow + r0) * K + c0 * 8;
        const __nv_bfloat16* gb = B0 + (size_t)(blockCol + r0) * K + c0 * 8;
        cp16(sb + so0,              ga);
        cp16(sb + TILE_B + so0,     A1 + (size_t)(blockRow + r0) * K + c0 * 8);
        cp16(sb + 2 * TILE_B + so0, gb);
        cp16(sb + 3 * TILE_B + so0, B1 + (size_t)(blockCol + r0) * K + c0 * 8);
        cp16(sb + so1,              A0 + (size_t)(blockRow + r1) * K + c1 * 8);
        cp16(sb + TILE_B + so1,     A1 + (size_t)(blockRow + r1) * K + c1 * 8);
        cp16(sb + 2 * TILE_B + so1, B0 + (size_t)(blockCol + r1) * K + c1 * 8);
        cp16(sb + 3 * TILE_B + so1, B1 + (size_t)(blockCol + r1) * K + c1 * 8);
        CP_COMMIT();
    }

    // ldmatrix per-thread base coords
    const int rA = wm * 32 + (lane & 15);              // + fm*16
    const int cAbase = lane >> 4;                      // + ks*2
    const int rB = wn * 64 + (lane & 7) + ((lane >> 4) << 3);   // + p*16
    const int cBbase = (lane >> 3) & 1;                // + ks*2

    for (int ch = 0; ch < NCH; ch++) {
        if (ch + 1 < NCH) {
            const uint32_t sb = smb + ((ch + 1) & 1) * STAGE_B;
            const int kb = (ch + 1) * GBK;
            cp16(sb + so0,              A0 + (size_t)(blockRow + r0) * K + kb + c0 * 8);
            cp16(sb + TILE_B + so0,     A1 + (size_t)(blockRow + r0) * K + kb + c0 * 8);
            cp16(sb + 2 * TILE_B + so0, B0 + (size_t)(blockCol + r0) * K + kb + c0 * 8);
            cp16(sb + 3 * TILE_B + so0, B1 + (size_t)(blockCol + r0) * K + kb + c0 * 8);
            cp16(sb + so1,              A0 + (size_t)(blockRow + r1) * K + kb + c1 * 8);
            cp16(sb + TILE_B + so1,     A1 + (size_t)(blockRow + r1) * K + kb + c1 * 8);
            cp16(sb + 2 * TILE_B + so1, B0 + (size_t)(blockCol + r1) * K + kb + c1 * 8);
            cp16(sb + 3 * TILE_B + so1, B1 + (size_t)(blockCol + r1) * K + kb + c1 * 8);
            CP_COMMIT();
            CP_WAIT(1);
        } else {
            CP_WAIT(0);
        }
        __syncthreads();   // stage ch resident for all warps

        const uint32_t sb  = smb + (ch & 1) * STAGE_B;
        const uint32_t sA0 = sb;
        const uint32_t sA1 = sb + TILE_B;
        const uint32_t sB0 = sb + 2 * TILE_B;
        const uint32_t sB1 = sb + 3 * TILE_B;

        #pragma unroll
        for (int ks = 0; ks < 2; ks++) {
            const int cA = ks * 2 + cAbase;
            const int cB = ks * 2 + cBbase;
            uint32_t a0f[2][4], a1f[2][4];
            #pragma unroll
            for (int fm = 0; fm < 2; fm++) {
                ldsm4(a0f[fm], sA0 + soff(rA + fm * 16, cA));
                ldsm4(a1f[fm], sA1 + soff(rA + fm * 16, cA));
            }
            uint32_t bf[4][4];
            // B0: A0*B0 and A1*B0
            #pragma unroll
            for (int p = 0; p < 4; p++)
                ldsm4(bf[p], sB0 + soff(rB + p * 16, cB));
            #pragma unroll
            for (int fm = 0; fm < 2; fm++)
                #pragma unroll
                for (int fn = 0; fn < 8; fn++) {
                    mma_bf16(acc[fm][fn], a0f[fm], &bf[fn >> 1][(fn & 1) * 2]);
                    mma_bf16(acc[fm][fn], a1f[fm], &bf[fn >> 1][(fn & 1) * 2]);
                }
            // B1: A0*B1
            #pragma unroll
            for (int p = 0; p < 4; p++)
                ldsm4(bf[p], sB1 + soff(rB + p * 16, cB));
            #pragma unroll
            for (int fm = 0; fm < 2; fm++)
                #pragma unroll
                for (int fn = 0; fn < 8; fn++)
                    mma_bf16(acc[fm][fn], a0f[fm], &bf[fn >> 1][(fn & 1) * 2]);
        }
        __syncthreads();   // all reads done before next stage overwrite
    }

    // Epilogue: fragment -> global (float2 per half-fragment)
    #pragma unroll
    for (int fm = 0; fm < 2; fm++) {
        const int rr = blockRow + wm * 32 + fm * 16 + (lane >> 2);
        #pragma unroll
        for (int fn = 0; fn < 8; fn++) {
            const int cc = blockCol + wn * 64 + fn * 8 + (lane & 3) * 2;
            *(float2*)&C[(size_t)rr * N + cc] =
                make_float2(acc[fm][fn][0], acc[fm][fn][1]);
            *(float2*)&C[(size_t)(rr + 8) * N + cc] =
                make_float2(acc[fm][fn][2], acc[fm][fn][3]);
        }
    }
}

// Wait: the A0*B0 and A1*B0 products above are issued as two mma on the same
// bf[] operand — that is intentional (same B fragment, different A).

// ---------------------------------------------------------------------------
// Kernel 4: register-tiled flash attention (fp32), epilogue writes bf16
// hi/lo split of ctx for the output-projection MMA.
// ---------------------------------------------------------------------------
#define BQA 128
#define BKA 64

__global__ __launch_bounds__(128)
void attn_kernel(const float* __restrict__ qkv,
                 __nv_bfloat16* __restrict__ c0,
                 __nv_bfloat16* __restrict__ c1) {
    extern __shared__ float smf[];
    float* Qt = smf;                          // [64][128]  32 KB
    float* Kt = Qt + 64 * 128;                // [64][64]   16 KB
    float* Vs = Kt + 64 * 64;                 // [64][64]   16 KB
    float* Pt = Vs + 64 * 64;                 // [64][128]  32 KB

    const int tid  = threadIdx.x;
    const int trow = tid >> 3;                // 0..15  -> queries 8*trow..+8
    const int tcol = tid & 7;                 // 0..7   -> keys/d 8*tcol..+8
    const int bh   = blockIdx.y;              // 0..31
    const int b    = bh & (B_ - 1);
    const int h    = bh >> 1;
    const int q0   = blockIdx.x * BQA;

    #pragma unroll
    for (int it = 0; it < 16; it++) {
        int idx = tid + it * 128;
        int q   = idx & 127;
        int c4  = idx >> 7;
        float4 v = *(const float4*)&qkv[(size_t)((q0 + q) * B_ + b) * Q3_ +
                                        h * D_ + c4 * 4];
        Qt[(c4 * 4 + 0) * 128 + q] = v.x;
        Qt[(c4 * 4 + 1) * 128 + q] = v.y;
        Qt[(c4 * 4 + 2) * 128 + q] = v.z;
        Qt[(c4 * 4 + 3) * 128 + q] = v.w;
    }

    float acc[8][8];
    float m[8], l[8];
    #pragma unroll
    for (int i = 0; i < 8; i++) {
        m[i] = -1e30f; l[i] = 0.f;
        #pragma unroll
        for (int j = 0; j < 8; j++) acc[i][j] = 0.f;
    }

    for (int kc = 0; kc < S_; kc += BKA) {
        __syncthreads();
        #pragma unroll
        for (int it = 0; it < 8; it++) {
            int idx = tid + it * 128;
            int r   = idx & 63;
            int c4  = idx >> 6;
            float4 v = *(const float4*)&qkv[(size_t)((kc + r) * B_ + b) * Q3_ +
                                            HD_ + h * D_ + c4 * 4];
            Kt[(c4 * 4 + 0) * 64 + r] = v.x;
            Kt[(c4 * 4 + 1) * 64 + r] = v.y;
            Kt[(c4 * 4 + 2) * 64 + r] = v.z;
            Kt[(c4 * 4 + 3) * 64 + r] = v.w;
        }
        #pragma unroll
        for (int it = 0; it < 8; it++) {
            int idx = tid + it * 128;
            int r   = idx >> 4;
            int c   = (idx & 15) << 2;
            *(float4*)&Vs[r * 64 + c] =
                *(const float4*)&qkv[(size_t)((kc + r) * B_ + b) * Q3_ +
                                     2 * HD_ + h * D_ + c];
        }
        __syncthreads();

        float s[8][8];
        #pragma unroll
        for (int i = 0; i < 8; i++)
            #pragma unroll
            for (int j = 0; j < 8; j++) s[i][j] = 0.f;

        #pragma unroll 8
        for (int d = 0; d < D_; d++) {
            float av[8], bv[8];
            float4 a0 = *(const float4*)&Qt[d * 128 + trow * 8];
            float4 a1 = *(const float4*)&Qt[d * 128 + trow * 8 + 4];
            av[0]=a0.x; av[1]=a0.y; av[2]=a0.z; av[3]=a0.w;
            av[4]=a1.x; av[5]=a1.y; av[6]=a1.z; av[7]=a1.w;
            float4 b0 = *(const float4*)&Kt[d * 64 + tcol * 8];
            float4 b1 = *(const float4*)&Kt[d * 64 + tcol * 8 + 4];
            bv[0]=b0.x; bv[1]=b0.y; bv[2]=b0.z; bv[3]=b0.w;
            bv[4]=b1.x; bv[5]=b1.y; bv[6]=b1.z; bv[7]=b1.w;
            #pragma unroll
            for (int i = 0; i < 8; i++)
                #pragma unroll
                for (int j = 0; j < 8; j++)
                    s[i][j] += av[i] * bv[j];
        }

        #pragma unroll
        for (int i = 0; i < 8; i++) {
            float rm = s[i][0];
            #pragma unroll
            for (int j = 1; j < 8; j++) rm = fmaxf(rm, s[i][j]);
            rm = fmaxf(rm, __shfl_xor_sync(0xFFFFFFFFu, rm, 1));
            rm = fmaxf(rm, __shfl_xor_sync(0xFFFFFFFFu, rm, 2));
            rm = fmaxf(rm, __shfl_xor_sync(0xFFFFFFFFu, rm, 4));
            float mnew = fmaxf(m[i], rm);
            float al   = __expf(m[i] - mnew);
            m[i] = mnew;
            float rs = 0.f;
            #pragma unroll
            for (int j = 0; j < 8; j++) {
                float p = __expf(s[i][j] - mnew);
                s[i][j] = p;
                rs += p;
            }
            rs += __shfl_xor_sync(0xFFFFFFFFu, rs, 1);
            rs += __shfl_xor_sync(0xFFFFFFFFu, rs, 2);
            rs += __shfl_xor_sync(0xFFFFFFFFu, rs, 4);
            l[i] = l[i] * al + rs;
            #pragma unroll
            for (int j = 0; j < 8; j++) acc[i][j] *= al;
        }

        #pragma unroll
        for (int j = 0; j < 8; j++) {
            int k = tcol * 8 + j;
            *(float4*)&Pt[k * 128 + trow * 8] =
                make_float4(s[0][j], s[1][j], s[2][j], s[3][j]);
            *(float4*)&Pt[k * 128 + trow * 8 + 4] =
                make_float4(s[4][j], s[5][j], s[6][j], s[7][j]);
        }
        __syncthreads();

        #pragma unroll 8
        for (int k = 0; k < BKA; k++) {
            float pv[8], vv[8];
            float4 p0 = *(const float4*)&Pt[k * 128 + trow * 8];
            float4 p1 = *(const float4*)&Pt[k * 128 + trow * 8 + 4];
            pv[0]=p0.x; pv[1]=p0.y; pv[2]=p0.z; pv[3]=p0.w;
            pv[4]=p1.x; pv[5]=p1.y; pv[6]=p1.z; pv[7]=p1.w;
            float4 v0 = *(const float4*)&Vs[k * 64 + tcol * 8];
            float4 v1 = *(const float4*)&Vs[k * 64 + tcol * 8 + 4];
            vv[0]=v0.x; vv[1]=v0.y; vv[2]=v0.z; vv[3]=v0.w;
            vv[4]=v1.x; vv[5]=v1.y; vv[6]=v1.z; vv[7]=v1.w;
            #pragma unroll
            for (int i = 0; i < 8; i++)
                #pragma unroll
                for (int j = 0; j < 8; j++)
                    acc[i][j] += pv[i] * vv[j];
        }
    }

    // Epilogue: normalize + bf16 hi/lo split for out-proj MMA
    #pragma unroll
    for (int i = 0; i < 8; i++) {
        float inv = 1.f / l[i];
        int q = q0 + trow * 8 + i;
        size_t off = (size_t)(q * B_ + b) * HD_ + h * D_ + tcol * 8;
        #pragma unroll
        for (int j = 0; j < 8; j += 2) {
            float x0 = acc[i][j] * inv;
            float x1 = acc[i][j + 1] * inv;
            __nv_bfloat162 hh, ll;
            hh.x = __float2bfloat16(x0);
            hh.y = __float2bfloat16(x1);
            ll.x = __float2bfloat16(x0 - __bfloat162float(hh.x));
            ll.y = __float2bfloat16(x1 - __bfloat162float(hh.y));
            *(__nv_bfloat162*)&c0[off + j] = hh;
            *(__nv_bfloat162*)&c1[off + j] = ll;
        }
    }
}

// ---------------------------------------------------------------------------
// kernel_launch: LN+split -> wsplits -> QKV HMMA -> flash attention -> out HMMA
// ---------------------------------------------------------------------------
extern "C" void kernel_launch(void* const* d_in, const int* in_sizes, int n_in,
                              void* d_out, int out_size) {
    const float* x        = (const float*)d_in[0];   // [S,B,E]
    const float* ln_scale = (const float*)d_in[1];   // [E]
    const float* w_qkv    = (const float*)d_in[2];   // [E, 3*H*D]
    const float* w_out    = (const float*)d_in[3];   // [H*D, E]
    float* out = (float*)d_out;                      // [S,B,E]

    float* p_qkv;
    __nv_bfloat16 *p_a0, *p_a1, *p_wq0, *p_wq1, *p_wo0, *p_wo1, *p_c0, *p_c1;
    cudaGetSymbolAddress((void**)&p_qkv, g_qkv);
    cudaGetSymbolAddress((void**)&p_a0,  g_a0);
    cudaGetSymbolAddress((void**)&p_a1,  g_a1);
    cudaGetSymbolAddress((void**)&p_wq0, g_wq0);
    cudaGetSymbolAddress((void**)&p_wq1, g_wq1);
    cudaGetSymbolAddress((void**)&p_wo0, g_wo0);
    cudaGetSymbolAddress((void**)&p_wo1, g_wo1);
    cudaGetSymbolAddress((void**)&p_c0,  g_c0);
    cudaGetSymbolAddress((void**)&p_c1,  g_c1);

    cudaFuncSetAttribute(mma_gemm_kernel,
                         cudaFuncAttributeMaxDynamicSharedMemorySize, GSM_TOTAL);
    cudaFuncSetAttribute(attn_kernel,
                         cudaFuncAttributeMaxDynamicSharedMemorySize, 96 * 1024);

    // 1. LayerNorm + A-operand split
    ln_split_kernel<<<NROWS, 256>>>(x, ln_scale, p_a0, p_a1);

    // 2. Weight transpose + split
    wsplit_kernel<<<dim3(Q3_ / 32, E_ / 32), 256>>>(w_qkv, p_wq0, p_wq1, E_, Q3_);
    wsplit_kernel<<<dim3(E_ / 32, HD_ / 32), 256>>>(w_out, p_wo0, p_wo1, HD_, E_);

    // 3. QKV projection on HMMA: [4096,1024] x [1024,3072]
    mma_gemm_kernel<<<dim3(Q3_ / GBN, NROWS / GBM), 256, GSM_TOTAL>>>(
        p_a0, p_a1, p_wq0, p_wq1, p_qkv, Q3_, E_);

    // 4. Flash attention (96 KB dynamic smem)
    {
        const int smem_bytes = (64 * 128 + 64 * 64 + 64 * 64 + 64 * 128) * 4;
        dim3 grid(S_ / BQA, B_ * H_);
        attn_kernel<<<grid, 128, smem_bytes>>>(p_qkv, p_c0, p_c1);
    }

    // 5. Output projection on HMMA: [4096,1024] x [1024,1024]
    mma_gemm_kernel<<<dim3(E_ / GBN, NROWS / GBM), 256, GSM_TOTAL>>>(
        p_c0, p_c1, p_wo0, p_wo1, out, E_, HD_);
}

// round 9
// speedup vs baseline: 4.8505x; 2.1143x over previous
#include <cuda_runtime.h>
#include <cuda_bf16.h>
#include <cstdint>

// Problem constants
#define S_    2048
#define B_    2
#define E_    1024
#define H_    16
#define D_    64
#define HD_   1024
#define Q3_   3072
#define NROWS (S_ * B_)   // 4096 rows, row index = s*B + b
#define BH_   32          // b*16 + h

// ---------------------------------------------------------------------------
// Scratch (device globals: cudaMalloc is forbidden by the harness)
// ---------------------------------------------------------------------------
__device__ __align__(16) __nv_bfloat16 g_a0[(size_t)NROWS * E_];   // LN out hi
__device__ __align__(16) __nv_bfloat16 g_a1[(size_t)NROWS * E_];   // LN out lo
__device__ __align__(16) __nv_bfloat16 g_wq0[(size_t)Q3_ * E_];    // w_qkv^T hi [3072,1024]
__device__ __align__(16) __nv_bfloat16 g_wq1[(size_t)Q3_ * E_];
__device__ __align__(16) __nv_bfloat16 g_wo0[(size_t)E_ * HD_];    // w_out^T hi [1024,1024]
__device__ __align__(16) __nv_bfloat16 g_wo1[(size_t)E_ * HD_];
// Attention operands, written by the QKV GEMM epilogue:
__device__ __align__(16) __nv_bfloat16 g_q0[(size_t)BH_ * S_ * D_];  // [bh][s][d]
__device__ __align__(16) __nv_bfloat16 g_q1[(size_t)BH_ * S_ * D_];
__device__ __align__(16) __nv_bfloat16 g_k0[(size_t)BH_ * S_ * D_];  // [bh][s][d]
__device__ __align__(16) __nv_bfloat16 g_k1[(size_t)BH_ * S_ * D_];
__device__ __align__(16) __nv_bfloat16 g_v0[(size_t)BH_ * D_ * S_];  // [bh][d][s] (transposed)
__device__ __align__(16) __nv_bfloat16 g_v1[(size_t)BH_ * D_ * S_];
__device__ __align__(16) __nv_bfloat16 g_c0[(size_t)NROWS * HD_];  // ctx hi
__device__ __align__(16) __nv_bfloat16 g_c1[(size_t)NROWS * HD_];  // ctx lo

// ---------------------------------------------------------------------------
// PTX helpers: arch-agnostic tensor path (mma.sync / ldmatrix / cp.async).
// tcgen05 is NOT usable: the harness PTX stage targets compute_103 (no 'a').
// ---------------------------------------------------------------------------
__device__ __forceinline__ uint32_t smem_u32(const void* p) {
    return (uint32_t)__cvta_generic_to_shared(p);
}

__device__ __forceinline__ void cp16(uint32_t saddr, const void* g) {
    asm volatile("cp.async.cg.shared.global [%0], [%1], 16;"
                 :: "r"(saddr), "l"(g));
}
#define CP_COMMIT() asm volatile("cp.async.commit_group;" ::: "memory")
#define CP_WAIT(n)  asm volatile("cp.async.wait_group %0;" :: "n"(n) : "memory")

__device__ __forceinline__ void ldsm4(uint32_t* r, uint32_t addr) {
    asm volatile("ldmatrix.sync.aligned.m8n8.x4.shared.b16 {%0,%1,%2,%3}, [%4];"
                 : "=r"(r[0]), "=r"(r[1]), "=r"(r[2]), "=r"(r[3]) : "r"(addr));
}

__device__ __forceinline__ void mma_bf16(float* c, const uint32_t* a,
                                         const uint32_t* b) {
    asm volatile(
        "mma.sync.aligned.m16n8k16.row.col.f32.bf16.bf16.f32 "
        "{%0,%1,%2,%3}, {%4,%5,%6,%7}, {%8,%9}, {%0,%1,%2,%3};"
        : "+f"(c[0]), "+f"(c[1]), "+f"(c[2]), "+f"(c[3])
        : "r"(a[0]), "r"(a[1]), "r"(a[2]), "r"(a[3]), "r"(b[0]), "r"(b[1]));
}

// GEMM tiles: [128 x 32] bf16, 64-byte rows (4 x 16B chunks), chunk' = c^((r>>1)&3)
__device__ __forceinline__ uint32_t soff(int r, int c) {
    return (uint32_t)(r * 64 + ((c ^ ((r >> 1) & 3)) << 4));
}
// Attention tiles: [rows x 64] bf16, 128-byte rows (8 x 16B chunks), chunk' = c^(r&7)
__device__ __forceinline__ uint32_t s128(int r, int c) {
    return (uint32_t)(r * 128 + ((c ^ (r & 7)) << 4));
}

// hi/lo bf16 split of a float pair, packed as bf16x2 words
__device__ __forceinline__ void split2(float x0, float x1,
                                       uint32_t& hi, uint32_t& lo) {
    __nv_bfloat162 h, l;
    h.x = __float2bfloat16(x0);
    h.y = __float2bfloat16(x1);
    l.x = __float2bfloat16(x0 - __bfloat162float(h.x));
    l.y = __float2bfloat16(x1 - __bfloat162float(h.y));
    hi = *(uint32_t*)&h;
    lo = *(uint32_t*)&l;
}

// ---------------------------------------------------------------------------
// Kernel 1: LayerNorm (scale-only) fused with bf16 hi/lo split
// ---------------------------------------------------------------------------
__global__ void ln_split_kernel(const float* __restrict__ x,
                                const float* __restrict__ scale,
                                __nv_bfloat16* __restrict__ a0,
                                __nv_bfloat16* __restrict__ a1) {
    __shared__ float red_s[8];
    __shared__ float red_ss[8];
    const int row = blockIdx.x;
    const int t   = threadIdx.x;
    const float* xr = x + (size_t)row * E_;

    float4 v = *(const float4*)&xr[t * 4];
    float s  = v.x + v.y + v.z + v.w;
    float ss = v.x * v.x + v.y * v.y + v.z * v.z + v.w * v.w;

    #pragma unroll
    for (int o = 16; o; o >>= 1) {
        s  += __shfl_xor_sync(0xFFFFFFFFu, s,  o);
        ss += __shfl_xor_sync(0xFFFFFFFFu, ss, o);
    }
    if ((t & 31) == 0) { red_s[t >> 5] = s; red_ss[t >> 5] = ss; }
    __syncthreads();
    if (t < 32) {
        float s2  = (t < 8) ? red_s[t]  : 0.f;
        float ss2 = (t < 8) ? red_ss[t] : 0.f;
        #pragma unroll
        for (int o = 4; o; o >>= 1) {
            s2  += __shfl_xor_sync(0xFFFFFFFFu, s2,  o);
            ss2 += __shfl_xor_sync(0xFFFFFFFFu, ss2, o);
        }
        if (t == 0) { red_s[0] = s2; red_ss[0] = ss2; }
    }
    __syncthreads();

    const float inv_e = 1.f / (float)E_;
    float mu  = red_s[0] * inv_e;
    float var = red_ss[0] * inv_e - mu * mu;
    float r   = rsqrtf(var + 1e-6f);

    float4 sc = *(const float4*)&scale[t * 4];
    float ov[4];
    ov[0] = (v.x - mu) * r * sc.x;
    ov[1] = (v.y - mu) * r * sc.y;
    ov[2] = (v.z - mu) * r * sc.z;
    ov[3] = (v.w - mu) * r * sc.w;

    const size_t base = (size_t)row * E_ + t * 4;
    #pragma unroll
    for (int p = 0; p < 2; p++) {
        uint32_t hi, lo;
        split2(ov[p * 2], ov[p * 2 + 1], hi, lo);
        *(uint32_t*)&a0[base + p * 2] = hi;
        *(uint32_t*)&a1[base + p * 2] = lo;
    }
}

// ---------------------------------------------------------------------------
// Kernel 2: weight transpose + bf16 hi/lo split.
// W [K,N] row-major (fp32) -> hi/lo [N,K] row-major (K-major for MMA B operand)
// ---------------------------------------------------------------------------
__global__ __launch_bounds__(256)
void wsplit_kernel(const float* __restrict__ W,
                   __nv_bfloat16* __restrict__ hi,
                   __nv_bfloat16* __restrict__ lo, int K, int N) {
    __shared__ float tile[32][33];
    const int bx = blockIdx.x * 32;        // n base
    const int by = blockIdx.y * 32;        // k base
    const int tx = threadIdx.x & 31;
    const int ty = threadIdx.x >> 5;

    #pragma unroll
    for (int i = 0; i < 32; i += 8)
        tile[ty + i][tx] = W[(size_t)(by + ty + i) * N + bx + tx];
    __syncthreads();
    #pragma unroll
    for (int i = 0; i < 32; i += 8) {
        float v = tile[tx][ty + i];
        __nv_bfloat16 h = __float2bfloat16(v);
        __nv_bfloat16 l = __float2bfloat16(v - __bfloat162float(h));
        size_t off = (size_t)(bx + ty + i) * K + by + tx;
        hi[off] = h;
        lo[off] = l;
    }
}

// ---------------------------------------------------------------------------
// Kernel 3: HMMA GEMM with bf16x3 split: C = A0*B0 + A0*B1 + A1*B0.
// MODE 0: fp32 C store. MODE 1 (QKV): scatter hi/lo bf16 to Q/K [bh][s][d]
// and V [bh][d][s] (pre-transposed for the attention PV mma).
// ---------------------------------------------------------------------------
#define GBM 128
#define GBN 128
#define GBK 32
#define TILE_B   8192
#define STAGE_B  (4 * TILE_B)
#define GSM_TOTAL (2 * STAGE_B)       // 64 KB

template <int MODE>
__global__ __launch_bounds__(256, 2)
void mma_gemm_kernel(const __nv_bfloat16* __restrict__ A0,
                     const __nv_bfloat16* __restrict__ A1,
                     const __nv_bfloat16* __restrict__ B0,
                     const __nv_bfloat16* __restrict__ B1,
                     float* __restrict__ C,
                     __nv_bfloat16* __restrict__ oQ0, __nv_bfloat16* __restrict__ oQ1,
                     __nv_bfloat16* __restrict__ oK0, __nv_bfloat16* __restrict__ oK1,
                     __nv_bfloat16* __restrict__ oV0, __nv_bfloat16* __restrict__ oV1,
                     int N, int K) {
    extern __shared__ char sm[];
    const uint32_t smb = smem_u32(sm);

    const int tid  = threadIdx.x;
    const int lane = tid & 31;
    const int wid  = tid >> 5;
    const int wm   = wid & 3;
    const int wn   = wid >> 2;
    const int blockRow = blockIdx.y * GBM;
    const int blockCol = blockIdx.x * GBN;

    float acc[2][8][4];
    #pragma unroll
    for (int i = 0; i < 2; i++)
        #pragma unroll
        for (int j = 0; j < 8; j++)
            #pragma unroll
            for (int q = 0; q < 4; q++) acc[i][j][q] = 0.f;

    const int r0 = (tid + 0)   >> 2, c0 = (tid + 0)   & 3;
    const int r1 = (tid + 256) >> 2, c1 = (tid + 256) & 3;
    const uint32_t so0 = soff(r0, c0), so1 = soff(r1, c1);

    const int NCH = K / GBK;

    {   // Prologue: stage 0
        const uint32_t sb = smb;
        cp16(sb + so0,              A0 + (size_t)(blockRow + r0) * K + c0 * 8);
        cp16(sb + TILE_B + so0,     A1 + (size_t)(blockRow + r0) * K + c0 * 8);
        cp16(sb + 2 * TILE_B + so0, B0 + (size_t)(blockCol + r0) * K + c0 * 8);
        cp16(sb + 3 * TILE_B + so0, B1 + (size_t)(blockCol + r0) * K + c0 * 8);
        cp16(sb + so1,              A0 + (size_t)(blockRow + r1) * K + c1 * 8);
        cp16(sb + TILE_B + so1,     A1 + (size_t)(blockRow + r1) * K + c1 * 8);
        cp16(sb + 2 * TILE_B + so1, B0 + (size_t)(blockCol + r1) * K + c1 * 8);
        cp16(sb + 3 * TILE_B + so1, B1 + (size_t)(blockCol + r1) * K + c1 * 8);
        CP_COMMIT();
    }

    const int rA = wm * 32 + (lane & 15);
    const int cAbase = lane >> 4;
    const int rB = wn * 64 + (lane & 7) + ((lane >> 4) << 3);
    const int cBbase = (lane >> 3) & 1;

    for (int ch = 0; ch < NCH; ch++) {
        if (ch + 1 < NCH) {
            const uint32_t sb = smb + ((ch + 1) & 1) * STAGE_B;
            const int kb = (ch + 1) * GBK;
            cp16(sb + so0,              A0 + (size_t)(blockRow + r0) * K + kb + c0 * 8);
            cp16(sb + TILE_B + so0,     A1 + (size_t)(blockRow + r0) * K + kb + c0 * 8);
            cp16(sb + 2 * TILE_B + so0, B0 + (size_t)(blockCol + r0) * K + kb + c0 * 8);
            cp16(sb + 3 * TILE_B + so0, B1 + (size_t)(blockCol + r0) * K + kb + c0 * 8);
            cp16(sb + so1,              A0 + (size_t)(blockRow + r1) * K + kb + c1 * 8);
            cp16(sb + TILE_B + so1,     A1 + (size_t)(blockRow + r1) * K + kb + c1 * 8);
            cp16(sb + 2 * TILE_B + so1, B0 + (size_t)(blockCol + r1) * K + kb + c1 * 8);
            cp16(sb + 3 * TILE_B + so1, B1 + (size_t)(blockCol + r1) * K + kb + c1 * 8);
            CP_COMMIT();
            CP_WAIT(1);
        } else {
            CP_WAIT(0);
        }
        __syncthreads();

        const uint32_t sb  = smb + (ch & 1) * STAGE_B;
        const uint32_t sA0 = sb;
        const uint32_t sA1 = sb + TILE_B;
        const uint32_t sB0 = sb + 2 * TILE_B;
        const uint32_t sB1 = sb + 3 * TILE_B;

        #pragma unroll
        for (int ks = 0; ks < 2; ks++) {
            const int cA = ks * 2 + cAbase;
            const int cB = ks * 2 + cBbase;
            uint32_t a0f[2][4], a1f[2][4];
            #pragma unroll
            for (int fm = 0; fm < 2; fm++) {
                ldsm4(a0f[fm], sA0 + soff(rA + fm * 16, cA));
                ldsm4(a1f[fm], sA1 + soff(rA + fm * 16, cA));
            }
            uint32_t bf[4][4];
            #pragma unroll
            for (int p = 0; p < 4; p++)
                ldsm4(bf[p], sB0 + soff(rB + p * 16, cB));
            #pragma unroll
            for (int fm = 0; fm < 2; fm++)
                #pragma unroll
                for (int fn = 0; fn < 8; fn++) {
                    mma_bf16(acc[fm][fn], a0f[fm], &bf[fn >> 1][(fn & 1) * 2]);
                    mma_bf16(acc[fm][fn], a1f[fm], &bf[fn >> 1][(fn & 1) * 2]);
                }
            #pragma unroll
            for (int p = 0; p < 4; p++)
                ldsm4(bf[p], sB1 + soff(rB + p * 16, cB));
            #pragma unroll
            for (int fm = 0; fm < 2; fm++)
                #pragma unroll
                for (int fn = 0; fn < 8; fn++)
                    mma_bf16(acc[fm][fn], a0f[fm], &bf[fn >> 1][(fn & 1) * 2]);
        }
        __syncthreads();
    }

    if (MODE == 0) {
        // fp32 C store
        #pragma unroll
        for (int fm = 0; fm < 2; fm++) {
            const int rr = blockRow + wm * 32 + fm * 16 + (lane >> 2);
            #pragma unroll
            for (int fn = 0; fn < 8; fn++) {
                const int cc = blockCol + wn * 64 + fn * 8 + (lane & 3) * 2;
                *(float2*)&C[(size_t)rr * N + cc] =
                    make_float2(acc[fm][fn][0], acc[fm][fn][1]);
                *(float2*)&C[(size_t)(rr + 8) * N + cc] =
                    make_float2(acc[fm][fn][2], acc[fm][fn][3]);
            }
        }
    } else {
        // QKV scatter: part uniform per CTA (1024 | 128*gridX boundaries)
        const int part = blockCol >> 10;   // 0=q, 1=k, 2=v
        #pragma unroll
        for (int fm = 0; fm < 2; fm++) {
            const int rbase = blockRow + wm * 32 + fm * 16 + (lane >> 2);
            #pragma unroll
            for (int fn = 0; fn < 8; fn++) {
                const int cc = blockCol + wn * 64 + fn * 8 + (lane & 3) * 2;
                const int h = (cc >> 6) & 15;
                const int d = cc & 63;
                #pragma unroll
                for (int hf = 0; hf < 2; hf++) {
                    const int rr = rbase + hf * 8;
                    const int s = rr >> 1, b = rr & 1;
                    const int bh = b * 16 + h;
                    uint32_t hi, lo;
                    split2(acc[fm][fn][hf * 2], acc[fm][fn][hf * 2 + 1], hi, lo);
                    if (part == 0) {
                        size_t off = ((size_t)bh * S_ + s) * D_ + d;
                        *(uint32_t*)&oQ0[off] = hi;
                        *(uint32_t*)&oQ1[off] = lo;
                    } else if (part == 1) {
                        size_t off = ((size_t)bh * S_ + s) * D_ + d;
                        *(uint32_t*)&oK0[off] = hi;
                        *(uint32_t*)&oK1[off] = lo;
                    } else {
                        __nv_bfloat162 hv = *(__nv_bfloat162*)&hi;
                        __nv_bfloat162 lv = *(__nv_bfloat162*)&lo;
                        size_t offa = ((size_t)bh * D_ + d) * S_ + s;
                        size_t offb = ((size_t)bh * D_ + d + 1) * S_ + s;
                        oV0[offa] = hv.x; oV0[offb] = hv.y;
                        oV1[offa] = lv.x; oV1[offb] = lv.y;
                    }
                }
            }
        }
    }
}

// ---------------------------------------------------------------------------
// Kernel 4: tensor-core flash attention.
// Grid (S/128, 32 bh). 256 threads = 8 warps; warp w owns q rows [16w,16w+16).
// Per key tile (64 keys): QK^T = Q0K0+Q0K1+Q1K0 (bf16x3); softmax on the
// fp32 C fragments (row stats via shfl over the 4-lane row group); P hi/lo
// packed directly from C-frags into A-frags (no smem); PV = P0V0+P0V1+P1V0
// with V pre-transposed in gmem so B-frags use plain ldmatrix.
// K/V tiles double-buffered via cp.async; Q frags loaded once.
// ---------------------------------------------------------------------------
#define AQT 128
#define ASM_STAGE 32768     // K0|K1|V0|V1, each 8 KB
#define ASM_Q0 65536
#define ASM_Q1 81920
#define ASM_TOTAL 98304     // 96 KB

__global__ __launch_bounds__(256)
void attn_mma_kernel(const __nv_bfloat16* __restrict__ Qh,
                     const __nv_bfloat16* __restrict__ Ql,
                     const __nv_bfloat16* __restrict__ Kh,
                     const __nv_bfloat16* __restrict__ Kl,
                     const __nv_bfloat16* __restrict__ Vh,
                     const __nv_bfloat16* __restrict__ Vl,
                     __nv_bfloat16* __restrict__ c0,
                     __nv_bfloat16* __restrict__ c1) {
    extern __shared__ char sm[];
    const uint32_t smb = smem_u32(sm);
    const int tid  = threadIdx.x;
    const int lane = tid & 31;
    const int wq   = tid >> 5;               // 0..7
    const int bh   = blockIdx.y;             // b*16 + h
    const int qb   = blockIdx.x * AQT;
    const size_t kbase = (size_t)bh * S_ * D_;   // Q/K [bh][s][d]
    const size_t vbase = (size_t)bh * D_ * S_;   // V  [bh][d][s]

    // Stage Q hi/lo tiles [128][64]
    #pragma unroll
    for (int i = 0; i < 4; i++) {
        int idx = tid + i * 256;             // 0..1023
        int r = idx >> 3, c = idx & 7;
        uint32_t so = s128(r, c);
        size_t g = kbase + (size_t)(qb + r) * D_ + c * 8;
        cp16(smb + ASM_Q0 + so, Qh + g);
        cp16(smb + ASM_Q1 + so, Ql + g);
    }
    CP_COMMIT();
    // Stage 0: key tile 0
    #pragma unroll
    for (int i = 0; i < 2; i++) {
        int idx = tid + i * 256;             // 0..511
        int r = idx >> 3, c = idx & 7;
        uint32_t so = s128(r, c);
        size_t gk = kbase + (size_t)r * D_ + c * 8;
        size_t gv = vbase + (size_t)r * S_ + c * 8;
        cp16(smb + so,         Kh + gk);
        cp16(smb + 8192 + so,  Kl + gk);
        cp16(smb + 16384 + so, Vh + gv);
        cp16(smb + 24576 + so, Vl + gv);
    }
    CP_COMMIT();
    CP_WAIT(1);        // Q resident (stage 0 may still be in flight)
    __syncthreads();

    // Q fragments (held for the whole kernel)
    uint32_t qfh[4][4], qfl[4][4];
    {
        const int rA = wq * 16 + (lane & 15);
        const int cA = lane >> 4;
        #pragma unroll
        for (int t = 0; t < 4; t++) {
            ldsm4(qfh[t], smb + ASM_Q0 + s128(rA, t * 2 + cA));
            ldsm4(qfl[t], smb + ASM_Q1 + s128(rA, t * 2 + cA));
        }
    }

    float acc[8][4];
    #pragma unroll
    for (int j = 0; j < 8; j++)
        #pragma unroll
        for (int q = 0; q < 4; q++) acc[j][q] = 0.f;
    float mrow[2] = {-1e30f, -1e30f};
    float lrow[2] = {0.f, 0.f};

    const int rB = (lane & 7) + ((lane >> 4) << 3);
    const int cB = (lane >> 3) & 1;
    const int NKT = S_ / 64;                 // 32 key tiles

    for (int kc = 0; kc < NKT; kc++) {
        if (kc + 1 < NKT) {
            const uint32_t sb = smb + ((kc + 1) & 1) * ASM_STAGE;
            #pragma unroll
            for (int i = 0; i < 2; i++) {
                int idx = tid + i * 256;
                int r = idx >> 3, c = idx & 7;
                uint32_t so = s128(r, c);
                size_t gk = kbase + (size_t)((kc + 1) * 64 + r) * D_ + c * 8;
                size_t gv = vbase + (size_t)r * S_ + (kc + 1) * 64 + c * 8;
                cp16(sb + so,         Kh + gk);
                cp16(sb + 8192 + so,  Kl + gk);
                cp16(sb + 16384 + so, Vh + gv);
                cp16(sb + 24576 + so, Vl + gv);
            }
            CP_COMMIT();
            CP_WAIT(1);
        } else {
            CP_WAIT(0);
        }
        __syncthreads();
        const uint32_t sb = smb + (kc & 1) * ASM_STAGE;

        // ---- Scores: s[16q x 64k] over d=64, 3 split products ----
        float sc[8][4];
        #pragma unroll
        for (int j = 0; j < 8; j++)
            #pragma unroll
            for (int q = 0; q < 4; q++) sc[j][q] = 0.f;

        #pragma unroll
        for (int t = 0; t < 4; t++) {
            #pragma unroll
            for (int jj = 0; jj < 4; jj++) {
                uint32_t k0f[4], k1f[4];
                ldsm4(k0f, sb + s128(jj * 16 + rB, t * 2 + cB));
                ldsm4(k1f, sb + 8192 + s128(jj * 16 + rB, t * 2 + cB));
                mma_bf16(sc[2 * jj],     qfh[t], &k0f[0]);
                mma_bf16(sc[2 * jj + 1], qfh[t], &k0f[2]);
                mma_bf16(sc[2 * jj],     qfh[t], &k1f[0]);
                mma_bf16(sc[2 * jj + 1], qfh[t], &k1f[2]);
                mma_bf16(sc[2 * jj],     qfl[t], &k0f[0]);
                mma_bf16(sc[2 * jj + 1], qfl[t], &k0f[2]);
            }
        }

        // ---- Online softmax on fragments (rows r=lane>>2 and r+8) ----
        #pragma unroll
        for (int h2 = 0; h2 < 2; h2++) {
            float rm = sc[0][2 * h2];
            #pragma unroll
            for (int j = 0; j < 8; j++) {
                rm = fmaxf(rm, sc[j][2 * h2]);
                rm = fmaxf(rm, sc[j][2 * h2 + 1]);
            }
            rm = fmaxf(rm, __shfl_xor_sync(0xFFFFFFFFu, rm, 1));
            rm = fmaxf(rm, __shfl_xor_sync(0xFFFFFFFFu, rm, 2));
            float mnew = fmaxf(mrow[h2], rm);
            float al   = __expf(mrow[h2] - mnew);
            mrow[h2] = mnew;
            float rs = 0.f;
            #pragma unroll
            for (int j = 0; j < 8; j++) {
                float p0 = __expf(sc[j][2 * h2]     - mnew);
                float p1 = __expf(sc[j][2 * h2 + 1] - mnew);
                sc[j][2 * h2]     = p0;
                sc[j][2 * h2 + 1] = p1;
                rs += p0 + p1;
            }
            rs += __shfl_xor_sync(0xFFFFFFFFu, rs, 1);
            rs += __shfl_xor_sync(0xFFFFFFFFu, rs, 2);
            lrow[h2] = lrow[h2] * al + rs;
            #pragma unroll
            for (int j = 0; j < 8; j++) {
                acc[j][2 * h2]     *= al;
                acc[j][2 * h2 + 1] *= al;
            }
        }

        // ---- PV: ctx += P * V, 3 split products; P packed from C-frags ----
        #pragma unroll
        for (int t2 = 0; t2 < 4; t2++) {
            uint32_t ah[4], alo[4];
            split2(sc[2 * t2][0],     sc[2 * t2][1],     ah[0], alo[0]);
            split2(sc[2 * t2][2],     sc[2 * t2][3],     ah[1], alo[1]);
            split2(sc[2 * t2 + 1][0], sc[2 * t2 + 1][1], ah[2], alo[2]);
            split2(sc[2 * t2 + 1][2], sc[2 * t2 + 1][3], ah[3], alo[3]);
            #pragma unroll
            for (int jj = 0; jj < 4; jj++) {
                uint32_t v0f[4], v1f[4];
                ldsm4(v0f, sb + 16384 + s128(jj * 16 + rB, t2 * 2 + cB));
                ldsm4(v1f, sb + 24576 + s128(jj * 16 + rB, t2 * 2 + cB));
                mma_bf16(acc[2 * jj],     ah,  &v0f[0]);
                mma_bf16(acc[2 * jj + 1], ah,  &v0f[2]);
                mma_bf16(acc[2 * jj],     ah,  &v1f[0]);
                mma_bf16(acc[2 * jj + 1], ah,  &v1f[2]);
                mma_bf16(acc[2 * jj],     alo, &v0f[0]);
                mma_bf16(acc[2 * jj + 1], alo, &v0f[2]);
            }
        }
        __syncthreads();    // all warps done with stage before next overwrite
    }

    // ---- Epilogue: normalize, bf16 hi/lo split into c0/c1 [NROWS][HD] ----
    const int b = bh >> 4, h = bh & 15;
    const float inv0 = 1.f / lrow[0];
    const float inv1 = 1.f / lrow[1];
    const int r  = lane >> 2;
    const int c2 = (lane & 3) * 2;
    #pragma unroll
    for (int j = 0; j < 8; j++) {
        const int d = j * 8 + c2;
        const int qg = qb + wq * 16 + r;
        size_t off0 = (size_t)(qg * 2 + b) * HD_ + h * 64 + d;
        size_t off1 = (size_t)((qg + 8) * 2 + b) * HD_ + h * 64 + d;
        uint32_t hi, lo;
        split2(acc[j][0] * inv0, acc[j][1] * inv0, hi, lo);
        *(uint32_t*)&c0[off0] = hi;
        *(uint32_t*)&c1[off0] = lo;
        split2(acc[j][2] * inv1, acc[j][3] * inv1, hi, lo);
        *(uint32_t*)&c0[off1] = hi;
        *(uint32_t*)&c1[off1] = lo;
    }
}

// ---------------------------------------------------------------------------
// kernel_launch
// ---------------------------------------------------------------------------
extern "C" void kernel_launch(void* const* d_in, const int* in_sizes, int n_in,
                              void* d_out, int out_size) {
    const float* x        = (const float*)d_in[0];   // [S,B,E]
    const float* ln_scale = (const float*)d_in[1];   // [E]
    const float* w_qkv    = (const float*)d_in[2];   // [E, 3*H*D]
    const float* w_out    = (const float*)d_in[3];   // [H*D, E]
    float* out = (float*)d_out;                      // [S,B,E]

    __nv_bfloat16 *p_a0, *p_a1, *p_wq0, *p_wq1, *p_wo0, *p_wo1;
    __nv_bfloat16 *pQ0, *pQ1, *pK0, *pK1, *pV0, *pV1, *p_c0, *p_c1;
    cudaGetSymbolAddress((void**)&p_a0,  g_a0);
    cudaGetSymbolAddress((void**)&p_a1,  g_a1);
    cudaGetSymbolAddress((void**)&p_wq0, g_wq0);
    cudaGetSymbolAddress((void**)&p_wq1, g_wq1);
    cudaGetSymbolAddress((void**)&p_wo0, g_wo0);
    cudaGetSymbolAddress((void**)&p_wo1, g_wo1);
    cudaGetSymbolAddress((void**)&pQ0,   g_q0);
    cudaGetSymbolAddress((void**)&pQ1,   g_q1);
    cudaGetSymbolAddress((void**)&pK0,   g_k0);
    cudaGetSymbolAddress((void**)&pK1,   g_k1);
    cudaGetSymbolAddress((void**)&pV0,   g_v0);
    cudaGetSymbolAddress((void**)&pV1,   g_v1);
    cudaGetSymbolAddress((void**)&p_c0,  g_c0);
    cudaGetSymbolAddress((void**)&p_c1,  g_c1);

    cudaFuncSetAttribute(mma_gemm_kernel<0>,
                         cudaFuncAttributeMaxDynamicSharedMemorySize, GSM_TOTAL);
    cudaFuncSetAttribute(mma_gemm_kernel<1>,
                         cudaFuncAttributeMaxDynamicSharedMemorySize, GSM_TOTAL);
    cudaFuncSetAttribute(attn_mma_kernel,
                         cudaFuncAttributeMaxDynamicSharedMemorySize, ASM_TOTAL);

    // 1. LayerNorm + A-operand split
    ln_split_kernel<<<NROWS, 256>>>(x, ln_scale, p_a0, p_a1);

    // 2. Weight transpose + split
    wsplit_kernel<<<dim3(Q3_ / 32, E_ / 32), 256>>>(w_qkv, p_wq0, p_wq1, E_, Q3_);
    wsplit_kernel<<<dim3(E_ / 32, HD_ / 32), 256>>>(w_out, p_wo0, p_wo1, HD_, E_);

    // 3. QKV projection -> Q/K/V bf16 hi/lo buffers (V transposed)
    mma_gemm_kernel<1><<<dim3(Q3_ / GBN, NROWS / GBM), 256, GSM_TOTAL>>>(
        p_a0, p_a1, p_wq0, p_wq1, nullptr,
        pQ0, pQ1, pK0, pK1, pV0, pV1, Q3_, E_);

    // 4. Tensor-core flash attention
    attn_mma_kernel<<<dim3(S_ / AQT, BH_), 256, ASM_TOTAL>>>(
        pQ0, pQ1, pK0, pK1, pV0, pV1, p_c0, p_c1);

    // 5. Output projection (fp32 out)
    mma_gemm_kernel<0><<<dim3(E_ / GBN, NROWS / GBM), 256, GSM_TOTAL>>>(
        p_c0, p_c1, p_wo0, p_wo1, out,
        nullptr, nullptr, nullptr, nullptr, nullptr, nullptr, E_, HD_);
}

// round 10
// speedup vs baseline: 4.9997x; 1.0308x over previous
#include <cuda_runtime.h>
#include <cuda_bf16.h>
#include <cstdint>

// Problem constants
#define S_    2048
#define B_    2
#define E_    1024
#define H_    16
#define D_    64
#define HD_   1024
#define Q3_   3072
#define NROWS (S_ * B_)   // 4096 rows, row index = s*B + b
#define BH_   32          // b*16 + h

// ---------------------------------------------------------------------------
// Scratch (device globals: cudaMalloc is forbidden by the harness)
// ---------------------------------------------------------------------------
__device__ __align__(16) __nv_bfloat16 g_a0[(size_t)NROWS * E_];   // LN out hi
__device__ __align__(16) __nv_bfloat16 g_a1[(size_t)NROWS * E_];   // LN out lo
__device__ __align__(16) __nv_bfloat16 g_wq0[(size_t)Q3_ * E_];    // w_qkv^T hi [3072,1024]
__device__ __align__(16) __nv_bfloat16 g_wq1[(size_t)Q3_ * E_];
__device__ __align__(16) __nv_bfloat16 g_wo0[(size_t)E_ * HD_];    // w_out^T hi [1024,1024]
__device__ __align__(16) __nv_bfloat16 g_wo1[(size_t)E_ * HD_];
// Attention operands, written by the QKV GEMM epilogue:
__device__ __align__(16) __nv_bfloat16 g_q0[(size_t)BH_ * S_ * D_];  // [bh][s][d]
__device__ __align__(16) __nv_bfloat16 g_q1[(size_t)BH_ * S_ * D_];
__device__ __align__(16) __nv_bfloat16 g_k0[(size_t)BH_ * S_ * D_];  // [bh][s][d]
__device__ __align__(16) __nv_bfloat16 g_k1[(size_t)BH_ * S_ * D_];
__device__ __align__(16) __nv_bfloat16 g_v0[(size_t)BH_ * D_ * S_];  // [bh][d][s] (transposed)
__device__ __align__(16) __nv_bfloat16 g_v1[(size_t)BH_ * D_ * S_];
__device__ __align__(16) __nv_bfloat16 g_c0[(size_t)NROWS * HD_];  // ctx hi
__device__ __align__(16) __nv_bfloat16 g_c1[(size_t)NROWS * HD_];  // ctx lo

// ---------------------------------------------------------------------------
// PTX helpers: arch-agnostic tensor path (mma.sync / ldmatrix / cp.async).
// tcgen05 is NOT usable: the harness PTX stage targets compute_103 (no 'a').
// ---------------------------------------------------------------------------
__device__ __forceinline__ uint32_t smem_u32(const void* p) {
    return (uint32_t)__cvta_generic_to_shared(p);
}

__device__ __forceinline__ void cp16(uint32_t saddr, const void* g) {
    asm volatile("cp.async.cg.shared.global [%0], [%1], 16;"
                 :: "r"(saddr), "l"(g));
}
#define CP_COMMIT() asm volatile("cp.async.commit_group;" ::: "memory")
#define CP_WAIT(n)  asm volatile("cp.async.wait_group %0;" :: "n"(n) : "memory")

__device__ __forceinline__ void ldsm4(uint32_t* r, uint32_t addr) {
    asm volatile("ldmatrix.sync.aligned.m8n8.x4.shared.b16 {%0,%1,%2,%3}, [%4];"
                 : "=r"(r[0]), "=r"(r[1]), "=r"(r[2]), "=r"(r[3]) : "r"(addr));
}

__device__ __forceinline__ void mma_bf16(float* c, const uint32_t* a,
                                         const uint32_t* b) {
    asm volatile(
        "mma.sync.aligned.m16n8k16.row.col.f32.bf16.bf16.f32 "
        "{%0,%1,%2,%3}, {%4,%5,%6,%7}, {%8,%9}, {%0,%1,%2,%3};"
        : "+f"(c[0]), "+f"(c[1]), "+f"(c[2]), "+f"(c[3])
        : "r"(a[0]), "r"(a[1]), "r"(a[2]), "r"(a[3]), "r"(b[0]), "r"(b[1]));
}

// GEMM tiles: [128 x 32] bf16, 64-byte rows (4 x 16B chunks), chunk' = c^((r>>1)&3)
__device__ __forceinline__ uint32_t soff(int r, int c) {
    return (uint32_t)(r * 64 + ((c ^ ((r >> 1) & 3)) << 4));
}
// Attention tiles: [rows x 64] bf16, 128-byte rows (8 x 16B chunks), chunk' = c^(r&7)
__device__ __forceinline__ uint32_t s128(int r, int c) {
    return (uint32_t)(r * 128 + ((c ^ (r & 7)) << 4));
}

// hi/lo bf16 split of a float pair, packed as bf16x2 words
__device__ __forceinline__ void split2(float x0, float x1,
                                       uint32_t& hi, uint32_t& lo) {
    __nv_bfloat162 h, l;
    h.x = __float2bfloat16(x0);
    h.y = __float2bfloat16(x1);
    l.x = __float2bfloat16(x0 - __bfloat162float(h.x));
    l.y = __float2bfloat16(x1 - __bfloat162float(h.y));
    hi = *(uint32_t*)&h;
    lo = *(uint32_t*)&l;
}

// ---------------------------------------------------------------------------
// Kernel 1 (fused preprocessing): one launch covering
//   blocks [0, 4096):          LayerNorm + bf16 hi/lo split of activations
//   blocks [4096, 7168):       w_qkv transpose + split  (96 x 32 tiles)
//   blocks [7168, 8192):       w_out transpose + split  (32 x 32 tiles)
// ---------------------------------------------------------------------------
__device__ __forceinline__ void wsplit_body(float* sh,
                                            const float* __restrict__ W,
                                            __nv_bfloat16* __restrict__ hi,
                                            __nv_bfloat16* __restrict__ lo,
                                            int K, int N, int gx, int gy) {
    float (*tile)[33] = (float(*)[33])sh;
    const int bx = gx * 32;        // n base
    const int by = gy * 32;        // k base
    const int tx = threadIdx.x & 31;
    const int ty = threadIdx.x >> 5;

    #pragma unroll
    for (int i = 0; i < 32; i += 8)
        tile[ty + i][tx] = W[(size_t)(by + ty + i) * N + bx + tx];
    __syncthreads();
    #pragma unroll
    for (int i = 0; i < 32; i += 8) {
        float v = tile[tx][ty + i];
        __nv_bfloat16 h = __float2bfloat16(v);
        __nv_bfloat16 l = __float2bfloat16(v - __bfloat162float(h));
        size_t off = (size_t)(bx + ty + i) * K + by + tx;
        hi[off] = h;
        lo[off] = l;
    }
}

__global__ __launch_bounds__(256)
void pre_kernel(const float* __restrict__ x,
                const float* __restrict__ scale,
                __nv_bfloat16* __restrict__ a0,
                __nv_bfloat16* __restrict__ a1,
                const float* __restrict__ wqkv,
                __nv_bfloat16* __restrict__ wq0,
                __nv_bfloat16* __restrict__ wq1,
                const float* __restrict__ wout,
                __nv_bfloat16* __restrict__ wo0,
                __nv_bfloat16* __restrict__ wo1) {
    __shared__ float sh[32 * 33];
    const int bid = blockIdx.x;

    if (bid >= NROWS) {
        if (bid < NROWS + 3072) {
            int idx = bid - NROWS;
            wsplit_body(sh, wqkv, wq0, wq1, E_, Q3_, idx % 96, idx / 96);
        } else {
            int idx = bid - NROWS - 3072;
            wsplit_body(sh, wout, wo0, wo1, HD_, E_, idx % 32, idx / 32);
        }
        return;
    }

    // ---- LayerNorm + split ----
    float* red_s  = sh;
    float* red_ss = sh + 8;
    const int row = bid;
    const int t   = threadIdx.x;
    const float* xr = x + (size_t)row * E_;

    float4 v = *(const float4*)&xr[t * 4];
    float s  = v.x + v.y + v.z + v.w;
    float ss = v.x * v.x + v.y * v.y + v.z * v.z + v.w * v.w;

    #pragma unroll
    for (int o = 16; o; o >>= 1) {
        s  += __shfl_xor_sync(0xFFFFFFFFu, s,  o);
        ss += __shfl_xor_sync(0xFFFFFFFFu, ss, o);
    }
    if ((t & 31) == 0) { red_s[t >> 5] = s; red_ss[t >> 5] = ss; }
    __syncthreads();
    if (t < 32) {
        float s2  = (t < 8) ? red_s[t]  : 0.f;
        float ss2 = (t < 8) ? red_ss[t] : 0.f;
        #pragma unroll
        for (int o = 4; o; o >>= 1) {
            s2  += __shfl_xor_sync(0xFFFFFFFFu, s2,  o);
            ss2 += __shfl_xor_sync(0xFFFFFFFFu, ss2, o);
        }
        if (t == 0) { red_s[0] = s2; red_ss[0] = ss2; }
    }
    __syncthreads();

    const float inv_e = 1.f / (float)E_;
    float mu  = red_s[0] * inv_e;
    float var = red_ss[0] * inv_e - mu * mu;
    float r   = rsqrtf(var + 1e-6f);

    float4 sc = *(const float4*)&scale[t * 4];
    float ov[4];
    ov[0] = (v.x - mu) * r * sc.x;
    ov[1] = (v.y - mu) * r * sc.y;
    ov[2] = (v.z - mu) * r * sc.z;
    ov[3] = (v.w - mu) * r * sc.w;

    const size_t base = (size_t)row * E_ + t * 4;
    #pragma unroll
    for (int p = 0; p < 2; p++) {
        uint32_t hi, lo;
        split2(ov[p * 2], ov[p * 2 + 1], hi, lo);
        *(uint32_t*)&a0[base + p * 2] = hi;
        *(uint32_t*)&a1[base + p * 2] = lo;
    }
}

// ---------------------------------------------------------------------------
// Kernel 2: HMMA GEMM with bf16x3 split: C = A0*B0 + A0*B1 + A1*B0.
// 3-stage cp.async pipeline, ONE barrier per K-chunk:
//   wait(stage c) -> syncthreads -> issue chunk c+2 -> compute c
// The barrier both publishes stage c (each thread CP_WAITed its own groups
// before it) and proves compute c-1 finished block-wide, making stage
// (c+2)%3 == (c-1)%3 safe to overwrite.
// MODE 0: fp32 C store. MODE 1 (QKV): scatter hi/lo bf16 to Q/K [bh][s][d]
// and V [bh][d][s] (pre-transposed for the attention PV mma).
// ---------------------------------------------------------------------------
#define GBM 128
#define GBN 128
#define GBK 32
#define TILE_B   8192
#define STAGE_B  (4 * TILE_B)
#define GSM_TOTAL (3 * STAGE_B)       // 96 KB, 3 stages

template <int MODE>
__global__ __launch_bounds__(256, 2)
void mma_gemm_kernel(const __nv_bfloat16* __restrict__ A0,
                     const __nv_bfloat16* __restrict__ A1,
                     const __nv_bfloat16* __restrict__ B0,
                     const __nv_bfloat16* __restrict__ B1,
                     float* __restrict__ C,
                     __nv_bfloat16* __restrict__ oQ0, __nv_bfloat16* __restrict__ oQ1,
                     __nv_bfloat16* __restrict__ oK0, __nv_bfloat16* __restrict__ oK1,
                     __nv_bfloat16* __restrict__ oV0, __nv_bfloat16* __restrict__ oV1,
                     int N, int K) {
    extern __shared__ char sm[];
    const uint32_t smb = smem_u32(sm);

    const int tid  = threadIdx.x;
    const int lane = tid & 31;
    const int wid  = tid >> 5;
    const int wm   = wid & 3;
    const int wn   = wid >> 2;
    const int blockRow = blockIdx.y * GBM;
    const int blockCol = blockIdx.x * GBN;

    float acc[2][8][4];
    #pragma unroll
    for (int i = 0; i < 2; i++)
        #pragma unroll
        for (int j = 0; j < 8; j++)
            #pragma unroll
            for (int q = 0; q < 4; q++) acc[i][j][q] = 0.f;

    const int r0 = (tid + 0)   >> 2, c0 = (tid + 0)   & 3;
    const int r1 = (tid + 256) >> 2, c1 = (tid + 256) & 3;
    const uint32_t so0 = soff(r0, c0), so1 = soff(r1, c1);

    const int NCH = K / GBK;               // 32

    // Prologue: stages 0 and 1 (chunks 0 and 1), separate commit groups
    #pragma unroll
    for (int st = 0; st < 2; st++) {
        const uint32_t sb = smb + st * STAGE_B;
        const int kb = st * GBK;
        cp16(sb + so0,              A0 + (size_t)(blockRow + r0) * K + kb + c0 * 8);
        cp16(sb + TILE_B + so0,     A1 + (size_t)(blockRow + r0) * K + kb + c0 * 8);
        cp16(sb + 2 * TILE_B + so0, B0 + (size_t)(blockCol + r0) * K + kb + c0 * 8);
        cp16(sb + 3 * TILE_B + so0, B1 + (size_t)(blockCol + r0) * K + kb + c0 * 8);
        cp16(sb + so1,              A0 + (size_t)(blockRow + r1) * K + kb + c1 * 8);
        cp16(sb + TILE_B + so1,     A1 + (size_t)(blockRow + r1) * K + kb + c1 * 8);
        cp16(sb + 2 * TILE_B + so1, B0 + (size_t)(blockCol + r1) * K + kb + c1 * 8);
        cp16(sb + 3 * TILE_B + so1, B1 + (size_t)(blockCol + r1) * K + kb + c1 * 8);
        CP_COMMIT();
    }

    const int rA = wm * 32 + (lane & 15);
    const int cAbase = lane >> 4;
    const int rB = wn * 64 + (lane & 7) + ((lane >> 4) << 3);
    const int cBbase = (lane >> 3) & 1;

    for (int ch = 0; ch < NCH; ch++) {
        // stage ch ready (own groups); allow the one later group to fly
        if (ch + 1 < NCH) { CP_WAIT(1); } else { CP_WAIT(0); }
        __syncthreads();    // publish stage ch + prove compute ch-1 done

        if (ch + 2 < NCH) {
            const uint32_t sb = smb + ((ch + 2) % 3) * STAGE_B;
            const int kb = (ch + 2) * GBK;
            cp16(sb + so0,              A0 + (size_t)(blockRow + r0) * K + kb + c0 * 8);
            cp16(sb + TILE_B + so0,     A1 + (size_t)(blockRow + r0) * K + kb + c0 * 8);
            cp16(sb + 2 * TILE_B + so0, B0 + (size_t)(blockCol + r0) * K + kb + c0 * 8);
            cp16(sb + 3 * TILE_B + so0, B1 + (size_t)(blockCol + r0) * K + kb + c0 * 8);
            cp16(sb + so1,              A0 + (size_t)(blockRow + r1) * K + kb + c1 * 8);
            cp16(sb + TILE_B + so1,     A1 + (size_t)(blockRow + r1) * K + kb + c1 * 8);
            cp16(sb + 2 * TILE_B + so1, B0 + (size_t)(blockCol + r1) * K + kb + c1 * 8);
            cp16(sb + 3 * TILE_B + so1, B1 + (size_t)(blockCol + r1) * K + kb + c1 * 8);
            CP_COMMIT();
        }

        const uint32_t sb  = smb + (ch % 3) * STAGE_B;
        const uint32_t sA0 = sb;
        const uint32_t sA1 = sb + TILE_B;
        const uint32_t sB0 = sb + 2 * TILE_B;
        const uint32_t sB1 = sb + 3 * TILE_B;

        #pragma unroll
        for (int ks = 0; ks < 2; ks++) {
            const int cA = ks * 2 + cAbase;
            const int cB = ks * 2 + cBbase;
            uint32_t a0f[2][4], a1f[2][4];
            #pragma unroll
            for (int fm = 0; fm < 2; fm++) {
                ldsm4(a0f[fm], sA0 + soff(rA + fm * 16, cA));
                ldsm4(a1f[fm], sA1 + soff(rA + fm * 16, cA));
            }
            uint32_t bf[4][4];
            #pragma unroll
            for (int p = 0; p < 4; p++)
                ldsm4(bf[p], sB0 + soff(rB + p * 16, cB));
            #pragma unroll
            for (int fm = 0; fm < 2; fm++)
                #pragma unroll
                for (int fn = 0; fn < 8; fn++) {
                    mma_bf16(acc[fm][fn], a0f[fm], &bf[fn >> 1][(fn & 1) * 2]);
                    mma_bf16(acc[fm][fn], a1f[fm], &bf[fn >> 1][(fn & 1) * 2]);
                }
            #pragma unroll
            for (int p = 0; p < 4; p++)
                ldsm4(bf[p], sB1 + soff(rB + p * 16, cB));
            #pragma unroll
            for (int fm = 0; fm < 2; fm++)
                #pragma unroll
                for (int fn = 0; fn < 8; fn++)
                    mma_bf16(acc[fm][fn], a0f[fm], &bf[fn >> 1][(fn & 1) * 2]);
        }
        // no trailing barrier: next iteration's barrier protects stage reuse
    }

    if (MODE == 0) {
        // fp32 C store
        #pragma unroll
        for (int fm = 0; fm < 2; fm++) {
            const int rr = blockRow + wm * 32 + fm * 16 + (lane >> 2);
            #pragma unroll
            for (int fn = 0; fn < 8; fn++) {
                const int cc = blockCol + wn * 64 + fn * 8 + (lane & 3) * 2;
                *(float2*)&C[(size_t)rr * N + cc] =
                    make_float2(acc[fm][fn][0], acc[fm][fn][1]);
                *(float2*)&C[(size_t)(rr + 8) * N + cc] =
                    make_float2(acc[fm][fn][2], acc[fm][fn][3]);
            }
        }
    } else {
        // QKV scatter: part uniform per CTA (1024 | 128*gridX boundaries)
        const int part = blockCol >> 10;   // 0=q, 1=k, 2=v
        #pragma unroll
        for (int fm = 0; fm < 2; fm++) {
            const int rbase = blockRow + wm * 32 + fm * 16 + (lane >> 2);
            #pragma unroll
            for (int fn = 0; fn < 8; fn++) {
                const int cc = blockCol + wn * 64 + fn * 8 + (lane & 3) * 2;
                const int h = (cc >> 6) & 15;
                const int d = cc & 63;
                #pragma unroll
                for (int hf = 0; hf < 2; hf++) {
                    const int rr = rbase + hf * 8;
                    const int s = rr >> 1, b = rr & 1;
                    const int bh = b * 16 + h;
                    uint32_t hi, lo;
                    split2(acc[fm][fn][hf * 2], acc[fm][fn][hf * 2 + 1], hi, lo);
                    if (part == 0) {
                        size_t off = ((size_t)bh * S_ + s) * D_ + d;
                        *(uint32_t*)&oQ0[off] = hi;
                        *(uint32_t*)&oQ1[off] = lo;
                    } else if (part == 1) {
                        size_t off = ((size_t)bh * S_ + s) * D_ + d;
                        *(uint32_t*)&oK0[off] = hi;
                        *(uint32_t*)&oK1[off] = lo;
                    } else {
                        __nv_bfloat162 hv = *(__nv_bfloat162*)&hi;
                        __nv_bfloat162 lv = *(__nv_bfloat162*)&lo;
                        size_t offa = ((size_t)bh * D_ + d) * S_ + s;
                        size_t offb = ((size_t)bh * D_ + d + 1) * S_ + s;
                        oV0[offa] = hv.x; oV0[offb] = hv.y;
                        oV1[offa] = lv.x; oV1[offb] = lv.y;
                    }
                }
            }
        }
    }
}

// ---------------------------------------------------------------------------
// Kernel 3: tensor-core flash attention (single barrier per key tile).
// Grid (S/128, 32 bh). 256 threads = 8 warps; warp w owns q rows [16w,16w+16).
// Per key tile (64 keys): QK^T = Q0K0+Q0K1+Q1K0 (bf16x3); softmax on the
// fp32 C fragments; P hi/lo packed directly from C-frags into A-frags;
// PV = P0V0+P0V1+P1V0 with V pre-transposed in gmem.
// Loop: wait(stage kc) -> syncthreads -> issue kc+1 -> compute (no tail sync).
// ---------------------------------------------------------------------------
#define AQT 128
#define ASM_STAGE 32768     // K0|K1|V0|V1, each 8 KB
#define ASM_Q0 65536
#define ASM_Q1 81920
#define ASM_TOTAL 98304     // 96 KB

__global__ __launch_bounds__(256)
void attn_mma_kernel(const __nv_bfloat16* __restrict__ Qh,
                     const __nv_bfloat16* __restrict__ Ql,
                     const __nv_bfloat16* __restrict__ Kh,
                     const __nv_bfloat16* __restrict__ Kl,
                     const __nv_bfloat16* __restrict__ Vh,
                     const __nv_bfloat16* __restrict__ Vl,
                     __nv_bfloat16* __restrict__ c0,
                     __nv_bfloat16* __restrict__ c1) {
    extern __shared__ char sm[];
    const uint32_t smb = smem_u32(sm);
    const int tid  = threadIdx.x;
    const int lane = tid & 31;
    const int wq   = tid >> 5;               // 0..7
    const int bh   = blockIdx.y;             // b*16 + h
    const int qb   = blockIdx.x * AQT;
    const size_t kbase = (size_t)bh * S_ * D_;   // Q/K [bh][s][d]
    const size_t vbase = (size_t)bh * D_ * S_;   // V  [bh][d][s]

    // Stage Q hi/lo tiles [128][64]  (group 0)
    #pragma unroll
    for (int i = 0; i < 4; i++) {
        int idx = tid + i * 256;             // 0..1023
        int r = idx >> 3, c = idx & 7;
        uint32_t so = s128(r, c);
        size_t g = kbase + (size_t)(qb + r) * D_ + c * 8;
        cp16(smb + ASM_Q0 + so, Qh + g);
        cp16(smb + ASM_Q1 + so, Ql + g);
    }
    CP_COMMIT();
    // Key tile 0 (group 1)
    #pragma unroll
    for (int i = 0; i < 2; i++) {
        int idx = tid + i * 256;             // 0..511
        int r = idx >> 3, c = idx & 7;
        uint32_t so = s128(r, c);
        size_t gk = kbase + (size_t)r * D_ + c * 8;
        size_t gv = vbase + (size_t)r * S_ + c * 8;
        cp16(smb + so,         Kh + gk);
        cp16(smb + 8192 + so,  Kl + gk);
        cp16(smb + 16384 + so, Vh + gv);
        cp16(smb + 24576 + so, Vl + gv);
    }
    CP_COMMIT();
    CP_WAIT(1);        // Q resident (stage 0 may still be in flight)
    __syncthreads();

    // Q fragments (held for the whole kernel)
    uint32_t qfh[4][4], qfl[4][4];
    {
        const int rA = wq * 16 + (lane & 15);
        const int cA = lane >> 4;
        #pragma unroll
        for (int t = 0; t < 4; t++) {
            ldsm4(qfh[t], smb + ASM_Q0 + s128(rA, t * 2 + cA));
            ldsm4(qfl[t], smb + ASM_Q1 + s128(rA, t * 2 + cA));
        }
    }

    float acc[8][4];
    #pragma unroll
    for (int j = 0; j < 8; j++)
        #pragma unroll
        for (int q = 0; q < 4; q++) acc[j][q] = 0.f;
    float mrow[2] = {-1e30f, -1e30f};
    float lrow[2] = {0.f, 0.f};

    const int rB = (lane & 7) + ((lane >> 4) << 3);
    const int cB = (lane >> 3) & 1;
    const int NKT = S_ / 64;                 // 32 key tiles

    for (int kc = 0; kc < NKT; kc++) {
        CP_WAIT(0);         // stage kc ready (own groups)
        __syncthreads();    // publish stage kc + prove compute kc-1 done

        if (kc + 1 < NKT) {
            const uint32_t sb = smb + ((kc + 1) & 1) * ASM_STAGE;
            #pragma unroll
            for (int i = 0; i < 2; i++) {
                int idx = tid + i * 256;
                int r = idx >> 3, c = idx & 7;
                uint32_t so = s128(r, c);
                size_t gk = kbase + (size_t)((kc + 1) * 64 + r) * D_ + c * 8;
                size_t gv = vbase + (size_t)r * S_ + (kc + 1) * 64 + c * 8;
                cp16(sb + so,         Kh + gk);
                cp16(sb + 8192 + so,  Kl + gk);
                cp16(sb + 16384 + so, Vh + gv);
                cp16(sb + 24576 + so, Vl + gv);
            }
            CP_COMMIT();
        }
        const uint32_t sb = smb + (kc & 1) * ASM_STAGE;

        // ---- Scores: s[16q x 64k] over d=64, 3 split products ----
        float sc[8][4];
        #pragma unroll
        for (int j = 0; j < 8; j++)
            #pragma unroll
            for (int q = 0; q < 4; q++) sc[j][q] = 0.f;

        #pragma unroll
        for (int t = 0; t < 4; t++) {
            #pragma unroll
            for (int jj = 0; jj < 4; jj++) {
                uint32_t k0f[4], k1f[4];
                ldsm4(k0f, sb + s128(jj * 16 + rB, t * 2 + cB));
                ldsm4(k1f, sb + 8192 + s128(jj * 16 + rB, t * 2 + cB));
                mma_bf16(sc[2 * jj],     qfh[t], &k0f[0]);
                mma_bf16(sc[2 * jj + 1], qfh[t], &k0f[2]);
                mma_bf16(sc[2 * jj],     qfh[t], &k1f[0]);
                mma_bf16(sc[2 * jj + 1], qfh[t], &k1f[2]);
                mma_bf16(sc[2 * jj],     qfl[t], &k0f[0]);
                mma_bf16(sc[2 * jj + 1], qfl[t], &k0f[2]);
            }
        }

        // ---- Online softmax on fragments (rows r=lane>>2 and r+8) ----
        #pragma unroll
        for (int h2 = 0; h2 < 2; h2++) {
            float rm = sc[0][2 * h2];
            #pragma unroll
            for (int j = 0; j < 8; j++) {
                rm = fmaxf(rm, sc[j][2 * h2]);
                rm = fmaxf(rm, sc[j][2 * h2 + 1]);
            }
            rm = fmaxf(rm, __shfl_xor_sync(0xFFFFFFFFu, rm, 1));
            rm = fmaxf(rm, __shfl_xor_sync(0xFFFFFFFFu, rm, 2));
            float mnew = fmaxf(mrow[h2], rm);
            float al   = __expf(mrow[h2] - mnew);
            mrow[h2] = mnew;
            float rs = 0.f;
            #pragma unroll
            for (int j = 0; j < 8; j++) {
                float p0 = __expf(sc[j][2 * h2]     - mnew);
                float p1 = __expf(sc[j][2 * h2 + 1] - mnew);
                sc[j][2 * h2]     = p0;
                sc[j][2 * h2 + 1] = p1;
                rs += p0 + p1;
            }
            rs += __shfl_xor_sync(0xFFFFFFFFu, rs, 1);
            rs += __shfl_xor_sync(0xFFFFFFFFu, rs, 2);
            lrow[h2] = lrow[h2] * al + rs;
            #pragma unroll
            for (int j = 0; j < 8; j++) {
                acc[j][2 * h2]     *= al;
                acc[j][2 * h2 + 1] *= al;
            }
        }

        // ---- PV: ctx += P * V, 3 split products; P packed from C-frags ----
        #pragma unroll
        for (int t2 = 0; t2 < 4; t2++) {
            uint32_t ah[4], alo[4];
            split2(sc[2 * t2][0],     sc[2 * t2][1],     ah[0], alo[0]);
            split2(sc[2 * t2][2],     sc[2 * t2][3],     ah[1], alo[1]);
            split2(sc[2 * t2 + 1][0], sc[2 * t2 + 1][1], ah[2], alo[2]);
            split2(sc[2 * t2 + 1][2], sc[2 * t2 + 1][3], ah[3], alo[3]);
            #pragma unroll
            for (int jj = 0; jj < 4; jj++) {
                uint32_t v0f[4], v1f[4];
                ldsm4(v0f, sb + 16384 + s128(jj * 16 + rB, t2 * 2 + cB));
                ldsm4(v1f, sb + 24576 + s128(jj * 16 + rB, t2 * 2 + cB));
                mma_bf16(acc[2 * jj],     ah,  &v0f[0]);
                mma_bf16(acc[2 * jj + 1], ah,  &v0f[2]);
                mma_bf16(acc[2 * jj],     ah,  &v1f[0]);
                mma_bf16(acc[2 * jj + 1], ah,  &v1f[2]);
                mma_bf16(acc[2 * jj],     alo, &v0f[0]);
                mma_bf16(acc[2 * jj + 1], alo, &v0f[2]);
            }
        }
        // no trailing barrier: next iteration's barrier protects stage reuse
    }

    // ---- Epilogue: normalize, bf16 hi/lo split into c0/c1 [NROWS][HD] ----
    const int b = bh >> 4, h = bh & 15;
    const float inv0 = 1.f / lrow[0];
    const float inv1 = 1.f / lrow[1];
    const int r  = lane >> 2;
    const int c2 = (lane & 3) * 2;
    #pragma unroll
    for (int j = 0; j < 8; j++) {
        const int d = j * 8 + c2;
        const int qg = qb + wq * 16 + r;
        size_t off0 = (size_t)(qg * 2 + b) * HD_ + h * 64 + d;
        size_t off1 = (size_t)((qg + 8) * 2 + b) * HD_ + h * 64 + d;
        uint32_t hi, lo;
        split2(acc[j][0] * inv0, acc[j][1] * inv0, hi, lo);
        *(uint32_t*)&c0[off0] = hi;
        *(uint32_t*)&c1[off0] = lo;
        split2(acc[j][2] * inv1, acc[j][3] * inv1, hi, lo);
        *(uint32_t*)&c0[off1] = hi;
        *(uint32_t*)&c1[off1] = lo;
    }
}

// ---------------------------------------------------------------------------
// kernel_launch
// ---------------------------------------------------------------------------
extern "C" void kernel_launch(void* const* d_in, const int* in_sizes, int n_in,
                              void* d_out, int out_size) {
    const float* x        = (const float*)d_in[0];   // [S,B,E]
    const float* ln_scale = (const float*)d_in[1];   // [E]
    const float* w_qkv    = (const float*)d_in[2];   // [E, 3*H*D]
    const float* w_out    = (const float*)d_in[3];   // [H*D, E]
    float* out = (float*)d_out;                      // [S,B,E]

    __nv_bfloat16 *p_a0, *p_a1, *p_wq0, *p_wq1, *p_wo0, *p_wo1;
    __nv_bfloat16 *pQ0, *pQ1, *pK0, *pK1, *pV0, *pV1, *p_c0, *p_c1;
    cudaGetSymbolAddress((void**)&p_a0,  g_a0);
    cudaGetSymbolAddress((void**)&p_a1,  g_a1);
    cudaGetSymbolAddress((void**)&p_wq0, g_wq0);
    cudaGetSymbolAddress((void**)&p_wq1, g_wq1);
    cudaGetSymbolAddress((void**)&p_wo0, g_wo0);
    cudaGetSymbolAddress((void**)&p_wo1, g_wo1);
    cudaGetSymbolAddress((void**)&pQ0,   g_q0);
    cudaGetSymbolAddress((void**)&pQ1,   g_q1);
    cudaGetSymbolAddress((void**)&pK0,   g_k0);
    cudaGetSymbolAddress((void**)&pK1,   g_k1);
    cudaGetSymbolAddress((void**)&pV0,   g_v0);
    cudaGetSymbolAddress((void**)&pV1,   g_v1);
    cudaGetSymbolAddress((void**)&p_c0,  g_c0);
    cudaGetSymbolAddress((void**)&p_c1,  g_c1);

    cudaFuncSetAttribute(mma_gemm_kernel<0>,
                         cudaFuncAttributeMaxDynamicSharedMemorySize, GSM_TOTAL);
    cudaFuncSetAttribute(mma_gemm_kernel<1>,
                         cudaFuncAttributeMaxDynamicSharedMemorySize, GSM_TOTAL);
    cudaFuncSetAttribute(attn_mma_kernel,
                         cudaFuncAttributeMaxDynamicSharedMemorySize, ASM_TOTAL);

    // 1. Fused preprocessing: LayerNorm+split and both weight transpose+splits
    pre_kernel<<<NROWS + 3072 + 1024, 256>>>(
        x, ln_scale, p_a0, p_a1, w_qkv, p_wq0, p_wq1, w_out, p_wo0, p_wo1);

    // 2. QKV projection -> Q/K/V bf16 hi/lo buffers (V transposed)
    mma_gemm_kernel<1><<<dim3(Q3_ / GBN, NROWS / GBM), 256, GSM_TOTAL>>>(
        p_a0, p_a1, p_wq0, p_wq1, nullptr,
        pQ0, pQ1, pK0, pK1, pV0, pV1, Q3_, E_);

    // 3. Tensor-core flash attention
    attn_mma_kernel<<<dim3(S_ / AQT, BH_), 256, ASM_TOTAL>>>(
        pQ0, pQ1, pK0, pK1, pV0, pV1, p_c0, p_c1);

    // 4. Output projection (fp32 out)
    mma_gemm_kernel<0><<<dim3(E_ / GBN, NROWS / GBM), 256, GSM_TOTAL>>>(
        p_c0, p_c1, p_wo0, p_wo1, out,
        nullptr, nullptr, nullptr, nullptr, nullptr, nullptr, E_, HD_);
}

// round 11
// speedup vs baseline: 5.5909x; 1.1182x over previous
#include <cuda_runtime.h>
#include <cuda_bf16.h>
#include <cuda_fp16.h>
#include <cstdint>

// Problem constants
#define S_    2048
#define B_    2
#define E_    1024
#define H_    16
#define D_    64
#define HD_   1024
#define Q3_   3072
#define NROWS (S_ * B_)   // 4096 rows, row index = s*B + b
#define BH_   32          // b*16 + h

// ---------------------------------------------------------------------------
// Scratch (device globals: cudaMalloc is forbidden by the harness)
// ---------------------------------------------------------------------------
__device__ __align__(16) __nv_bfloat16 g_a0[(size_t)NROWS * E_];   // LN out hi
__device__ __align__(16) __nv_bfloat16 g_a1[(size_t)NROWS * E_];   // LN out lo
__device__ __align__(16) __nv_bfloat16 g_wq0[(size_t)Q3_ * E_];    // w_qkv^T hi [3072,1024]
__device__ __align__(16) __nv_bfloat16 g_wq1[(size_t)Q3_ * E_];
__device__ __align__(16) __nv_bfloat16 g_wo0[(size_t)E_ * HD_];    // w_out^T hi [1024,1024]
__device__ __align__(16) __nv_bfloat16 g_wo1[(size_t)E_ * HD_];
// Attention operands (fp16), written by the QKV GEMM epilogue:
__device__ __align__(16) __half g_q0[(size_t)BH_ * S_ * D_];   // Q hi [bh][s][d]
__device__ __align__(16) __half g_q1[(size_t)BH_ * S_ * D_];   // Q lo
__device__ __align__(16) __half g_k0[(size_t)BH_ * S_ * D_];   // K single [bh][s][d]
__device__ __align__(16) __half g_v0[(size_t)BH_ * D_ * S_];   // V single [bh][d][s]
__device__ __align__(16) __nv_bfloat16 g_c0[(size_t)NROWS * HD_];  // ctx hi (bf16)
__device__ __align__(16) __nv_bfloat16 g_c1[(size_t)NROWS * HD_];  // ctx lo

// ---------------------------------------------------------------------------
// PTX helpers: arch-agnostic tensor path (mma.sync / ldmatrix / cp.async).
// tcgen05 is NOT usable: the harness PTX stage targets compute_103 (no 'a').
// ---------------------------------------------------------------------------
__device__ __forceinline__ uint32_t smem_u32(const void* p) {
    return (uint32_t)__cvta_generic_to_shared(p);
}

__device__ __forceinline__ void cp16(uint32_t saddr, const void* g) {
    asm volatile("cp.async.cg.shared.global [%0], [%1], 16;"
                 :: "r"(saddr), "l"(g));
}
#define CP_COMMIT() asm volatile("cp.async.commit_group;" ::: "memory")
#define CP_WAIT(n)  asm volatile("cp.async.wait_group %0;" :: "n"(n) : "memory")

__device__ __forceinline__ void ldsm4(uint32_t* r, uint32_t addr) {
    asm volatile("ldmatrix.sync.aligned.m8n8.x4.shared.b16 {%0,%1,%2,%3}, [%4];"
                 : "=r"(r[0]), "=r"(r[1]), "=r"(r[2]), "=r"(r[3]) : "r"(addr));
}

__device__ __forceinline__ void mma_bf16(float* c, const uint32_t* a,
                                         const uint32_t* b) {
    asm volatile(
        "mma.sync.aligned.m16n8k16.row.col.f32.bf16.bf16.f32 "
        "{%0,%1,%2,%3}, {%4,%5,%6,%7}, {%8,%9}, {%0,%1,%2,%3};"
        : "+f"(c[0]), "+f"(c[1]), "+f"(c[2]), "+f"(c[3])
        : "r"(a[0]), "r"(a[1]), "r"(a[2]), "r"(a[3]), "r"(b[0]), "r"(b[1]));
}

__device__ __forceinline__ void mma_f16(float* c, const uint32_t* a,
                                        const uint32_t* b) {
    asm volatile(
        "mma.sync.aligned.m16n8k16.row.col.f32.f16.f16.f32 "
        "{%0,%1,%2,%3}, {%4,%5,%6,%7}, {%8,%9}, {%0,%1,%2,%3};"
        : "+f"(c[0]), "+f"(c[1]), "+f"(c[2]), "+f"(c[3])
        : "r"(a[0]), "r"(a[1]), "r"(a[2]), "r"(a[3]), "r"(b[0]), "r"(b[1]));
}

// GEMM tiles: [128 x 32] bf16, 64-byte rows (4 x 16B chunks), chunk' = c^((r>>1)&3)
__device__ __forceinline__ uint32_t soff(int r, int c) {
    return (uint32_t)(r * 64 + ((c ^ ((r >> 1) & 3)) << 4));
}
// Attention tiles: [rows x 64] halfword, 128-byte rows (8 x 16B), chunk' = c^(r&7)
__device__ __forceinline__ uint32_t s128(int r, int c) {
    return (uint32_t)(r * 128 + ((c ^ (r & 7)) << 4));
}

// hi/lo bf16 split of a float pair, packed as bf16x2 words
__device__ __forceinline__ void split2(float x0, float x1,
                                       uint32_t& hi, uint32_t& lo) {
    __nv_bfloat162 h, l;
    h.x = __float2bfloat16(x0);
    h.y = __float2bfloat16(x1);
    l.x = __float2bfloat16(x0 - __bfloat162float(h.x));
    l.y = __float2bfloat16(x1 - __bfloat162float(h.y));
    hi = *(uint32_t*)&h;
    lo = *(uint32_t*)&l;
}

// hi/lo fp16 split of a float pair, packed as half2 words
__device__ __forceinline__ void split2h(float x0, float x1,
                                        uint32_t& hi, uint32_t& lo) {
    __half2 h, l;
    h.x = __float2half_rn(x0);
    h.y = __float2half_rn(x1);
    l.x = __float2half_rn(x0 - __half2float(h.x));
    l.y = __float2half_rn(x1 - __half2float(h.y));
    hi = *(uint32_t*)&h;
    lo = *(uint32_t*)&l;
}

// ---------------------------------------------------------------------------
// Kernel 1 (fused preprocessing): one launch covering
//   blocks [0, 4096):          LayerNorm + bf16 hi/lo split of activations
//   blocks [4096, 7168):       w_qkv transpose + split  (96 x 32 tiles)
//   blocks [7168, 8192):       w_out transpose + split  (32 x 32 tiles)
// ---------------------------------------------------------------------------
__device__ __forceinline__ void wsplit_body(float* sh,
                                            const float* __restrict__ W,
                                            __nv_bfloat16* __restrict__ hi,
                                            __nv_bfloat16* __restrict__ lo,
                                            int K, int N, int gx, int gy) {
    float (*tile)[33] = (float(*)[33])sh;
    const int bx = gx * 32;        // n base
    const int by = gy * 32;        // k base
    const int tx = threadIdx.x & 31;
    const int ty = threadIdx.x >> 5;

    #pragma unroll
    for (int i = 0; i < 32; i += 8)
        tile[ty + i][tx] = W[(size_t)(by + ty + i) * N + bx + tx];
    __syncthreads();
    #pragma unroll
    for (int i = 0; i < 32; i += 8) {
        float v = tile[tx][ty + i];
        __nv_bfloat16 h = __float2bfloat16(v);
        __nv_bfloat16 l = __float2bfloat16(v - __bfloat162float(h));
        size_t off = (size_t)(bx + ty + i) * K + by + tx;
        hi[off] = h;
        lo[off] = l;
    }
}

__global__ __launch_bounds__(256)
void pre_kernel(const float* __restrict__ x,
                const float* __restrict__ scale,
                __nv_bfloat16* __restrict__ a0,
                __nv_bfloat16* __restrict__ a1,
                const float* __restrict__ wqkv,
                __nv_bfloat16* __restrict__ wq0,
                __nv_bfloat16* __restrict__ wq1,
                const float* __restrict__ wout,
                __nv_bfloat16* __restrict__ wo0,
                __nv_bfloat16* __restrict__ wo1) {
    __shared__ float sh[32 * 33];
    const int bid = blockIdx.x;

    if (bid >= NROWS) {
        if (bid < NROWS + 3072) {
            int idx = bid - NROWS;
            wsplit_body(sh, wqkv, wq0, wq1, E_, Q3_, idx % 96, idx / 96);
        } else {
            int idx = bid - NROWS - 3072;
            wsplit_body(sh, wout, wo0, wo1, HD_, E_, idx % 32, idx / 32);
        }
        return;
    }

    // ---- LayerNorm + split ----
    float* red_s  = sh;
    float* red_ss = sh + 8;
    const int row = bid;
    const int t   = threadIdx.x;
    const float* xr = x + (size_t)row * E_;

    float4 v = *(const float4*)&xr[t * 4];
    float s  = v.x + v.y + v.z + v.w;
    float ss = v.x * v.x + v.y * v.y + v.z * v.z + v.w * v.w;

    #pragma unroll
    for (int o = 16; o; o >>= 1) {
        s  += __shfl_xor_sync(0xFFFFFFFFu, s,  o);
        ss += __shfl_xor_sync(0xFFFFFFFFu, ss, o);
    }
    if ((t & 31) == 0) { red_s[t >> 5] = s; red_ss[t >> 5] = ss; }
    __syncthreads();
    if (t < 32) {
        float s2  = (t < 8) ? red_s[t]  : 0.f;
        float ss2 = (t < 8) ? red_ss[t] : 0.f;
        #pragma unroll
        for (int o = 4; o; o >>= 1) {
            s2  += __shfl_xor_sync(0xFFFFFFFFu, s2,  o);
            ss2 += __shfl_xor_sync(0xFFFFFFFFu, ss2, o);
        }
        if (t == 0) { red_s[0] = s2; red_ss[0] = ss2; }
    }
    __syncthreads();

    const float inv_e = 1.f / (float)E_;
    float mu  = red_s[0] * inv_e;
    float var = red_ss[0] * inv_e - mu * mu;
    float r   = rsqrtf(var + 1e-6f);

    float4 sc = *(const float4*)&scale[t * 4];
    float ov[4];
    ov[0] = (v.x - mu) * r * sc.x;
    ov[1] = (v.y - mu) * r * sc.y;
    ov[2] = (v.z - mu) * r * sc.z;
    ov[3] = (v.w - mu) * r * sc.w;

    const size_t base = (size_t)row * E_ + t * 4;
    #pragma unroll
    for (int p = 0; p < 2; p++) {
        uint32_t hi, lo;
        split2(ov[p * 2], ov[p * 2 + 1], hi, lo);
        *(uint32_t*)&a0[base + p * 2] = hi;
        *(uint32_t*)&a1[base + p * 2] = lo;
    }
}

// ---------------------------------------------------------------------------
// Kernel 2: HMMA GEMM with bf16x3 split: C = A0*B0 + A0*B1 + A1*B0.
// 3-stage cp.async pipeline, ONE barrier per K-chunk.
// MODE 0: fp32 C store. MODE 1 (QKV): scatter to fp16 attention operands —
// Q hi/lo [bh][s][d], K single [bh][s][d], V single [bh][d][s] (transposed).
// ---------------------------------------------------------------------------
#define GBM 128
#define GBN 128
#define GBK 32
#define TILE_B   8192
#define STAGE_B  (4 * TILE_B)
#define GSM_TOTAL (3 * STAGE_B)       // 96 KB, 3 stages

template <int MODE>
__global__ __launch_bounds__(256, 2)
void mma_gemm_kernel(const __nv_bfloat16* __restrict__ A0,
                     const __nv_bfloat16* __restrict__ A1,
                     const __nv_bfloat16* __restrict__ B0,
                     const __nv_bfloat16* __restrict__ B1,
                     float* __restrict__ C,
                     __half* __restrict__ oQ0, __half* __restrict__ oQ1,
                     __half* __restrict__ oK0, __half* __restrict__ oV0,
                     int N, int K) {
    extern __shared__ char sm[];
    const uint32_t smb = smem_u32(sm);

    const int tid  = threadIdx.x;
    const int lane = tid & 31;
    const int wid  = tid >> 5;
    const int wm   = wid & 3;
    const int wn   = wid >> 2;
    const int blockRow = blockIdx.y * GBM;
    const int blockCol = blockIdx.x * GBN;

    float acc[2][8][4];
    #pragma unroll
    for (int i = 0; i < 2; i++)
        #pragma unroll
        for (int j = 0; j < 8; j++)
            #pragma unroll
            for (int q = 0; q < 4; q++) acc[i][j][q] = 0.f;

    const int r0 = (tid + 0)   >> 2, c0 = (tid + 0)   & 3;
    const int r1 = (tid + 256) >> 2, c1 = (tid + 256) & 3;
    const uint32_t so0 = soff(r0, c0), so1 = soff(r1, c1);

    const int NCH = K / GBK;               // 32

    // Prologue: stages 0 and 1 (chunks 0 and 1), separate commit groups
    #pragma unroll
    for (int st = 0; st < 2; st++) {
        const uint32_t sb = smb + st * STAGE_B;
        const int kb = st * GBK;
        cp16(sb + so0,              A0 + (size_t)(blockRow + r0) * K + kb + c0 * 8);
        cp16(sb + TILE_B + so0,     A1 + (size_t)(blockRow + r0) * K + kb + c0 * 8);
        cp16(sb + 2 * TILE_B + so0, B0 + (size_t)(blockCol + r0) * K + kb + c0 * 8);
        cp16(sb + 3 * TILE_B + so0, B1 + (size_t)(blockCol + r0) * K + kb + c0 * 8);
        cp16(sb + so1,              A0 + (size_t)(blockRow + r1) * K + kb + c1 * 8);
        cp16(sb + TILE_B + so1,     A1 + (size_t)(blockRow + r1) * K + kb + c1 * 8);
        cp16(sb + 2 * TILE_B + so1, B0 + (size_t)(blockCol + r1) * K + kb + c1 * 8);
        cp16(sb + 3 * TILE_B + so1, B1 + (size_t)(blockCol + r1) * K + kb + c1 * 8);
        CP_COMMIT();
    }

    const int rA = wm * 32 + (lane & 15);
    const int cAbase = lane >> 4;
    const int rB = wn * 64 + (lane & 7) + ((lane >> 4) << 3);
    const int cBbase = (lane >> 3) & 1;

    for (int ch = 0; ch < NCH; ch++) {
        if (ch + 1 < NCH) { CP_WAIT(1); } else { CP_WAIT(0); }
        __syncthreads();    // publish stage ch + prove compute ch-1 done

        if (ch + 2 < NCH) {
            const uint32_t sb = smb + ((ch + 2) % 3) * STAGE_B;
            const int kb = (ch + 2) * GBK;
            cp16(sb + so0,              A0 + (size_t)(blockRow + r0) * K + kb + c0 * 8);
            cp16(sb + TILE_B + so0,     A1 + (size_t)(blockRow + r0) * K + kb + c0 * 8);
            cp16(sb + 2 * TILE_B + so0, B0 + (size_t)(blockCol + r0) * K + kb + c0 * 8);
            cp16(sb + 3 * TILE_B + so0, B1 + (size_t)(blockCol + r0) * K + kb + c0 * 8);
            cp16(sb + so1,              A0 + (size_t)(blockRow + r1) * K + kb + c1 * 8);
            cp16(sb + TILE_B + so1,     A1 + (size_t)(blockRow + r1) * K + kb + c1 * 8);
            cp16(sb + 2 * TILE_B + so1, B0 + (size_t)(blockCol + r1) * K + kb + c1 * 8);
            cp16(sb + 3 * TILE_B + so1, B1 + (size_t)(blockCol + r1) * K + kb + c1 * 8);
            CP_COMMIT();
        }

        const uint32_t sb  = smb + (ch % 3) * STAGE_B;
        const uint32_t sA0 = sb;
        const uint32_t sA1 = sb + TILE_B;
        const uint32_t sB0 = sb + 2 * TILE_B;
        const uint32_t sB1 = sb + 3 * TILE_B;

        #pragma unroll
        for (int ks = 0; ks < 2; ks++) {
            const int cA = ks * 2 + cAbase;
            const int cB = ks * 2 + cBbase;
            uint32_t a0f[2][4], a1f[2][4];
            #pragma unroll
            for (int fm = 0; fm < 2; fm++) {
                ldsm4(a0f[fm], sA0 + soff(rA + fm * 16, cA));
                ldsm4(a1f[fm], sA1 + soff(rA + fm * 16, cA));
            }
            uint32_t bf[4][4];
            #pragma unroll
            for (int p = 0; p < 4; p++)
                ldsm4(bf[p], sB0 + soff(rB + p * 16, cB));
            #pragma unroll
            for (int fm = 0; fm < 2; fm++)
                #pragma unroll
                for (int fn = 0; fn < 8; fn++) {
                    mma_bf16(acc[fm][fn], a0f[fm], &bf[fn >> 1][(fn & 1) * 2]);
                    mma_bf16(acc[fm][fn], a1f[fm], &bf[fn >> 1][(fn & 1) * 2]);
                }
            #pragma unroll
            for (int p = 0; p < 4; p++)
                ldsm4(bf[p], sB1 + soff(rB + p * 16, cB));
            #pragma unroll
            for (int fm = 0; fm < 2; fm++)
                #pragma unroll
                for (int fn = 0; fn < 8; fn++)
                    mma_bf16(acc[fm][fn], a0f[fm], &bf[fn >> 1][(fn & 1) * 2]);
        }
        // no trailing barrier: next iteration's barrier protects stage reuse
    }

    if (MODE == 0) {
        // fp32 C store
        #pragma unroll
        for (int fm = 0; fm < 2; fm++) {
            const int rr = blockRow + wm * 32 + fm * 16 + (lane >> 2);
            #pragma unroll
            for (int fn = 0; fn < 8; fn++) {
                const int cc = blockCol + wn * 64 + fn * 8 + (lane & 3) * 2;
                *(float2*)&C[(size_t)rr * N + cc] =
                    make_float2(acc[fm][fn][0], acc[fm][fn][1]);
                *(float2*)&C[(size_t)(rr + 8) * N + cc] =
                    make_float2(acc[fm][fn][2], acc[fm][fn][3]);
            }
        }
    } else {
        // QKV scatter: part uniform per CTA (1024 | 128*gridX boundaries)
        const int part = blockCol >> 10;   // 0=q, 1=k, 2=v
        #pragma unroll
        for (int fm = 0; fm < 2; fm++) {
            const int rbase = blockRow + wm * 32 + fm * 16 + (lane >> 2);
            #pragma unroll
            for (int fn = 0; fn < 8; fn++) {
                const int cc = blockCol + wn * 64 + fn * 8 + (lane & 3) * 2;
                const int h = (cc >> 6) & 15;
                const int d = cc & 63;
                #pragma unroll
                for (int hf = 0; hf < 2; hf++) {
                    const int rr = rbase + hf * 8;
                    const int s = rr >> 1, b = rr & 1;
                    const int bh = b * 16 + h;
                    const float x0 = acc[fm][fn][hf * 2];
                    const float x1 = acc[fm][fn][hf * 2 + 1];
                    if (part == 0) {
                        uint32_t hi, lo;
                        split2h(x0, x1, hi, lo);
                        size_t off = ((size_t)bh * S_ + s) * D_ + d;
                        *(uint32_t*)&oQ0[off] = hi;
                        *(uint32_t*)&oQ1[off] = lo;
                    } else if (part == 1) {
                        __half2 hv;
                        hv.x = __float2half_rn(x0);
                        hv.y = __float2half_rn(x1);
                        size_t off = ((size_t)bh * S_ + s) * D_ + d;
                        *(__half2*)&oK0[off] = hv;
                    } else {
                        size_t offa = ((size_t)bh * D_ + d) * S_ + s;
                        size_t offb = ((size_t)bh * D_ + d + 1) * S_ + s;
                        oV0[offa] = __float2half_rn(x0);
                        oV0[offb] = __float2half_rn(x1);
                    }
                }
            }
        }
    }
}

// ---------------------------------------------------------------------------
// Kernel 3: fp16 tensor-core flash attention (A-side splits only).
// Grid (S/128, 32 bh). 256 threads = 8 warps; warp w owns q rows [16w,16w+16).
// QK^T = Q0*K + Q1*K (Q hi/lo fp16, K single fp16): 2 products.
// PV   = P0*V + P1*V (P split fp16 in-register, V single fp16): 2 products.
// K/V tiles (16 KB/stage) double-buffered via cp.async; single barrier/tile.
// ---------------------------------------------------------------------------
#define AQT 128
#define ASM_STAGE 16384     // K | V, each 8 KB
#define ASM_Q0 32768
#define ASM_Q1 49152
#define ASM_TOTAL 65536     // 64 KB

__global__ __launch_bounds__(256)
void attn_mma_kernel(const __half* __restrict__ Qh,
                     const __half* __restrict__ Ql,
                     const __half* __restrict__ Kh,
                     const __half* __restrict__ Vh,
                     __nv_bfloat16* __restrict__ c0,
                     __nv_bfloat16* __restrict__ c1) {
    extern __shared__ char sm[];
    const uint32_t smb = smem_u32(sm);
    const int tid  = threadIdx.x;
    const int lane = tid & 31;
    const int wq   = tid >> 5;               // 0..7
    const int bh   = blockIdx.y;             // b*16 + h
    const int qb   = blockIdx.x * AQT;
    const size_t kbase = (size_t)bh * S_ * D_;   // Q/K [bh][s][d]
    const size_t vbase = (size_t)bh * D_ * S_;   // V  [bh][d][s]

    // Stage Q hi/lo tiles [128][64] fp16 (group 0)
    #pragma unroll
    for (int i = 0; i < 4; i++) {
        int idx = tid + i * 256;             // 0..1023
        int r = idx >> 3, c = idx & 7;
        uint32_t so = s128(r, c);
        size_t g = kbase + (size_t)(qb + r) * D_ + c * 8;
        cp16(smb + ASM_Q0 + so, Qh + g);
        cp16(smb + ASM_Q1 + so, Ql + g);
    }
    CP_COMMIT();
    // Key tile 0 (group 1): K [64][64], V [64][64]
    #pragma unroll
    for (int i = 0; i < 2; i++) {
        int idx = tid + i * 256;             // 0..511
        int r = idx >> 3, c = idx & 7;
        uint32_t so = s128(r, c);
        cp16(smb + so,        Kh + kbase + (size_t)r * D_ + c * 8);
        cp16(smb + 8192 + so, Vh + vbase + (size_t)r * S_ + c * 8);
    }
    CP_COMMIT();
    CP_WAIT(1);        // Q resident (tile 0 may still be in flight)
    __syncthreads();

    // Q fragments (held for the whole kernel)
    uint32_t qfh[4][4], qfl[4][4];
    {
        const int rA = wq * 16 + (lane & 15);
        const int cA = lane >> 4;
        #pragma unroll
        for (int t = 0; t < 4; t++) {
            ldsm4(qfh[t], smb + ASM_Q0 + s128(rA, t * 2 + cA));
            ldsm4(qfl[t], smb + ASM_Q1 + s128(rA, t * 2 + cA));
        }
    }

    float acc[8][4];
    #pragma unroll
    for (int j = 0; j < 8; j++)
        #pragma unroll
        for (int q = 0; q < 4; q++) acc[j][q] = 0.f;
    float mrow[2] = {-1e30f, -1e30f};
    float lrow[2] = {0.f, 0.f};

    const int rB = (lane & 7) + ((lane >> 4) << 3);
    const int cB = (lane >> 3) & 1;
    const int NKT = S_ / 64;                 // 32 key tiles

    for (int kc = 0; kc < NKT; kc++) {
        CP_WAIT(0);         // stage kc ready (own groups)
        __syncthreads();    // publish stage kc + prove compute kc-1 done

        if (kc + 1 < NKT) {
            const uint32_t sb = smb + ((kc + 1) & 1) * ASM_STAGE;
            #pragma unroll
            for (int i = 0; i < 2; i++) {
                int idx = tid + i * 256;
                int r = idx >> 3, c = idx & 7;
                uint32_t so = s128(r, c);
                cp16(sb + so,
                     Kh + kbase + (size_t)((kc + 1) * 64 + r) * D_ + c * 8);
                cp16(sb + 8192 + so,
                     Vh + vbase + (size_t)r * S_ + (kc + 1) * 64 + c * 8);
            }
            CP_COMMIT();
        }
        const uint32_t sb = smb + (kc & 1) * ASM_STAGE;

        // ---- Scores: s[16q x 64k] over d=64, 2 split products ----
        float sc[8][4];
        #pragma unroll
        for (int j = 0; j < 8; j++)
            #pragma unroll
            for (int q = 0; q < 4; q++) sc[j][q] = 0.f;

        #pragma unroll
        for (int t = 0; t < 4; t++) {
            #pragma unroll
            for (int jj = 0; jj < 4; jj++) {
                uint32_t k0f[4];
                ldsm4(k0f, sb + s128(jj * 16 + rB, t * 2 + cB));
                mma_f16(sc[2 * jj],     qfh[t], &k0f[0]);
                mma_f16(sc[2 * jj + 1], qfh[t], &k0f[2]);
                mma_f16(sc[2 * jj],     qfl[t], &k0f[0]);
                mma_f16(sc[2 * jj + 1], qfl[t], &k0f[2]);
            }
        }

        // ---- Online softmax on fragments (rows r=lane>>2 and r+8) ----
        #pragma unroll
        for (int h2 = 0; h2 < 2; h2++) {
            float rm = sc[0][2 * h2];
            #pragma unroll
            for (int j = 0; j < 8; j++) {
                rm = fmaxf(rm, sc[j][2 * h2]);
                rm = fmaxf(rm, sc[j][2 * h2 + 1]);
            }
            rm = fmaxf(rm, __shfl_xor_sync(0xFFFFFFFFu, rm, 1));
            rm = fmaxf(rm, __shfl_xor_sync(0xFFFFFFFFu, rm, 2));
            float mnew = fmaxf(mrow[h2], rm);
            float al   = __expf(mrow[h2] - mnew);
            mrow[h2] = mnew;
            float rs = 0.f;
            #pragma unroll
            for (int j = 0; j < 8; j++) {
                float p0 = __expf(sc[j][2 * h2]     - mnew);
                float p1 = __expf(sc[j][2 * h2 + 1] - mnew);
                sc[j][2 * h2]     = p0;
                sc[j][2 * h2 + 1] = p1;
                rs += p0 + p1;
            }
            rs += __shfl_xor_sync(0xFFFFFFFFu, rs, 1);
            rs += __shfl_xor_sync(0xFFFFFFFFu, rs, 2);
            lrow[h2] = lrow[h2] * al + rs;
            #pragma unroll
            for (int j = 0; j < 8; j++) {
                acc[j][2 * h2]     *= al;
                acc[j][2 * h2 + 1] *= al;
            }
        }

        // ---- PV: ctx += P * V, 2 split products; P packed from C-frags ----
        #pragma unroll
        for (int t2 = 0; t2 < 4; t2++) {
            uint32_t ah[4], alo[4];
            split2h(sc[2 * t2][0],     sc[2 * t2][1],     ah[0], alo[0]);
            split2h(sc[2 * t2][2],     sc[2 * t2][3],     ah[1], alo[1]);
            split2h(sc[2 * t2 + 1][0], sc[2 * t2 + 1][1], ah[2], alo[2]);
            split2h(sc[2 * t2 + 1][2], sc[2 * t2 + 1][3], ah[3], alo[3]);
            #pragma unroll
            for (int jj = 0; jj < 4; jj++) {
                uint32_t v0f[4];
                ldsm4(v0f, sb + 8192 + s128(jj * 16 + rB, t2 * 2 + cB));
                mma_f16(acc[2 * jj],     ah,  &v0f[0]);
                mma_f16(acc[2 * jj + 1], ah,  &v0f[2]);
                mma_f16(acc[2 * jj],     alo, &v0f[0]);
                mma_f16(acc[2 * jj + 1], alo, &v0f[2]);
            }
        }
        // no trailing barrier: next iteration's barrier protects stage reuse
    }

    // ---- Epilogue: normalize, bf16 hi/lo split into c0/c1 [NROWS][HD] ----
    const int b = bh >> 4, h = bh & 15;
    const float inv0 = 1.f / lrow[0];
    const float inv1 = 1.f / lrow[1];
    const int r  = lane >> 2;
    const int c2 = (lane & 3) * 2;
    #pragma unroll
    for (int j = 0; j < 8; j++) {
        const int d = j * 8 + c2;
        const int qg = qb + wq * 16 + r;
        size_t off0 = (size_t)(qg * 2 + b) * HD_ + h * 64 + d;
        size_t off1 = (size_t)((qg + 8) * 2 + b) * HD_ + h * 64 + d;
        uint32_t hi, lo;
        split2(acc[j][0] * inv0, acc[j][1] * inv0, hi, lo);
        *(uint32_t*)&c0[off0] = hi;
        *(uint32_t*)&c1[off0] = lo;
        split2(acc[j][2] * inv1, acc[j][3] * inv1, hi, lo);
        *(uint32_t*)&c0[off1] = hi;
        *(uint32_t*)&c1[off1] = lo;
    }
}

// ---------------------------------------------------------------------------
// kernel_launch
// ---------------------------------------------------------------------------
extern "C" void kernel_launch(void* const* d_in, const int* in_sizes, int n_in,
                              void* d_out, int out_size) {
    const float* x        = (const float*)d_in[0];   // [S,B,E]
    const float* ln_scale = (const float*)d_in[1];   // [E]
    const float* w_qkv    = (const float*)d_in[2];   // [E, 3*H*D]
    const float* w_out    = (const float*)d_in[3];   // [H*D, E]
    float* out = (float*)d_out;                      // [S,B,E]

    __nv_bfloat16 *p_a0, *p_a1, *p_wq0, *p_wq1, *p_wo0, *p_wo1, *p_c0, *p_c1;
    __half *pQ0, *pQ1, *pK0, *pV0;
    cudaGetSymbolAddress((void**)&p_a0,  g_a0);
    cudaGetSymbolAddress((void**)&p_a1,  g_a1);
    cudaGetSymbolAddress((void**)&p_wq0, g_wq0);
    cudaGetSymbolAddress((void**)&p_wq1, g_wq1);
    cudaGetSymbolAddress((void**)&p_wo0, g_wo0);
    cudaGetSymbolAddress((void**)&p_wo1, g_wo1);
    cudaGetSymbolAddress((void**)&pQ0,   g_q0);
    cudaGetSymbolAddress((void**)&pQ1,   g_q1);
    cudaGetSymbolAddress((void**)&pK0,   g_k0);
    cudaGetSymbolAddress((void**)&pV0,   g_v0);
    cudaGetSymbolAddress((void**)&p_c0,  g_c0);
    cudaGetSymbolAddress((void**)&p_c1,  g_c1);

    cudaFuncSetAttribute(mma_gemm_kernel<0>,
                         cudaFuncAttributeMaxDynamicSharedMemorySize, GSM_TOTAL);
    cudaFuncSetAttribute(mma_gemm_kernel<1>,
                         cudaFuncAttributeMaxDynamicSharedMemorySize, GSM_TOTAL);
    cudaFuncSetAttribute(attn_mma_kernel,
                         cudaFuncAttributeMaxDynamicSharedMemorySize, ASM_TOTAL);

    // 1. Fused preprocessing: LayerNorm+split and both weight transpose+splits
    pre_kernel<<<NROWS + 3072 + 1024, 256>>>(
        x, ln_scale, p_a0, p_a1, w_qkv, p_wq0, p_wq1, w_out, p_wo0, p_wo1);

    // 2. QKV projection -> fp16 attention operands (V transposed)
    mma_gemm_kernel<1><<<dim3(Q3_ / GBN, NROWS / GBM), 256, GSM_TOTAL>>>(
        p_a0, p_a1, p_wq0, p_wq1, nullptr,
        pQ0, pQ1, pK0, pV0, Q3_, E_);

    // 3. fp16 tensor-core flash attention
    attn_mma_kernel<<<dim3(S_ / AQT, BH_), 256, ASM_TOTAL>>>(
        pQ0, pQ1, pK0, pV0, p_c0, p_c1);

    // 4. Output projection (fp32 out, bf16x3)
    mma_gemm_kernel<0><<<dim3(E_ / GBN, NROWS / GBM), 256, GSM_TOTAL>>>(
        p_c0, p_c1, p_wo0, p_wo1, out,
        nullptr, nullptr, nullptr, nullptr, E_, HD_);
}

// round 12
// speedup vs baseline: 6.5921x; 1.1791x over previous
#include <cuda_runtime.h>
#include <cuda_fp16.h>
#include <cstdint>

// Problem constants
#define S_    2048
#define B_    2
#define E_    1024
#define H_    16
#define D_    64
#define HD_   1024
#define Q3_   3072
#define NROWS (S_ * B_)   // 4096 rows, row index = s*B + b
#define BH_   32          // b*16 + h

// ---------------------------------------------------------------------------
// Scratch (device globals: cudaMalloc is forbidden by the harness)
// ---------------------------------------------------------------------------
__device__ __align__(16) __half g_a0[(size_t)NROWS * E_];   // LN out hi (fp16)
__device__ __align__(16) __half g_a1[(size_t)NROWS * E_];   // LN out lo
__device__ __align__(16) __half g_wq[(size_t)Q3_ * E_];     // w_qkv^T fp16 [3072,1024]
__device__ __align__(16) __half g_wo[(size_t)E_ * HD_];     // w_out^T fp16 [1024,1024]
// Attention operands (fp16), written by the QKV GEMM epilogue:
__device__ __align__(16) __half g_q0[(size_t)BH_ * S_ * D_];   // Q hi [bh][s][d]
__device__ __align__(16) __half g_q1[(size_t)BH_ * S_ * D_];   // Q lo
__device__ __align__(16) __half g_k0[(size_t)BH_ * S_ * D_];   // K single [bh][s][d]
__device__ __align__(16) __half g_v0[(size_t)BH_ * D_ * S_];   // V single [bh][d][s]
__device__ __align__(16) __half g_c0[(size_t)NROWS * HD_];  // ctx hi (fp16)
__device__ __align__(16) __half g_c1[(size_t)NROWS * HD_];  // ctx lo

// ---------------------------------------------------------------------------
// PTX helpers: arch-agnostic tensor path (mma.sync / ldmatrix / cp.async).
// tcgen05 is NOT usable: the harness PTX stage targets compute_103 (no 'a').
// ---------------------------------------------------------------------------
__device__ __forceinline__ uint32_t smem_u32(const void* p) {
    return (uint32_t)__cvta_generic_to_shared(p);
}

__device__ __forceinline__ void cp16(uint32_t saddr, const void* g) {
    asm volatile("cp.async.cg.shared.global [%0], [%1], 16;"
                 :: "r"(saddr), "l"(g));
}
#define CP_COMMIT() asm volatile("cp.async.commit_group;" ::: "memory")
#define CP_WAIT(n)  asm volatile("cp.async.wait_group %0;" :: "n"(n) : "memory")

__device__ __forceinline__ void ldsm4(uint32_t* r, uint32_t addr) {
    asm volatile("ldmatrix.sync.aligned.m8n8.x4.shared.b16 {%0,%1,%2,%3}, [%4];"
                 : "=r"(r[0]), "=r"(r[1]), "=r"(r[2]), "=r"(r[3]) : "r"(addr));
}

__device__ __forceinline__ void mma_f16(float* c, const uint32_t* a,
                                        const uint32_t* b) {
    asm volatile(
        "mma.sync.aligned.m16n8k16.row.col.f32.f16.f16.f32 "
        "{%0,%1,%2,%3}, {%4,%5,%6,%7}, {%8,%9}, {%0,%1,%2,%3};"
        : "+f"(c[0]), "+f"(c[1]), "+f"(c[2]), "+f"(c[3])
        : "r"(a[0]), "r"(a[1]), "r"(a[2]), "r"(a[3]), "r"(b[0]), "r"(b[1]));
}

// GEMM tiles: [128 x 32] fp16, 64-byte rows (4 x 16B chunks), chunk' = c^((r>>1)&3)
__device__ __forceinline__ uint32_t soff(int r, int c) {
    return (uint32_t)(r * 64 + ((c ^ ((r >> 1) & 3)) << 4));
}
// Attention tiles: [rows x 64] halfword, 128-byte rows (8 x 16B), chunk' = c^(r&7)
__device__ __forceinline__ uint32_t s128(int r, int c) {
    return (uint32_t)(r * 128 + ((c ^ (r & 7)) << 4));
}

// hi/lo fp16 split of a float pair, packed as half2 words
__device__ __forceinline__ void split2h(float x0, float x1,
                                        uint32_t& hi, uint32_t& lo) {
    __half2 h, l;
    h.x = __float2half_rn(x0);
    h.y = __float2half_rn(x1);
    l.x = __float2half_rn(x0 - __half2float(h.x));
    l.y = __float2half_rn(x1 - __half2float(h.y));
    hi = *(uint32_t*)&h;
    lo = *(uint32_t*)&l;
}

// ---------------------------------------------------------------------------
// Kernel 1 (fused preprocessing): one launch covering
//   blocks [0, 4096):          LayerNorm + fp16 hi/lo split of activations
//   blocks [4096, 7168):       w_qkv transpose -> fp16  (96 x 32 tiles)
//   blocks [7168, 8192):       w_out transpose -> fp16  (32 x 32 tiles)
// ---------------------------------------------------------------------------
__device__ __forceinline__ void wtrans_body(float* sh,
                                            const float* __restrict__ W,
                                            __half* __restrict__ o,
                                            int K, int N, int gx, int gy) {
    float (*tile)[33] = (float(*)[33])sh;
    const int bx = gx * 32;        // n base
    const int by = gy * 32;        // k base
    const int tx = threadIdx.x & 31;
    const int ty = threadIdx.x >> 5;

    #pragma unroll
    for (int i = 0; i < 32; i += 8)
        tile[ty + i][tx] = W[(size_t)(by + ty + i) * N + bx + tx];
    __syncthreads();
    #pragma unroll
    for (int i = 0; i < 32; i += 8) {
        float v = tile[tx][ty + i];
        o[(size_t)(bx + ty + i) * K + by + tx] = __float2half_rn(v);
    }
}

__global__ __launch_bounds__(256)
void pre_kernel(const float* __restrict__ x,
                const float* __restrict__ scale,
                __half* __restrict__ a0,
                __half* __restrict__ a1,
                const float* __restrict__ wqkv,
                __half* __restrict__ wq,
                const float* __restrict__ wout,
                __half* __restrict__ wo) {
    __shared__ float sh[32 * 33];
    const int bid = blockIdx.x;

    if (bid >= NROWS) {
        if (bid < NROWS + 3072) {
            int idx = bid - NROWS;
            wtrans_body(sh, wqkv, wq, E_, Q3_, idx % 96, idx / 96);
        } else {
            int idx = bid - NROWS - 3072;
            wtrans_body(sh, wout, wo, HD_, E_, idx % 32, idx / 32);
        }
        return;
    }

    // ---- LayerNorm + split ----
    float* red_s  = sh;
    float* red_ss = sh + 8;
    const int row = bid;
    const int t   = threadIdx.x;
    const float* xr = x + (size_t)row * E_;

    float4 v = *(const float4*)&xr[t * 4];
    float s  = v.x + v.y + v.z + v.w;
    float ss = v.x * v.x + v.y * v.y + v.z * v.z + v.w * v.w;

    #pragma unroll
    for (int o = 16; o; o >>= 1) {
        s  += __shfl_xor_sync(0xFFFFFFFFu, s,  o);
        ss += __shfl_xor_sync(0xFFFFFFFFu, ss, o);
    }
    if ((t & 31) == 0) { red_s[t >> 5] = s; red_ss[t >> 5] = ss; }
    __syncthreads();
    if (t < 32) {
        float s2  = (t < 8) ? red_s[t]  : 0.f;
        float ss2 = (t < 8) ? red_ss[t] : 0.f;
        #pragma unroll
        for (int o = 4; o; o >>= 1) {
            s2  += __shfl_xor_sync(0xFFFFFFFFu, s2,  o);
            ss2 += __shfl_xor_sync(0xFFFFFFFFu, ss2, o);
        }
        if (t == 0) { red_s[0] = s2; red_ss[0] = ss2; }
    }
    __syncthreads();

    const float inv_e = 1.f / (float)E_;
    float mu  = red_s[0] * inv_e;
    float var = red_ss[0] * inv_e - mu * mu;
    float r   = rsqrtf(var + 1e-6f);

    float4 sc = *(const float4*)&scale[t * 4];
    float ov[4];
    ov[0] = (v.x - mu) * r * sc.x;
    ov[1] = (v.y - mu) * r * sc.y;
    ov[2] = (v.z - mu) * r * sc.z;
    ov[3] = (v.w - mu) * r * sc.w;

    const size_t base = (size_t)row * E_ + t * 4;
    #pragma unroll
    for (int p = 0; p < 2; p++) {
        uint32_t hi, lo;
        split2h(ov[p * 2], ov[p * 2 + 1], hi, lo);
        *(uint32_t*)&a0[base + p * 2] = hi;
        *(uint32_t*)&a1[base + p * 2] = lo;
    }
}

// ---------------------------------------------------------------------------
// Kernel 2: HMMA fp16 GEMM, A-side split only: C = A0*B + A1*B
// (A0/A1 = activation hi/lo fp16, B = weight single fp16, [N,K] K-major).
// 3-stage cp.async pipeline (3 tiles x 8KB per stage), ONE barrier per chunk.
// MODE 0: fp32 C store. MODE 1 (QKV): scatter to fp16 attention operands —
// Q hi/lo [bh][s][d], K single [bh][s][d], V single [bh][d][s] (transposed).
// ---------------------------------------------------------------------------
#define GBM 128
#define GBN 128
#define GBK 32
#define TILE_B   8192
#define STAGE_B  (3 * TILE_B)         // A0 | A1 | B
#define GSM_TOTAL (3 * STAGE_B)       // 72 KB, 3 stages

template <int MODE>
__global__ __launch_bounds__(256, 2)
void mma_gemm_kernel(const __half* __restrict__ A0,
                     const __half* __restrict__ A1,
                     const __half* __restrict__ B,
                     float* __restrict__ C,
                     __half* __restrict__ oQ0, __half* __restrict__ oQ1,
                     __half* __restrict__ oK0, __half* __restrict__ oV0,
                     int N, int K) {
    extern __shared__ char sm[];
    const uint32_t smb = smem_u32(sm);

    const int tid  = threadIdx.x;
    const int lane = tid & 31;
    const int wid  = tid >> 5;
    const int wm   = wid & 3;
    const int wn   = wid >> 2;
    const int blockRow = blockIdx.y * GBM;
    const int blockCol = blockIdx.x * GBN;

    float acc[2][8][4];
    #pragma unroll
    for (int i = 0; i < 2; i++)
        #pragma unroll
        for (int j = 0; j < 8; j++)
            #pragma unroll
            for (int q = 0; q < 4; q++) acc[i][j][q] = 0.f;

    const int r0 = (tid + 0)   >> 2, c0 = (tid + 0)   & 3;
    const int r1 = (tid + 256) >> 2, c1 = (tid + 256) & 3;
    const uint32_t so0 = soff(r0, c0), so1 = soff(r1, c1);

    const int NCH = K / GBK;               // 32

    // Prologue: stages 0 and 1 (chunks 0 and 1), separate commit groups
    #pragma unroll
    for (int st = 0; st < 2; st++) {
        const uint32_t sb = smb + st * STAGE_B;
        const int kb = st * GBK;
        cp16(sb + so0,              A0 + (size_t)(blockRow + r0) * K + kb + c0 * 8);
        cp16(sb + TILE_B + so0,     A1 + (size_t)(blockRow + r0) * K + kb + c0 * 8);
        cp16(sb + 2 * TILE_B + so0, B  + (size_t)(blockCol + r0) * K + kb + c0 * 8);
        cp16(sb + so1,              A0 + (size_t)(blockRow + r1) * K + kb + c1 * 8);
        cp16(sb + TILE_B + so1,     A1 + (size_t)(blockRow + r1) * K + kb + c1 * 8);
        cp16(sb + 2 * TILE_B + so1, B  + (size_t)(blockCol + r1) * K + kb + c1 * 8);
        CP_COMMIT();
    }

    const int rA = wm * 32 + (lane & 15);
    const int cAbase = lane >> 4;
    const int rB = wn * 64 + (lane & 7) + ((lane >> 4) << 3);
    const int cBbase = (lane >> 3) & 1;

    for (int ch = 0; ch < NCH; ch++) {
        if (ch + 1 < NCH) { CP_WAIT(1); } else { CP_WAIT(0); }
        __syncthreads();    // publish stage ch + prove compute ch-1 done

        if (ch + 2 < NCH) {
            const uint32_t sb = smb + ((ch + 2) % 3) * STAGE_B;
            const int kb = (ch + 2) * GBK;
            cp16(sb + so0,              A0 + (size_t)(blockRow + r0) * K + kb + c0 * 8);
            cp16(sb + TILE_B + so0,     A1 + (size_t)(blockRow + r0) * K + kb + c0 * 8);
            cp16(sb + 2 * TILE_B + so0, B  + (size_t)(blockCol + r0) * K + kb + c0 * 8);
            cp16(sb + so1,              A0 + (size_t)(blockRow + r1) * K + kb + c1 * 8);
            cp16(sb + TILE_B + so1,     A1 + (size_t)(blockRow + r1) * K + kb + c1 * 8);
            cp16(sb + 2 * TILE_B + so1, B  + (size_t)(blockCol + r1) * K + kb + c1 * 8);
            CP_COMMIT();
        }

        const uint32_t sb  = smb + (ch % 3) * STAGE_B;
        const uint32_t sA0 = sb;
        const uint32_t sA1 = sb + TILE_B;
        const uint32_t sB  = sb + 2 * TILE_B;

        #pragma unroll
        for (int ks = 0; ks < 2; ks++) {
            const int cA = ks * 2 + cAbase;
            const int cB = ks * 2 + cBbase;
            uint32_t a0f[2][4], a1f[2][4];
            #pragma unroll
            for (int fm = 0; fm < 2; fm++) {
                ldsm4(a0f[fm], sA0 + soff(rA + fm * 16, cA));
                ldsm4(a1f[fm], sA1 + soff(rA + fm * 16, cA));
            }
            uint32_t bf[4][4];
            #pragma unroll
            for (int p = 0; p < 4; p++)
                ldsm4(bf[p], sB + soff(rB + p * 16, cB));
            #pragma unroll
            for (int fm = 0; fm < 2; fm++)
                #pragma unroll
                for (int fn = 0; fn < 8; fn++) {
                    mma_f16(acc[fm][fn], a0f[fm], &bf[fn >> 1][(fn & 1) * 2]);
                    mma_f16(acc[fm][fn], a1f[fm], &bf[fn >> 1][(fn & 1) * 2]);
                }
        }
        // no trailing barrier: next iteration's barrier protects stage reuse
    }

    if (MODE == 0) {
        // fp32 C store
        #pragma unroll
        for (int fm = 0; fm < 2; fm++) {
            const int rr = blockRow + wm * 32 + fm * 16 + (lane >> 2);
            #pragma unroll
            for (int fn = 0; fn < 8; fn++) {
                const int cc = blockCol + wn * 64 + fn * 8 + (lane & 3) * 2;
                *(float2*)&C[(size_t)rr * N + cc] =
                    make_float2(acc[fm][fn][0], acc[fm][fn][1]);
                *(float2*)&C[(size_t)(rr + 8) * N + cc] =
                    make_float2(acc[fm][fn][2], acc[fm][fn][3]);
            }
        }
    } else {
        // QKV scatter: part uniform per CTA (1024 | 128*gridX boundaries)
        const int part = blockCol >> 10;   // 0=q, 1=k, 2=v
        #pragma unroll
        for (int fm = 0; fm < 2; fm++) {
            const int rbase = blockRow + wm * 32 + fm * 16 + (lane >> 2);
            #pragma unroll
            for (int fn = 0; fn < 8; fn++) {
                const int cc = blockCol + wn * 64 + fn * 8 + (lane & 3) * 2;
                const int h = (cc >> 6) & 15;
                const int d = cc & 63;
                #pragma unroll
                for (int hf = 0; hf < 2; hf++) {
                    const int rr = rbase + hf * 8;
                    const int s = rr >> 1, b = rr & 1;
                    const int bh = b * 16 + h;
                    const float x0 = acc[fm][fn][hf * 2];
                    const float x1 = acc[fm][fn][hf * 2 + 1];
                    if (part == 0) {
                        uint32_t hi, lo;
                        split2h(x0, x1, hi, lo);
                        size_t off = ((size_t)bh * S_ + s) * D_ + d;
                        *(uint32_t*)&oQ0[off] = hi;
                        *(uint32_t*)&oQ1[off] = lo;
                    } else if (part == 1) {
                        __half2 hv;
                        hv.x = __float2half_rn(x0);
                        hv.y = __float2half_rn(x1);
                        size_t off = ((size_t)bh * S_ + s) * D_ + d;
                        *(__half2*)&oK0[off] = hv;
                    } else {
                        size_t offa = ((size_t)bh * D_ + d) * S_ + s;
                        size_t offb = ((size_t)bh * D_ + d + 1) * S_ + s;
                        oV0[offa] = __float2half_rn(x0);
                        oV0[offb] = __float2half_rn(x1);
                    }
                }
            }
        }
    }
}

// ---------------------------------------------------------------------------
// Kernel 3: fp16 tensor-core flash attention (A-side splits only).
// Grid (S/128, 32 bh). 256 threads = 8 warps; warp w owns q rows [16w,16w+16).
// QK^T = Q0*K + Q1*K (Q hi/lo fp16, K single fp16): 2 products.
// PV   = P0*V + P1*V (P split fp16 in-register, V single fp16): 2 products.
// K/V tiles (16 KB/stage) double-buffered via cp.async; single barrier/tile.
// Epilogue: ctx hi/lo fp16 for the fp16 out-projection.
// ---------------------------------------------------------------------------
#define AQT 128
#define ASM_STAGE 16384     // K | V, each 8 KB
#define ASM_Q0 32768
#define ASM_Q1 49152
#define ASM_TOTAL 65536     // 64 KB

__global__ __launch_bounds__(256)
void attn_mma_kernel(const __half* __restrict__ Qh,
                     const __half* __restrict__ Ql,
                     const __half* __restrict__ Kh,
                     const __half* __restrict__ Vh,
                     __half* __restrict__ c0,
                     __half* __restrict__ c1) {
    extern __shared__ char sm[];
    const uint32_t smb = smem_u32(sm);
    const int tid  = threadIdx.x;
    const int lane = tid & 31;
    const int wq   = tid >> 5;               // 0..7
    const int bh   = blockIdx.y;             // b*16 + h
    const int qb   = blockIdx.x * AQT;
    const size_t kbase = (size_t)bh * S_ * D_;   // Q/K [bh][s][d]
    const size_t vbase = (size_t)bh * D_ * S_;   // V  [bh][d][s]

    // Stage Q hi/lo tiles [128][64] fp16 (group 0)
    #pragma unroll
    for (int i = 0; i < 4; i++) {
        int idx = tid + i * 256;             // 0..1023
        int r = idx >> 3, c = idx & 7;
        uint32_t so = s128(r, c);
        size_t g = kbase + (size_t)(qb + r) * D_ + c * 8;
        cp16(smb + ASM_Q0 + so, Qh + g);
        cp16(smb + ASM_Q1 + so, Ql + g);
    }
    CP_COMMIT();
    // Key tile 0 (group 1): K [64][64], V [64][64]
    #pragma unroll
    for (int i = 0; i < 2; i++) {
        int idx = tid + i * 256;             // 0..511
        int r = idx >> 3, c = idx & 7;
        uint32_t so = s128(r, c);
        cp16(smb + so,        Kh + kbase + (size_t)r * D_ + c * 8);
        cp16(smb + 8192 + so, Vh + vbase + (size_t)r * S_ + c * 8);
    }
    CP_COMMIT();
    CP_WAIT(1);        // Q resident (tile 0 may still be in flight)
    __syncthreads();

    // Q fragments (held for the whole kernel)
    uint32_t qfh[4][4], qfl[4][4];
    {
        const int rA = wq * 16 + (lane & 15);
        const int cA = lane >> 4;
        #pragma unroll
        for (int t = 0; t < 4; t++) {
            ldsm4(qfh[t], smb + ASM_Q0 + s128(rA, t * 2 + cA));
            ldsm4(qfl[t], smb + ASM_Q1 + s128(rA, t * 2 + cA));
        }
    }

    float acc[8][4];
    #pragma unroll
    for (int j = 0; j < 8; j++)
        #pragma unroll
        for (int q = 0; q < 4; q++) acc[j][q] = 0.f;
    float mrow[2] = {-1e30f, -1e30f};
    float lrow[2] = {0.f, 0.f};

    const int rB = (lane & 7) + ((lane >> 4) << 3);
    const int cB = (lane >> 3) & 1;
    const int NKT = S_ / 64;                 // 32 key tiles

    for (int kc = 0; kc < NKT; kc++) {
        CP_WAIT(0);         // stage kc ready (own groups)
        __syncthreads();    // publish stage kc + prove compute kc-1 done

        if (kc + 1 < NKT) {
            const uint32_t sb = smb + ((kc + 1) & 1) * ASM_STAGE;
            #pragma unroll
            for (int i = 0; i < 2; i++) {
                int idx = tid + i * 256;
                int r = idx >> 3, c = idx & 7;
                uint32_t so = s128(r, c);
                cp16(sb + so,
                     Kh + kbase + (size_t)((kc + 1) * 64 + r) * D_ + c * 8);
                cp16(sb + 8192 + so,
                     Vh + vbase + (size_t)r * S_ + (kc + 1) * 64 + c * 8);
            }
            CP_COMMIT();
        }
        const uint32_t sb = smb + (kc & 1) * ASM_STAGE;

        // ---- Scores: s[16q x 64k] over d=64, 2 split products ----
        float sc[8][4];
        #pragma unroll
        for (int j = 0; j < 8; j++)
            #pragma unroll
            for (int q = 0; q < 4; q++) sc[j][q] = 0.f;

        #pragma unroll
        for (int t = 0; t < 4; t++) {
            #pragma unroll
            for (int jj = 0; jj < 4; jj++) {
                uint32_t k0f[4];
                ldsm4(k0f, sb + s128(jj * 16 + rB, t * 2 + cB));
                mma_f16(sc[2 * jj],     qfh[t], &k0f[0]);
                mma_f16(sc[2 * jj + 1], qfh[t], &k0f[2]);
                mma_f16(sc[2 * jj],     qfl[t], &k0f[0]);
                mma_f16(sc[2 * jj + 1], qfl[t], &k0f[2]);
            }
        }

        // ---- Online softmax on fragments (rows r=lane>>2 and r+8) ----
        #pragma unroll
        for (int h2 = 0; h2 < 2; h2++) {
            float rm = sc[0][2 * h2];
            #pragma unroll
            for (int j = 0; j < 8; j++) {
                rm = fmaxf(rm, sc[j][2 * h2]);
                rm = fmaxf(rm, sc[j][2 * h2 + 1]);
            }
            rm = fmaxf(rm, __shfl_xor_sync(0xFFFFFFFFu, rm, 1));
            rm = fmaxf(rm, __shfl_xor_sync(0xFFFFFFFFu, rm, 2));
            float mnew = fmaxf(mrow[h2], rm);
            float al   = __expf(mrow[h2] - mnew);
            mrow[h2] = mnew;
            float rs = 0.f;
            #pragma unroll
            for (int j = 0; j < 8; j++) {
                float p0 = __expf(sc[j][2 * h2]     - mnew);
                float p1 = __expf(sc[j][2 * h2 + 1] - mnew);
                sc[j][2 * h2]     = p0;
                sc[j][2 * h2 + 1] = p1;
                rs += p0 + p1;
            }
            rs += __shfl_xor_sync(0xFFFFFFFFu, rs, 1);
            rs += __shfl_xor_sync(0xFFFFFFFFu, rs, 2);
            lrow[h2] = lrow[h2] * al + rs;
            #pragma unroll
            for (int j = 0; j < 8; j++) {
                acc[j][2 * h2]     *= al;
                acc[j][2 * h2 + 1] *= al;
            }
        }

        // ---- PV: ctx += P * V, 2 split products; P packed from C-frags ----
        #pragma unroll
        for (int t2 = 0; t2 < 4; t2++) {
            uint32_t ah[4], alo[4];
            split2h(sc[2 * t2][0],     sc[2 * t2][1],     ah[0], alo[0]);
            split2h(sc[2 * t2][2],     sc[2 * t2][3],     ah[1], alo[1]);
            split2h(sc[2 * t2 + 1][0], sc[2 * t2 + 1][1], ah[2], alo[2]);
            split2h(sc[2 * t2 + 1][2], sc[2 * t2 + 1][3], ah[3], alo[3]);
            #pragma unroll
            for (int jj = 0; jj < 4; jj++) {
                uint32_t v0f[4];
                ldsm4(v0f, sb + 8192 + s128(jj * 16 + rB, t2 * 2 + cB));
                mma_f16(acc[2 * jj],     ah,  &v0f[0]);
                mma_f16(acc[2 * jj + 1], ah,  &v0f[2]);
                mma_f16(acc[2 * jj],     alo, &v0f[0]);
                mma_f16(acc[2 * jj + 1], alo, &v0f[2]);
            }
        }
        // no trailing barrier: next iteration's barrier protects stage reuse
    }

    // ---- Epilogue: normalize, fp16 hi/lo split into c0/c1 [NROWS][HD] ----
    const int b = bh >> 4, h = bh & 15;
    const float inv0 = 1.f / lrow[0];
    const float inv1 = 1.f / lrow[1];
    const int r  = lane >> 2;
    const int c2 = (lane & 3) * 2;
    #pragma unroll
    for (int j = 0; j < 8; j++) {
        const int d = j * 8 + c2;
        const int qg = qb + wq * 16 + r;
        size_t off0 = (size_t)(qg * 2 + b) * HD_ + h * 64 + d;
        size_t off1 = (size_t)((qg + 8) * 2 + b) * HD_ + h * 64 + d;
        uint32_t hi, lo;
        split2h(acc[j][0] * inv0, acc[j][1] * inv0, hi, lo);
        *(uint32_t*)&c0[off0] = hi;
        *(uint32_t*)&c1[off0] = lo;
        split2h(acc[j][2] * inv1, acc[j][3] * inv1, hi, lo);
        *(uint32_t*)&c0[off1] = hi;
        *(uint32_t*)&c1[off1] = lo;
    }
}

// ---------------------------------------------------------------------------
// kernel_launch
// ---------------------------------------------------------------------------
extern "C" void kernel_launch(void* const* d_in, const int* in_sizes, int n_in,
                              void* d_out, int out_size) {
    const float* x        = (const float*)d_in[0];   // [S,B,E]
    const float* ln_scale = (const float*)d_in[1];   // [E]
    const float* w_qkv    = (const float*)d_in[2];   // [E, 3*H*D]
    const float* w_out    = (const float*)d_in[3];   // [H*D, E]
    float* out = (float*)d_out;                      // [S,B,E]

    __half *p_a0, *p_a1, *p_wq, *p_wo;
    __half *pQ0, *pQ1, *pK0, *pV0, *p_c0, *p_c1;
    cudaGetSymbolAddress((void**)&p_a0, g_a0);
    cudaGetSymbolAddress((void**)&p_a1, g_a1);
    cudaGetSymbolAddress((void**)&p_wq, g_wq);
    cudaGetSymbolAddress((void**)&p_wo, g_wo);
    cudaGetSymbolAddress((void**)&pQ0,  g_q0);
    cudaGetSymbolAddress((void**)&pQ1,  g_q1);
    cudaGetSymbolAddress((void**)&pK0,  g_k0);
    cudaGetSymbolAddress((void**)&pV0,  g_v0);
    cudaGetSymbolAddress((void**)&p_c0, g_c0);
    cudaGetSymbolAddress((void**)&p_c1, g_c1);

    cudaFuncSetAttribute(mma_gemm_kernel<0>,
                         cudaFuncAttributeMaxDynamicSharedMemorySize, GSM_TOTAL);
    cudaFuncSetAttribute(mma_gemm_kernel<1>,
                         cudaFuncAttributeMaxDynamicSharedMemorySize, GSM_TOTAL);
    cudaFuncSetAttribute(attn_mma_kernel,
                         cudaFuncAttributeMaxDynamicSharedMemorySize, ASM_TOTAL);

    // 1. Fused preprocessing: LayerNorm+split and both weight transposes
    pre_kernel<<<NROWS + 3072 + 1024, 256>>>(
        x, ln_scale, p_a0, p_a1, w_qkv, p_wq, w_out, p_wo);

    // 2. QKV projection -> fp16 attention operands (V transposed)
    mma_gemm_kernel<1><<<dim3(Q3_ / GBN, NROWS / GBM), 256, GSM_TOTAL>>>(
        p_a0, p_a1, p_wq, nullptr,
        pQ0, pQ1, pK0, pV0, Q3_, E_);

    // 3. fp16 tensor-core flash attention
    attn_mma_kernel<<<dim3(S_ / AQT, BH_), 256, ASM_TOTAL>>>(
        pQ0, pQ1, pK0, pV0, p_c0, p_c1);

    // 4. Output projection (fp32 out)
    mma_gemm_kernel<0><<<dim3(E_ / GBN, NROWS / GBM), 256, GSM_TOTAL>>>(
        p_c0, p_c1, p_wo, out,
        nullptr, nullptr, nullptr, nullptr, E_, HD_);
}

// round 13
// speedup vs baseline: 9.1841x; 1.3932x over previous
#include <cuda_runtime.h>
#include <cuda_fp16.h>
#include <cstdint>

// Problem constants
#define S_    2048
#define B_    2
#define E_    1024
#define H_    16
#define D_    64
#define HD_   1024
#define Q3_   3072
#define NROWS (S_ * B_)   // 4096 rows, row index = s*B + b
#define BH_   32          // b*16 + h

// ---------------------------------------------------------------------------
// Scratch (device globals: cudaMalloc is forbidden by the harness)
// ---------------------------------------------------------------------------
__device__ __align__(16) __half g_a0[(size_t)NROWS * E_];   // LN out hi (fp16)
__device__ __align__(16) __half g_a1[(size_t)NROWS * E_];   // LN out lo
__device__ __align__(16) __half g_wq[(size_t)Q3_ * E_];     // w_qkv^T fp16 [3072,1024]
__device__ __align__(16) __half g_wo[(size_t)E_ * HD_];     // w_out^T fp16 [1024,1024]
// Attention operands (single fp16), written by the QKV GEMM epilogue:
__device__ __align__(16) __half g_q0[(size_t)BH_ * S_ * D_];   // Q [bh][s][d]
__device__ __align__(16) __half g_k0[(size_t)BH_ * S_ * D_];   // K [bh][s][d]
__device__ __align__(16) __half g_v0[(size_t)BH_ * D_ * S_];   // V [bh][d][s]
__device__ __align__(16) __half g_c0[(size_t)NROWS * HD_];  // ctx hi (fp16)
__device__ __align__(16) __half g_c1[(size_t)NROWS * HD_];  // ctx lo

// ---------------------------------------------------------------------------
// PTX helpers: arch-agnostic tensor path (mma.sync / ldmatrix / cp.async).
// tcgen05 is NOT usable: the harness PTX stage targets compute_103 (no 'a').
// ---------------------------------------------------------------------------
__device__ __forceinline__ uint32_t smem_u32(const void* p) {
    return (uint32_t)__cvta_generic_to_shared(p);
}

__device__ __forceinline__ void cp16(uint32_t saddr, const void* g) {
    asm volatile("cp.async.cg.shared.global [%0], [%1], 16;"
                 :: "r"(saddr), "l"(g));
}
#define CP_COMMIT() asm volatile("cp.async.commit_group;" ::: "memory")
#define CP_WAIT(n)  asm volatile("cp.async.wait_group %0;" :: "n"(n) : "memory")

__device__ __forceinline__ void ldsm4(uint32_t* r, uint32_t addr) {
    asm volatile("ldmatrix.sync.aligned.m8n8.x4.shared.b16 {%0,%1,%2,%3}, [%4];"
                 : "=r"(r[0]), "=r"(r[1]), "=r"(r[2]), "=r"(r[3]) : "r"(addr));
}

__device__ __forceinline__ void mma_f16(float* c, const uint32_t* a,
                                        const uint32_t* b) {
    asm volatile(
        "mma.sync.aligned.m16n8k16.row.col.f32.f16.f16.f32 "
        "{%0,%1,%2,%3}, {%4,%5,%6,%7}, {%8,%9}, {%0,%1,%2,%3};"
        : "+f"(c[0]), "+f"(c[1]), "+f"(c[2]), "+f"(c[3])
        : "r"(a[0]), "r"(a[1]), "r"(a[2]), "r"(a[3]), "r"(b[0]), "r"(b[1]));
}

// GEMM tiles: [128 x 32] fp16, 64-byte rows (4 x 16B chunks), chunk' = c^((r>>1)&3)
__device__ __forceinline__ uint32_t soff(int r, int c) {
    return (uint32_t)(r * 64 + ((c ^ ((r >> 1) & 3)) << 4));
}
// Attention tiles: [rows x 64] halfword, 128-byte rows (8 x 16B), chunk' = c^(r&7)
__device__ __forceinline__ uint32_t s128(int r, int c) {
    return (uint32_t)(r * 128 + ((c ^ (r & 7)) << 4));
}

// hi/lo fp16 split of a float pair, packed as half2 words
__device__ __forceinline__ void split2h(float x0, float x1,
                                        uint32_t& hi, uint32_t& lo) {
    __half2 h, l;
    h.x = __float2half_rn(x0);
    h.y = __float2half_rn(x1);
    l.x = __float2half_rn(x0 - __half2float(h.x));
    l.y = __float2half_rn(x1 - __half2float(h.y));
    hi = *(uint32_t*)&h;
    lo = *(uint32_t*)&l;
}

// plain fp16 pack of a float pair
__device__ __forceinline__ uint32_t pack2h(float x0, float x1) {
    __half2 h;
    h.x = __float2half_rn(x0);
    h.y = __float2half_rn(x1);
    return *(uint32_t*)&h;
}

// ---------------------------------------------------------------------------
// Kernel 1 (fused preprocessing): one launch covering
//   blocks [0, 4096):          LayerNorm + fp16 hi/lo split of activations
//   blocks [4096, 7168):       w_qkv transpose -> fp16  (96 x 32 tiles)
//   blocks [7168, 8192):       w_out transpose -> fp16  (32 x 32 tiles)
// ---------------------------------------------------------------------------
__device__ __forceinline__ void wtrans_body(float* sh,
                                            const float* __restrict__ W,
                                            __half* __restrict__ o,
                                            int K, int N, int gx, int gy) {
    float (*tile)[33] = (float(*)[33])sh;
    const int bx = gx * 32;        // n base
    const int by = gy * 32;        // k base
    const int tx = threadIdx.x & 31;
    const int ty = threadIdx.x >> 5;

    #pragma unroll
    for (int i = 0; i < 32; i += 8)
        tile[ty + i][tx] = W[(size_t)(by + ty + i) * N + bx + tx];
    __syncthreads();
    #pragma unroll
    for (int i = 0; i < 32; i += 8) {
        float v = tile[tx][ty + i];
        o[(size_t)(bx + ty + i) * K + by + tx] = __float2half_rn(v);
    }
}

__global__ __launch_bounds__(256)
void pre_kernel(const float* __restrict__ x,
                const float* __restrict__ scale,
                __half* __restrict__ a0,
                __half* __restrict__ a1,
                const float* __restrict__ wqkv,
                __half* __restrict__ wq,
                const float* __restrict__ wout,
                __half* __restrict__ wo) {
    __shared__ float sh[32 * 33];
    const int bid = blockIdx.x;

    if (bid >= NROWS) {
        if (bid < NROWS + 3072) {
            int idx = bid - NROWS;
            wtrans_body(sh, wqkv, wq, E_, Q3_, idx % 96, idx / 96);
        } else {
            int idx = bid - NROWS - 3072;
            wtrans_body(sh, wout, wo, HD_, E_, idx % 32, idx / 32);
        }
        return;
    }

    // ---- LayerNorm + split ----
    float* red_s  = sh;
    float* red_ss = sh + 8;
    const int row = bid;
    const int t   = threadIdx.x;
    const float* xr = x + (size_t)row * E_;

    float4 v = *(const float4*)&xr[t * 4];
    float s  = v.x + v.y + v.z + v.w;
    float ss = v.x * v.x + v.y * v.y + v.z * v.z + v.w * v.w;

    #pragma unroll
    for (int o = 16; o; o >>= 1) {
        s  += __shfl_xor_sync(0xFFFFFFFFu, s,  o);
        ss += __shfl_xor_sync(0xFFFFFFFFu, ss, o);
    }
    if ((t & 31) == 0) { red_s[t >> 5] = s; red_ss[t >> 5] = ss; }
    __syncthreads();
    if (t < 32) {
        float s2  = (t < 8) ? red_s[t]  : 0.f;
        float ss2 = (t < 8) ? red_ss[t] : 0.f;
        #pragma unroll
        for (int o = 4; o; o >>= 1) {
            s2  += __shfl_xor_sync(0xFFFFFFFFu, s2,  o);
            ss2 += __shfl_xor_sync(0xFFFFFFFFu, ss2, o);
        }
        if (t == 0) { red_s[0] = s2; red_ss[0] = ss2; }
    }
    __syncthreads();

    const float inv_e = 1.f / (float)E_;
    float mu  = red_s[0] * inv_e;
    float var = red_ss[0] * inv_e - mu * mu;
    float r   = rsqrtf(var + 1e-6f);

    float4 sc = *(const float4*)&scale[t * 4];
    float ov[4];
    ov[0] = (v.x - mu) * r * sc.x;
    ov[1] = (v.y - mu) * r * sc.y;
    ov[2] = (v.z - mu) * r * sc.z;
    ov[3] = (v.w - mu) * r * sc.w;

    const size_t base = (size_t)row * E_ + t * 4;
    #pragma unroll
    for (int p = 0; p < 2; p++) {
        uint32_t hi, lo;
        split2h(ov[p * 2], ov[p * 2 + 1], hi, lo);
        *(uint32_t*)&a0[base + p * 2] = hi;
        *(uint32_t*)&a1[base + p * 2] = lo;
    }
}

// ---------------------------------------------------------------------------
// Kernel 2: HMMA fp16 GEMM, A-side split only: C = A0*B + A1*B
// (A0/A1 = activation hi/lo fp16, B = weight single fp16, [N,K] K-major).
// 3-stage cp.async pipeline (3 tiles x 8KB per stage), ONE barrier per chunk.
// MODE 0: fp32 C store. MODE 1 (QKV): scatter to single-fp16 attention
// operands — Q/K [bh][s][d], V [bh][d][s] (transposed).
// ---------------------------------------------------------------------------
#define GBM 128
#define GBN 128
#define GBK 32
#define TILE_B   8192
#define STAGE_B  (3 * TILE_B)         // A0 | A1 | B
#define GSM_TOTAL (3 * STAGE_B)       // 72 KB, 3 stages

template <int MODE>
__global__ __launch_bounds__(256, 2)
void mma_gemm_kernel(const __half* __restrict__ A0,
                     const __half* __restrict__ A1,
                     const __half* __restrict__ B,
                     float* __restrict__ C,
                     __half* __restrict__ oQ0,
                     __half* __restrict__ oK0, __half* __restrict__ oV0,
                     int N, int K) {
    extern __shared__ char sm[];
    const uint32_t smb = smem_u32(sm);

    const int tid  = threadIdx.x;
    const int lane = tid & 31;
    const int wid  = tid >> 5;
    const int wm   = wid & 3;
    const int wn   = wid >> 2;
    const int blockRow = blockIdx.y * GBM;
    const int blockCol = blockIdx.x * GBN;

    float acc[2][8][4];
    #pragma unroll
    for (int i = 0; i < 2; i++)
        #pragma unroll
        for (int j = 0; j < 8; j++)
            #pragma unroll
            for (int q = 0; q < 4; q++) acc[i][j][q] = 0.f;

    const int r0 = (tid + 0)   >> 2, c0 = (tid + 0)   & 3;
    const int r1 = (tid + 256) >> 2, c1 = (tid + 256) & 3;
    const uint32_t so0 = soff(r0, c0), so1 = soff(r1, c1);

    const int NCH = K / GBK;               // 32

    // Prologue: stages 0 and 1 (chunks 0 and 1), separate commit groups
    #pragma unroll
    for (int st = 0; st < 2; st++) {
        const uint32_t sb = smb + st * STAGE_B;
        const int kb = st * GBK;
        cp16(sb + so0,              A0 + (size_t)(blockRow + r0) * K + kb + c0 * 8);
        cp16(sb + TILE_B + so0,     A1 + (size_t)(blockRow + r0) * K + kb + c0 * 8);
        cp16(sb + 2 * TILE_B + so0, B  + (size_t)(blockCol + r0) * K + kb + c0 * 8);
        cp16(sb + so1,              A0 + (size_t)(blockRow + r1) * K + kb + c1 * 8);
        cp16(sb + TILE_B + so1,     A1 + (size_t)(blockRow + r1) * K + kb + c1 * 8);
        cp16(sb + 2 * TILE_B + so1, B  + (size_t)(blockCol + r1) * K + kb + c1 * 8);
        CP_COMMIT();
    }

    const int rA = wm * 32 + (lane & 15);
    const int cAbase = lane >> 4;
    const int rB = wn * 64 + (lane & 7) + ((lane >> 4) << 3);
    const int cBbase = (lane >> 3) & 1;

    for (int ch = 0; ch < NCH; ch++) {
        if (ch + 1 < NCH) { CP_WAIT(1); } else { CP_WAIT(0); }
        __syncthreads();    // publish stage ch + prove compute ch-1 done

        if (ch + 2 < NCH) {
            const uint32_t sb = smb + ((ch + 2) % 3) * STAGE_B;
            const int kb = (ch + 2) * GBK;
            cp16(sb + so0,              A0 + (size_t)(blockRow + r0) * K + kb + c0 * 8);
            cp16(sb + TILE_B + so0,     A1 + (size_t)(blockRow + r0) * K + kb + c0 * 8);
            cp16(sb + 2 * TILE_B + so0, B  + (size_t)(blockCol + r0) * K + kb + c0 * 8);
            cp16(sb + so1,              A0 + (size_t)(blockRow + r1) * K + kb + c1 * 8);
            cp16(sb + TILE_B + so1,     A1 + (size_t)(blockRow + r1) * K + kb + c1 * 8);
            cp16(sb + 2 * TILE_B + so1, B  + (size_t)(blockCol + r1) * K + kb + c1 * 8);
            CP_COMMIT();
        }

        const uint32_t sb  = smb + (ch % 3) * STAGE_B;
        const uint32_t sA0 = sb;
        const uint32_t sA1 = sb + TILE_B;
        const uint32_t sB  = sb + 2 * TILE_B;

        #pragma unroll
        for (int ks = 0; ks < 2; ks++) {
            const int cA = ks * 2 + cAbase;
            const int cB = ks * 2 + cBbase;
            uint32_t a0f[2][4], a1f[2][4];
            #pragma unroll
            for (int fm = 0; fm < 2; fm++) {
                ldsm4(a0f[fm], sA0 + soff(rA + fm * 16, cA));
                ldsm4(a1f[fm], sA1 + soff(rA + fm * 16, cA));
            }
            uint32_t bf[4][4];
            #pragma unroll
            for (int p = 0; p < 4; p++)
                ldsm4(bf[p], sB + soff(rB + p * 16, cB));
            #pragma unroll
            for (int fm = 0; fm < 2; fm++)
                #pragma unroll
                for (int fn = 0; fn < 8; fn++) {
                    mma_f16(acc[fm][fn], a0f[fm], &bf[fn >> 1][(fn & 1) * 2]);
                    mma_f16(acc[fm][fn], a1f[fm], &bf[fn >> 1][(fn & 1) * 2]);
                }
        }
        // no trailing barrier: next iteration's barrier protects stage reuse
    }

    if (MODE == 0) {
        // fp32 C store
        #pragma unroll
        for (int fm = 0; fm < 2; fm++) {
            const int rr = blockRow + wm * 32 + fm * 16 + (lane >> 2);
            #pragma unroll
            for (int fn = 0; fn < 8; fn++) {
                const int cc = blockCol + wn * 64 + fn * 8 + (lane & 3) * 2;
                *(float2*)&C[(size_t)rr * N + cc] =
                    make_float2(acc[fm][fn][0], acc[fm][fn][1]);
                *(float2*)&C[(size_t)(rr + 8) * N + cc] =
                    make_float2(acc[fm][fn][2], acc[fm][fn][3]);
            }
        }
    } else {
        // QKV scatter: part uniform per CTA (1024 | 128*gridX boundaries)
        const int part = blockCol >> 10;   // 0=q, 1=k, 2=v
        #pragma unroll
        for (int fm = 0; fm < 2; fm++) {
            const int rbase = blockRow + wm * 32 + fm * 16 + (lane >> 2);
            #pragma unroll
            for (int fn = 0; fn < 8; fn++) {
                const int cc = blockCol + wn * 64 + fn * 8 + (lane & 3) * 2;
                const int h = (cc >> 6) & 15;
                const int d = cc & 63;
                #pragma unroll
                for (int hf = 0; hf < 2; hf++) {
                    const int rr = rbase + hf * 8;
                    const int s = rr >> 1, b = rr & 1;
                    const int bh = b * 16 + h;
                    const float x0 = acc[fm][fn][hf * 2];
                    const float x1 = acc[fm][fn][hf * 2 + 1];
                    if (part == 0) {
                        size_t off = ((size_t)bh * S_ + s) * D_ + d;
                        *(uint32_t*)&oQ0[off] = pack2h(x0, x1);
                    } else if (part == 1) {
                        size_t off = ((size_t)bh * S_ + s) * D_ + d;
                        *(uint32_t*)&oK0[off] = pack2h(x0, x1);
                    } else {
                        size_t offa = ((size_t)bh * D_ + d) * S_ + s;
                        size_t offb = ((size_t)bh * D_ + d + 1) * S_ + s;
                        oV0[offa] = __float2half_rn(x0);
                        oV0[offb] = __float2half_rn(x1);
                    }
                }
            }
        }
    }
}

// ---------------------------------------------------------------------------
// Kernel 3: fp16 tensor-core flash attention, single product per stage.
// Grid (S/128, 32 bh). 256 threads = 8 warps; warp w owns q rows [16w,16w+16).
// QK^T = Q*K (single fp16).  PV = P*V (single fp16, P packed from C-frags).
// K/V tiles (16 KB/stage) double-buffered via cp.async; single barrier/tile.
// Epilogue: ctx hi/lo fp16 for the out-projection's A-side split.
// ---------------------------------------------------------------------------
#define AQT 128
#define ASM_STAGE 16384     // K | V, each 8 KB
#define ASM_Q 32768
#define ASM_TOTAL 49152     // 48 KB

__global__ __launch_bounds__(256)
void attn_mma_kernel(const __half* __restrict__ Qh,
                     const __half* __restrict__ Kh,
                     const __half* __restrict__ Vh,
                     __half* __restrict__ c0,
                     __half* __restrict__ c1) {
    extern __shared__ char sm[];
    const uint32_t smb = smem_u32(sm);
    const int tid  = threadIdx.x;
    const int lane = tid & 31;
    const int wq   = tid >> 5;               // 0..7
    const int bh   = blockIdx.y;             // b*16 + h
    const int qb   = blockIdx.x * AQT;
    const size_t kbase = (size_t)bh * S_ * D_;   // Q/K [bh][s][d]
    const size_t vbase = (size_t)bh * D_ * S_;   // V  [bh][d][s]

    // Stage Q tile [128][64] fp16 (group 0)
    #pragma unroll
    for (int i = 0; i < 4; i++) {
        int idx = tid + i * 256;             // 0..1023
        int r = idx >> 3, c = idx & 7;
        cp16(smb + ASM_Q + s128(r, c),
             Qh + kbase + (size_t)(qb + r) * D_ + c * 8);
    }
    CP_COMMIT();
    // Key tile 0 (group 1): K [64][64], V [64][64]
    #pragma unroll
    for (int i = 0; i < 2; i++) {
        int idx = tid + i * 256;             // 0..511
        int r = idx >> 3, c = idx & 7;
        uint32_t so = s128(r, c);
        cp16(smb + so,        Kh + kbase + (size_t)r * D_ + c * 8);
        cp16(smb + 8192 + so, Vh + vbase + (size_t)r * S_ + c * 8);
    }
    CP_COMMIT();
    CP_WAIT(1);        // Q resident (tile 0 may still be in flight)
    __syncthreads();

    // Q fragments (held for the whole kernel)
    uint32_t qf[4][4];
    {
        const int rA = wq * 16 + (lane & 15);
        const int cA = lane >> 4;
        #pragma unroll
        for (int t = 0; t < 4; t++)
            ldsm4(qf[t], smb + ASM_Q + s128(rA, t * 2 + cA));
    }

    float acc[8][4];
    #pragma unroll
    for (int j = 0; j < 8; j++)
        #pragma unroll
        for (int q = 0; q < 4; q++) acc[j][q] = 0.f;
    float mrow[2] = {-1e30f, -1e30f};
    float lrow[2] = {0.f, 0.f};

    const int rB = (lane & 7) + ((lane >> 4) << 3);
    const int cB = (lane >> 3) & 1;
    const int NKT = S_ / 64;                 // 32 key tiles

    for (int kc = 0; kc < NKT; kc++) {
        CP_WAIT(0);         // stage kc ready (own groups)
        __syncthreads();    // publish stage kc + prove compute kc-1 done

        if (kc + 1 < NKT) {
            const uint32_t sb = smb + ((kc + 1) & 1) * ASM_STAGE;
            #pragma unroll
            for (int i = 0; i < 2; i++) {
                int idx = tid + i * 256;
                int r = idx >> 3, c = idx & 7;
                uint32_t so = s128(r, c);
                cp16(sb + so,
                     Kh + kbase + (size_t)((kc + 1) * 64 + r) * D_ + c * 8);
                cp16(sb + 8192 + so,
                     Vh + vbase + (size_t)r * S_ + (kc + 1) * 64 + c * 8);
            }
            CP_COMMIT();
        }
        const uint32_t sb = smb + (kc & 1) * ASM_STAGE;

        // ---- Scores: s[16q x 64k] over d=64, single product ----
        float sc[8][4];
        #pragma unroll
        for (int j = 0; j < 8; j++)
            #pragma unroll
            for (int q = 0; q < 4; q++) sc[j][q] = 0.f;

        #pragma unroll
        for (int t = 0; t < 4; t++) {
            #pragma unroll
            for (int jj = 0; jj < 4; jj++) {
                uint32_t k0f[4];
                ldsm4(k0f, sb + s128(jj * 16 + rB, t * 2 + cB));
                mma_f16(sc[2 * jj],     qf[t], &k0f[0]);
                mma_f16(sc[2 * jj + 1], qf[t], &k0f[2]);
            }
        }

        // ---- Online softmax on fragments (rows r=lane>>2 and r+8) ----
        #pragma unroll
        for (int h2 = 0; h2 < 2; h2++) {
            float rm = sc[0][2 * h2];
            #pragma unroll
            for (int j = 0; j < 8; j++) {
                rm = fmaxf(rm, sc[j][2 * h2]);
                rm = fmaxf(rm, sc[j][2 * h2 + 1]);
            }
            rm = fmaxf(rm, __shfl_xor_sync(0xFFFFFFFFu, rm, 1));
            rm = fmaxf(rm, __shfl_xor_sync(0xFFFFFFFFu, rm, 2));
            float mnew = fmaxf(mrow[h2], rm);
            float al   = __expf(mrow[h2] - mnew);
            mrow[h2] = mnew;
            float rs = 0.f;
            #pragma unroll
            for (int j = 0; j < 8; j++) {
                float p0 = __expf(sc[j][2 * h2]     - mnew);
                float p1 = __expf(sc[j][2 * h2 + 1] - mnew);
                sc[j][2 * h2]     = p0;
                sc[j][2 * h2 + 1] = p1;
                rs += p0 + p1;
            }
            rs += __shfl_xor_sync(0xFFFFFFFFu, rs, 1);
            rs += __shfl_xor_sync(0xFFFFFFFFu, rs, 2);
            lrow[h2] = lrow[h2] * al + rs;
            #pragma unroll
            for (int j = 0; j < 8; j++) {
                acc[j][2 * h2]     *= al;
                acc[j][2 * h2 + 1] *= al;
            }
        }

        // ---- PV: ctx += P * V, single product; P packed from C-frags ----
        #pragma unroll
        for (int t2 = 0; t2 < 4; t2++) {
            uint32_t ah[4];
            ah[0] = pack2h(sc[2 * t2][0],     sc[2 * t2][1]);
            ah[1] = pack2h(sc[2 * t2][2],     sc[2 * t2][3]);
            ah[2] = pack2h(sc[2 * t2 + 1][0], sc[2 * t2 + 1][1]);
            ah[3] = pack2h(sc[2 * t2 + 1][2], sc[2 * t2 + 1][3]);
            #pragma unroll
            for (int jj = 0; jj < 4; jj++) {
                uint32_t v0f[4];
                ldsm4(v0f, sb + 8192 + s128(jj * 16 + rB, t2 * 2 + cB));
                mma_f16(acc[2 * jj],     ah, &v0f[0]);
                mma_f16(acc[2 * jj + 1], ah, &v0f[2]);
            }
        }
        // no trailing barrier: next iteration's barrier protects stage reuse
    }

    // ---- Epilogue: normalize, fp16 hi/lo split into c0/c1 [NROWS][HD] ----
    const int b = bh >> 4, h = bh & 15;
    const float inv0 = 1.f / lrow[0];
    const float inv1 = 1.f / lrow[1];
    const int r  = lane >> 2;
    const int c2 = (lane & 3) * 2;
    #pragma unroll
    for (int j = 0; j < 8; j++) {
        const int d = j * 8 + c2;
        const int qg = qb + wq * 16 + r;
        size_t off0 = (size_t)(qg * 2 + b) * HD_ + h * 64 + d;
        size_t off1 = (size_t)((qg + 8) * 2 + b) * HD_ + h * 64 + d;
        uint32_t hi, lo;
        split2h(acc[j][0] * inv0, acc[j][1] * inv0, hi, lo);
        *(uint32_t*)&c0[off0] = hi;
        *(uint32_t*)&c1[off0] = lo;
        split2h(acc[j][2] * inv1, acc[j][3] * inv1, hi, lo);
        *(uint32_t*)&c0[off1] = hi;
        *(uint32_t*)&c1[off1] = lo;
    }
}

// ---------------------------------------------------------------------------
// kernel_launch
// ---------------------------------------------------------------------------
extern "C" void kernel_launch(void* const* d_in, const int* in_sizes, int n_in,
                              void* d_out, int out_size) {
    const float* x        = (const float*)d_in[0];   // [S,B,E]
    const float* ln_scale = (const float*)d_in[1];   // [E]
    const float* w_qkv    = (const float*)d_in[2];   // [E, 3*H*D]
    const float* w_out    = (const float*)d_in[3];   // [H*D, E]
    float* out = (float*)d_out;                      // [S,B,E]

    __half *p_a0, *p_a1, *p_wq, *p_wo;
    __half *pQ0, *pK0, *pV0, *p_c0, *p_c1;
    cudaGetSymbolAddress((void**)&p_a0, g_a0);
    cudaGetSymbolAddress((void**)&p_a1, g_a1);
    cudaGetSymbolAddress((void**)&p_wq, g_wq);
    cudaGetSymbolAddress((void**)&p_wo, g_wo);
    cudaGetSymbolAddress((void**)&pQ0,  g_q0);
    cudaGetSymbolAddress((void**)&pK0,  g_k0);
    cudaGetSymbolAddress((void**)&pV0,  g_v0);
    cudaGetSymbolAddress((void**)&p_c0, g_c0);
    cudaGetSymbolAddress((void**)&p_c1, g_c1);

    cudaFuncSetAttribute(mma_gemm_kernel<0>,
                         cudaFuncAttributeMaxDynamicSharedMemorySize, GSM_TOTAL);
    cudaFuncSetAttribute(mma_gemm_kernel<1>,
                         cudaFuncAttributeMaxDynamicSharedMemorySize, GSM_TOTAL);
    cudaFuncSetAttribute(attn_mma_kernel,
                         cudaFuncAttributeMaxDynamicSharedMemorySize, ASM_TOTAL);

    // 1. Fused preprocessing: LayerNorm+split and both weight transposes
    pre_kernel<<<NROWS + 3072 + 1024, 256>>>(
        x, ln_scale, p_a0, p_a1, w_qkv, p_wq, w_out, p_wo);

    // 2. QKV projection -> single-fp16 attention operands (V transposed)
    mma_gemm_kernel<1><<<dim3(Q3_ / GBN, NROWS / GBM), 256, GSM_TOTAL>>>(
        p_a0, p_a1, p_wq, nullptr,
        pQ0, pK0, pV0, Q3_, E_);

    // 3. fp16 tensor-core flash attention (single product per stage)
    attn_mma_kernel<<<dim3(S_ / AQT, BH_), 256, ASM_TOTAL>>>(
        pQ0, pK0, pV0, p_c0, p_c1);

    // 4. Output projection (fp32 out, A-side split)
    mma_gemm_kernel<0><<<dim3(E_ / GBN, NROWS / GBM), 256, GSM_TOTAL>>>(
        p_c0, p_c1, p_wo, out,
        nullptr, nullptr, nullptr, E_, HD_);
}

// round 14
// speedup vs baseline: 12.2402x; 1.3328x over previous
#include <cuda_runtime.h>
#include <cuda_fp16.h>
#include <cstdint>

// Problem constants
#define S_    2048
#define B_    2
#define E_    1024
#define H_    16
#define D_    64
#define HD_   1024
#define Q3_   3072
#define NROWS (S_ * B_)   // 4096 rows, row index = s*B + b
#define BH_   32          // b*16 + h

// ---------------------------------------------------------------------------
// Scratch (device globals: cudaMalloc is forbidden by the harness)
// ---------------------------------------------------------------------------
__device__ __align__(16) __half g_a0[(size_t)NROWS * E_];   // LN out (fp16)
__device__ __align__(16) __half g_wq[(size_t)Q3_ * E_];     // w_qkv^T fp16 [3072,1024]
__device__ __align__(16) __half g_wo[(size_t)E_ * HD_];     // w_out^T fp16 [1024,1024]
// Attention operands (single fp16), written by the QKV GEMM epilogue:
__device__ __align__(16) __half g_q0[(size_t)BH_ * S_ * D_];   // Q [bh][s][d]
__device__ __align__(16) __half g_k0[(size_t)BH_ * S_ * D_];   // K [bh][s][d]
__device__ __align__(16) __half g_v0[(size_t)BH_ * D_ * S_];   // V [bh][d][s]
__device__ __align__(16) __half g_c0[(size_t)NROWS * HD_];  // ctx (fp16)

// ---------------------------------------------------------------------------
// PTX helpers: arch-agnostic tensor path (mma.sync / ldmatrix / cp.async).
// tcgen05 is NOT usable: the harness PTX stage targets compute_103 (no 'a').
// ---------------------------------------------------------------------------
__device__ __forceinline__ uint32_t smem_u32(const void* p) {
    return (uint32_t)__cvta_generic_to_shared(p);
}

__device__ __forceinline__ void cp16(uint32_t saddr, const void* g) {
    asm volatile("cp.async.cg.shared.global [%0], [%1], 16;"
                 :: "r"(saddr), "l"(g));
}
#define CP_COMMIT() asm volatile("cp.async.commit_group;" ::: "memory")
#define CP_WAIT(n)  asm volatile("cp.async.wait_group %0;" :: "n"(n) : "memory")

__device__ __forceinline__ void ldsm4(uint32_t* r, uint32_t addr) {
    asm volatile("ldmatrix.sync.aligned.m8n8.x4.shared.b16 {%0,%1,%2,%3}, [%4];"
                 : "=r"(r[0]), "=r"(r[1]), "=r"(r[2]), "=r"(r[3]) : "r"(addr));
}

__device__ __forceinline__ void mma_f16(float* c, const uint32_t* a,
                                        const uint32_t* b) {
    asm volatile(
        "mma.sync.aligned.m16n8k16.row.col.f32.f16.f16.f32 "
        "{%0,%1,%2,%3}, {%4,%5,%6,%7}, {%8,%9}, {%0,%1,%2,%3};"
        : "+f"(c[0]), "+f"(c[1]), "+f"(c[2]), "+f"(c[3])
        : "r"(a[0]), "r"(a[1]), "r"(a[2]), "r"(a[3]), "r"(b[0]), "r"(b[1]));
}

// GEMM tiles: [128 x 32] fp16, 64-byte rows (4 x 16B chunks), chunk' = c^((r>>1)&3)
__device__ __forceinline__ uint32_t soff(int r, int c) {
    return (uint32_t)(r * 64 + ((c ^ ((r >> 1) & 3)) << 4));
}
// Attention tiles: [rows x 64] halfword, 128-byte rows (8 x 16B), chunk' = c^(r&7)
__device__ __forceinline__ uint32_t s128(int r, int c) {
    return (uint32_t)(r * 128 + ((c ^ (r & 7)) << 4));
}

// plain fp16 pack of a float pair
__device__ __forceinline__ uint32_t pack2h(float x0, float x1) {
    __half2 h;
    h.x = __float2half_rn(x0);
    h.y = __float2half_rn(x1);
    return *(uint32_t*)&h;
}

// ---------------------------------------------------------------------------
// Kernel 1 (fused preprocessing): one launch covering
//   blocks [0, 4096):          LayerNorm -> fp16 activations
//   blocks [4096, 7168):       w_qkv transpose -> fp16  (96 x 32 tiles)
//   blocks [7168, 8192):       w_out transpose -> fp16  (32 x 32 tiles)
// ---------------------------------------------------------------------------
__device__ __forceinline__ void wtrans_body(float* sh,
                                            const float* __restrict__ W,
                                            __half* __restrict__ o,
                                            int K, int N, int gx, int gy) {
    float (*tile)[33] = (float(*)[33])sh;
    const int bx = gx * 32;        // n base
    const int by = gy * 32;        // k base
    const int tx = threadIdx.x & 31;
    const int ty = threadIdx.x >> 5;

    #pragma unroll
    for (int i = 0; i < 32; i += 8)
        tile[ty + i][tx] = W[(size_t)(by + ty + i) * N + bx + tx];
    __syncthreads();
    #pragma unroll
    for (int i = 0; i < 32; i += 8) {
        float v = tile[tx][ty + i];
        o[(size_t)(bx + ty + i) * K + by + tx] = __float2half_rn(v);
    }
}

__global__ __launch_bounds__(256)
void pre_kernel(const float* __restrict__ x,
                const float* __restrict__ scale,
                __half* __restrict__ a0,
                const float* __restrict__ wqkv,
                __half* __restrict__ wq,
                const float* __restrict__ wout,
                __half* __restrict__ wo) {
    __shared__ float sh[32 * 33];
    const int bid = blockIdx.x;

    if (bid >= NROWS) {
        if (bid < NROWS + 3072) {
            int idx = bid - NROWS;
            wtrans_body(sh, wqkv, wq, E_, Q3_, idx % 96, idx / 96);
        } else {
            int idx = bid - NROWS - 3072;
            wtrans_body(sh, wout, wo, HD_, E_, idx % 32, idx / 32);
        }
        return;
    }

    // ---- LayerNorm -> fp16 ----
    float* red_s  = sh;
    float* red_ss = sh + 8;
    const int row = bid;
    const int t   = threadIdx.x;
    const float* xr = x + (size_t)row * E_;

    float4 v = *(const float4*)&xr[t * 4];
    float s  = v.x + v.y + v.z + v.w;
    float ss = v.x * v.x + v.y * v.y + v.z * v.z + v.w * v.w;

    #pragma unroll
    for (int o = 16; o; o >>= 1) {
        s  += __shfl_xor_sync(0xFFFFFFFFu, s,  o);
        ss += __shfl_xor_sync(0xFFFFFFFFu, ss, o);
    }
    if ((t & 31) == 0) { red_s[t >> 5] = s; red_ss[t >> 5] = ss; }
    __syncthreads();
    if (t < 32) {
        float s2  = (t < 8) ? red_s[t]  : 0.f;
        float ss2 = (t < 8) ? red_ss[t] : 0.f;
        #pragma unroll
        for (int o = 4; o; o >>= 1) {
            s2  += __shfl_xor_sync(0xFFFFFFFFu, s2,  o);
            ss2 += __shfl_xor_sync(0xFFFFFFFFu, ss2, o);
        }
        if (t == 0) { red_s[0] = s2; red_ss[0] = ss2; }
    }
    __syncthreads();

    const float inv_e = 1.f / (float)E_;
    float mu  = red_s[0] * inv_e;
    float var = red_ss[0] * inv_e - mu * mu;
    float r   = rsqrtf(var + 1e-6f);

    float4 sc = *(const float4*)&scale[t * 4];
    const size_t base = (size_t)row * E_ + t * 4;
    *(uint32_t*)&a0[base]     = pack2h((v.x - mu) * r * sc.x,
                                       (v.y - mu) * r * sc.y);
    *(uint32_t*)&a0[base + 2] = pack2h((v.z - mu) * r * sc.z,
                                       (v.w - mu) * r * sc.w);
}

// ---------------------------------------------------------------------------
// Kernel 2: plain fp16 HMMA GEMM: C = A*B  (A [M,K] fp16, B [N,K] K-major).
// 3-stage cp.async pipeline (2 tiles x 8KB per stage), ONE barrier per chunk.
// MODE 0: fp32 C store. MODE 1 (QKV): scatter to single-fp16 attention
// operands — Q/K [bh][s][d], V [bh][d][s] (transposed).
// ---------------------------------------------------------------------------
#define GBM 128
#define GBN 128
#define GBK 32
#define TILE_B   8192
#define STAGE_B  (2 * TILE_B)         // A | B
#define GSM_TOTAL (3 * STAGE_B)       // 48 KB, 3 stages

template <int MODE>
__global__ __launch_bounds__(256, 2)
void mma_gemm_kernel(const __half* __restrict__ A,
                     const __half* __restrict__ B,
                     float* __restrict__ C,
                     __half* __restrict__ oQ0,
                     __half* __restrict__ oK0, __half* __restrict__ oV0,
                     int N, int K) {
    extern __shared__ char sm[];
    const uint32_t smb = smem_u32(sm);

    const int tid  = threadIdx.x;
    const int lane = tid & 31;
    const int wid  = tid >> 5;
    const int wm   = wid & 3;
    const int wn   = wid >> 2;
    const int blockRow = blockIdx.y * GBM;
    const int blockCol = blockIdx.x * GBN;

    float acc[2][8][4];
    #pragma unroll
    for (int i = 0; i < 2; i++)
        #pragma unroll
        for (int j = 0; j < 8; j++)
            #pragma unroll
            for (int q = 0; q < 4; q++) acc[i][j][q] = 0.f;

    const int r0 = (tid + 0)   >> 2, c0 = (tid + 0)   & 3;
    const int r1 = (tid + 256) >> 2, c1 = (tid + 256) & 3;
    const uint32_t so0 = soff(r0, c0), so1 = soff(r1, c1);

    const int NCH = K / GBK;               // 32

    // Prologue: stages 0 and 1 (chunks 0 and 1), separate commit groups
    #pragma unroll
    for (int st = 0; st < 2; st++) {
        const uint32_t sb = smb + st * STAGE_B;
        const int kb = st * GBK;
        cp16(sb + so0,          A + (size_t)(blockRow + r0) * K + kb + c0 * 8);
        cp16(sb + TILE_B + so0, B + (size_t)(blockCol + r0) * K + kb + c0 * 8);
        cp16(sb + so1,          A + (size_t)(blockRow + r1) * K + kb + c1 * 8);
        cp16(sb + TILE_B + so1, B + (size_t)(blockCol + r1) * K + kb + c1 * 8);
        CP_COMMIT();
    }

    const int rA = wm * 32 + (lane & 15);
    const int cAbase = lane >> 4;
    const int rB = wn * 64 + (lane & 7) + ((lane >> 4) << 3);
    const int cBbase = (lane >> 3) & 1;

    for (int ch = 0; ch < NCH; ch++) {
        if (ch + 1 < NCH) { CP_WAIT(1); } else { CP_WAIT(0); }
        __syncthreads();    // publish stage ch + prove compute ch-1 done

        if (ch + 2 < NCH) {
            const uint32_t sb = smb + ((ch + 2) % 3) * STAGE_B;
            const int kb = (ch + 2) * GBK;
            cp16(sb + so0,          A + (size_t)(blockRow + r0) * K + kb + c0 * 8);
            cp16(sb + TILE_B + so0, B + (size_t)(blockCol + r0) * K + kb + c0 * 8);
            cp16(sb + so1,          A + (size_t)(blockRow + r1) * K + kb + c1 * 8);
            cp16(sb + TILE_B + so1, B + (size_t)(blockCol + r1) * K + kb + c1 * 8);
            CP_COMMIT();
        }

        const uint32_t sA = smb + (ch % 3) * STAGE_B;
        const uint32_t sB = sA + TILE_B;

        #pragma unroll
        for (int ks = 0; ks < 2; ks++) {
            const int cA = ks * 2 + cAbase;
            const int cB = ks * 2 + cBbase;
            uint32_t af[2][4];
            #pragma unroll
            for (int fm = 0; fm < 2; fm++)
                ldsm4(af[fm], sA + soff(rA + fm * 16, cA));
            uint32_t bf[4][4];
            #pragma unroll
            for (int p = 0; p < 4; p++)
                ldsm4(bf[p], sB + soff(rB + p * 16, cB));
            #pragma unroll
            for (int fm = 0; fm < 2; fm++)
                #pragma unroll
                for (int fn = 0; fn < 8; fn++)
                    mma_f16(acc[fm][fn], af[fm], &bf[fn >> 1][(fn & 1) * 2]);
        }
        // no trailing barrier: next iteration's barrier protects stage reuse
    }

    if (MODE == 0) {
        // fp32 C store
        #pragma unroll
        for (int fm = 0; fm < 2; fm++) {
            const int rr = blockRow + wm * 32 + fm * 16 + (lane >> 2);
            #pragma unroll
            for (int fn = 0; fn < 8; fn++) {
                const int cc = blockCol + wn * 64 + fn * 8 + (lane & 3) * 2;
                *(float2*)&C[(size_t)rr * N + cc] =
                    make_float2(acc[fm][fn][0], acc[fm][fn][1]);
                *(float2*)&C[(size_t)(rr + 8) * N + cc] =
                    make_float2(acc[fm][fn][2], acc[fm][fn][3]);
            }
        }
    } else {
        // QKV scatter: part uniform per CTA (1024 | 128*gridX boundaries)
        const int part = blockCol >> 10;   // 0=q, 1=k, 2=v
        #pragma unroll
        for (int fm = 0; fm < 2; fm++) {
            const int rbase = blockRow + wm * 32 + fm * 16 + (lane >> 2);
            #pragma unroll
            for (int fn = 0; fn < 8; fn++) {
                const int cc = blockCol + wn * 64 + fn * 8 + (lane & 3) * 2;
                const int h = (cc >> 6) & 15;
                const int d = cc & 63;
                #pragma unroll
                for (int hf = 0; hf < 2; hf++) {
                    const int rr = rbase + hf * 8;
                    const int s = rr >> 1, b = rr & 1;
                    const int bh = b * 16 + h;
                    const float x0 = acc[fm][fn][hf * 2];
                    const float x1 = acc[fm][fn][hf * 2 + 1];
                    if (part == 0) {
                        size_t off = ((size_t)bh * S_ + s) * D_ + d;
                        *(uint32_t*)&oQ0[off] = pack2h(x0, x1);
                    } else if (part == 1) {
                        size_t off = ((size_t)bh * S_ + s) * D_ + d;
                        *(uint32_t*)&oK0[off] = pack2h(x0, x1);
                    } else {
                        size_t offa = ((size_t)bh * D_ + d) * S_ + s;
                        size_t offb = ((size_t)bh * D_ + d + 1) * S_ + s;
                        oV0[offa] = __float2half_rn(x0);
                        oV0[offb] = __float2half_rn(x1);
                    }
                }
            }
        }
    }
}

// ---------------------------------------------------------------------------
// Kernel 3: fp16 tensor-core flash attention, single product per stage.
// Grid (S/128, 32 bh). 256 threads = 8 warps; warp w owns q rows [16w,16w+16).
// QK^T = Q*K.  PV = P*V (P packed from C-frags).
// K/V tiles (16 KB/stage) double-buffered via cp.async; single barrier/tile.
// Epilogue: single-fp16 ctx for the plain-fp16 out-projection.
// ---------------------------------------------------------------------------
#define AQT 128
#define ASM_STAGE 16384     // K | V, each 8 KB
#define ASM_Q 32768
#define ASM_TOTAL 49152     // 48 KB

__global__ __launch_bounds__(256)
void attn_mma_kernel(const __half* __restrict__ Qh,
                     const __half* __restrict__ Kh,
                     const __half* __restrict__ Vh,
                     __half* __restrict__ c0) {
    extern __shared__ char sm[];
    const uint32_t smb = smem_u32(sm);
    const int tid  = threadIdx.x;
    const int lane = tid & 31;
    const int wq   = tid >> 5;               // 0..7
    const int bh   = blockIdx.y;             // b*16 + h
    const int qb   = blockIdx.x * AQT;
    const size_t kbase = (size_t)bh * S_ * D_;   // Q/K [bh][s][d]
    const size_t vbase = (size_t)bh * D_ * S_;   // V  [bh][d][s]

    // Stage Q tile [128][64] fp16 (group 0)
    #pragma unroll
    for (int i = 0; i < 4; i++) {
        int idx = tid + i * 256;             // 0..1023
        int r = idx >> 3, c = idx & 7;
        cp16(smb + ASM_Q + s128(r, c),
             Qh + kbase + (size_t)(qb + r) * D_ + c * 8);
    }
    CP_COMMIT();
    // Key tile 0 (group 1): K [64][64], V [64][64]
    #pragma unroll
    for (int i = 0; i < 2; i++) {
        int idx = tid + i * 256;             // 0..511
        int r = idx >> 3, c = idx & 7;
        uint32_t so = s128(r, c);
        cp16(smb + so,        Kh + kbase + (size_t)r * D_ + c * 8);
        cp16(smb + 8192 + so, Vh + vbase + (size_t)r * S_ + c * 8);
    }
    CP_COMMIT();
    CP_WAIT(1);        // Q resident (tile 0 may still be in flight)
    __syncthreads();

    // Q fragments (held for the whole kernel)
    uint32_t qf[4][4];
    {
        const int rA = wq * 16 + (lane & 15);
        const int cA = lane >> 4;
        #pragma unroll
        for (int t = 0; t < 4; t++)
            ldsm4(qf[t], smb + ASM_Q + s128(rA, t * 2 + cA));
    }

    float acc[8][4];
    #pragma unroll
    for (int j = 0; j < 8; j++)
        #pragma unroll
        for (int q = 0; q < 4; q++) acc[j][q] = 0.f;
    float mrow[2] = {-1e30f, -1e30f};
    float lrow[2] = {0.f, 0.f};

    const int rB = (lane & 7) + ((lane >> 4) << 3);
    const int cB = (lane >> 3) & 1;
    const int NKT = S_ / 64;                 // 32 key tiles

    for (int kc = 0; kc < NKT; kc++) {
        CP_WAIT(0);         // stage kc ready (own groups)
        __syncthreads();    // publish stage kc + prove compute kc-1 done

        if (kc + 1 < NKT) {
            const uint32_t sb = smb + ((kc + 1) & 1) * ASM_STAGE;
            #pragma unroll
            for (int i = 0; i < 2; i++) {
                int idx = tid + i * 256;
                int r = idx >> 3, c = idx & 7;
                uint32_t so = s128(r, c);
                cp16(sb + so,
                     Kh + kbase + (size_t)((kc + 1) * 64 + r) * D_ + c * 8);
                cp16(sb + 8192 + so,
                     Vh + vbase + (size_t)r * S_ + (kc + 1) * 64 + c * 8);
            }
            CP_COMMIT();
        }
        const uint32_t sb = smb + (kc & 1) * ASM_STAGE;

        // ---- Scores: s[16q x 64k] over d=64, single product ----
        float sc[8][4];
        #pragma unroll
        for (int j = 0; j < 8; j++)
            #pragma unroll
            for (int q = 0; q < 4; q++) sc[j][q] = 0.f;

        #pragma unroll
        for (int t = 0; t < 4; t++) {
            #pragma unroll
            for (int jj = 0; jj < 4; jj++) {
                uint32_t k0f[4];
                ldsm4(k0f, sb + s128(jj * 16 + rB, t * 2 + cB));
                mma_f16(sc[2 * jj],     qf[t], &k0f[0]);
                mma_f16(sc[2 * jj + 1], qf[t], &k0f[2]);
            }
        }

        // ---- Online softmax on fragments (rows r=lane>>2 and r+8) ----
        #pragma unroll
        for (int h2 = 0; h2 < 2; h2++) {
            float rm = sc[0][2 * h2];
            #pragma unroll
            for (int j = 0; j < 8; j++) {
                rm = fmaxf(rm, sc[j][2 * h2]);
                rm = fmaxf(rm, sc[j][2 * h2 + 1]);
            }
            rm = fmaxf(rm, __shfl_xor_sync(0xFFFFFFFFu, rm, 1));
            rm = fmaxf(rm, __shfl_xor_sync(0xFFFFFFFFu, rm, 2));
            float mnew = fmaxf(mrow[h2], rm);
            float al   = __expf(mrow[h2] - mnew);
            mrow[h2] = mnew;
            float rs = 0.f;
            #pragma unroll
            for (int j = 0; j < 8; j++) {
                float p0 = __expf(sc[j][2 * h2]     - mnew);
                float p1 = __expf(sc[j][2 * h2 + 1] - mnew);
                sc[j][2 * h2]     = p0;
                sc[j][2 * h2 + 1] = p1;
                rs += p0 + p1;
            }
            rs += __shfl_xor_sync(0xFFFFFFFFu, rs, 1);
            rs += __shfl_xor_sync(0xFFFFFFFFu, rs, 2);
            lrow[h2] = lrow[h2] * al + rs;
            #pragma unroll
            for (int j = 0; j < 8; j++) {
                acc[j][2 * h2]     *= al;
                acc[j][2 * h2 + 1] *= al;
            }
        }

        // ---- PV: ctx += P * V, single product; P packed from C-frags ----
        #pragma unroll
        for (int t2 = 0; t2 < 4; t2++) {
            uint32_t ah[4];
            ah[0] = pack2h(sc[2 * t2][0],     sc[2 * t2][1]);
            ah[1] = pack2h(sc[2 * t2][2],     sc[2 * t2][3]);
            ah[2] = pack2h(sc[2 * t2 + 1][0], sc[2 * t2 + 1][1]);
            ah[3] = pack2h(sc[2 * t2 + 1][2], sc[2 * t2 + 1][3]);
            #pragma unroll
            for (int jj = 0; jj < 4; jj++) {
                uint32_t v0f[4];
                ldsm4(v0f, sb + 8192 + s128(jj * 16 + rB, t2 * 2 + cB));
                mma_f16(acc[2 * jj],     ah, &v0f[0]);
                mma_f16(acc[2 * jj + 1], ah, &v0f[2]);
            }
        }
        // no trailing barrier: next iteration's barrier protects stage reuse
    }

    // ---- Epilogue: normalize, single fp16 into c0 [NROWS][HD] ----
    const int b = bh >> 4, h = bh & 15;
    const float inv0 = 1.f / lrow[0];
    const float inv1 = 1.f / lrow[1];
    const int r  = lane >> 2;
    const int c2 = (lane & 3) * 2;
    #pragma unroll
    for (int j = 0; j < 8; j++) {
        const int d = j * 8 + c2;
        const int qg = qb + wq * 16 + r;
        size_t off0 = (size_t)(qg * 2 + b) * HD_ + h * 64 + d;
        size_t off1 = (size_t)((qg + 8) * 2 + b) * HD_ + h * 64 + d;
        *(uint32_t*)&c0[off0] = pack2h(acc[j][0] * inv0, acc[j][1] * inv0);
        *(uint32_t*)&c0[off1] = pack2h(acc[j][2] * inv1, acc[j][3] * inv1);
    }
}

// ---------------------------------------------------------------------------
// kernel_launch
// ---------------------------------------------------------------------------
extern "C" void kernel_launch(void* const* d_in, const int* in_sizes, int n_in,
                              void* d_out, int out_size) {
    const float* x        = (const float*)d_in[0];   // [S,B,E]
    const float* ln_scale = (const float*)d_in[1];   // [E]
    const float* w_qkv    = (const float*)d_in[2];   // [E, 3*H*D]
    const float* w_out    = (const float*)d_in[3];   // [H*D, E]
    float* out = (float*)d_out;                      // [S,B,E]

    __half *p_a0, *p_wq, *p_wo;
    __half *pQ0, *pK0, *pV0, *p_c0;
    cudaGetSymbolAddress((void**)&p_a0, g_a0);
    cudaGetSymbolAddress((void**)&p_wq, g_wq);
    cudaGetSymbolAddress((void**)&p_wo, g_wo);
    cudaGetSymbolAddress((void**)&pQ0,  g_q0);
    cudaGetSymbolAddress((void**)&pK0,  g_k0);
    cudaGetSymbolAddress((void**)&pV0,  g_v0);
    cudaGetSymbolAddress((void**)&p_c0, g_c0);

    cudaFuncSetAttribute(mma_gemm_kernel<0>,
                         cudaFuncAttributeMaxDynamicSharedMemorySize, GSM_TOTAL);
    cudaFuncSetAttribute(mma_gemm_kernel<1>,
                         cudaFuncAttributeMaxDynamicSharedMemorySize, GSM_TOTAL);
    cudaFuncSetAttribute(attn_mma_kernel,
                         cudaFuncAttributeMaxDynamicSharedMemorySize, ASM_TOTAL);

    // 1. Fused preprocessing: LayerNorm->fp16 and both weight transposes
    pre_kernel<<<NROWS + 3072 + 1024, 256>>>(
        x, ln_scale, p_a0, w_qkv, p_wq, w_out, p_wo);

    // 2. QKV projection -> single-fp16 attention operands (V transposed)
    mma_gemm_kernel<1><<<dim3(Q3_ / GBN, NROWS / GBM), 256, GSM_TOTAL>>>(
        p_a0, p_wq, nullptr, pQ0, pK0, pV0, Q3_, E_);

    // 3. fp16 tensor-core flash attention
    attn_mma_kernel<<<dim3(S_ / AQT, BH_), 256, ASM_TOTAL>>>(
        pQ0, pK0, pV0, p_c0);

    // 4. Output projection (fp32 out)
    mma_gemm_kernel<0><<<dim3(E_ / GBN, NROWS / GBM), 256, GSM_TOTAL>>>(
        p_c0, p_wo, out, nullptr, nullptr, nullptr, E_, HD_);
}

// round 15
// speedup vs baseline: 12.5247x; 1.0232x over previous
#include <cuda_runtime.h>
#include <cuda_fp16.h>
#include <cstdint>

// Problem constants
#define S_    2048
#define B_    2
#define E_    1024
#define H_    16
#define D_    64
#define HD_   1024
#define Q3_   3072
#define NROWS (S_ * B_)   // 4096 rows, row index = s*B + b
#define BH_   32          // b*16 + h

// ---------------------------------------------------------------------------
// Scratch (device globals: cudaMalloc is forbidden by the harness)
// ---------------------------------------------------------------------------
__device__ __align__(16) __half g_a0[(size_t)NROWS * E_];   // LN out (fp16)
__device__ __align__(16) __half g_wq[(size_t)Q3_ * E_];     // w_qkv^T fp16 [3072,1024]
__device__ __align__(16) __half g_wo[(size_t)E_ * HD_];     // w_out^T fp16 [1024,1024]
// Attention operands (single fp16), written by the QKV GEMM epilogue:
__device__ __align__(16) __half g_q0[(size_t)BH_ * S_ * D_];   // Q [bh][s][d]
__device__ __align__(16) __half g_k0[(size_t)BH_ * S_ * D_];   // K [bh][s][d]
__device__ __align__(16) __half g_v0[(size_t)BH_ * D_ * S_];   // V [bh][d][s]
__device__ __align__(16) __half g_c0[(size_t)NROWS * HD_];  // ctx (fp16)

// ---------------------------------------------------------------------------
// PTX helpers: arch-agnostic tensor path (mma.sync / ldmatrix / cp.async).
// tcgen05 is NOT usable: the harness PTX stage targets compute_103 (no 'a').
// ---------------------------------------------------------------------------
__device__ __forceinline__ uint32_t smem_u32(const void* p) {
    return (uint32_t)__cvta_generic_to_shared(p);
}

__device__ __forceinline__ void cp16(uint32_t saddr, const void* g) {
    asm volatile("cp.async.cg.shared.global [%0], [%1], 16;"
                 :: "r"(saddr), "l"(g));
}
#define CP_COMMIT() asm volatile("cp.async.commit_group;" ::: "memory")
#define CP_WAIT(n)  asm volatile("cp.async.wait_group %0;" :: "n"(n) : "memory")

__device__ __forceinline__ void ldsm4(uint32_t* r, uint32_t addr) {
    asm volatile("ldmatrix.sync.aligned.m8n8.x4.shared.b16 {%0,%1,%2,%3}, [%4];"
                 : "=r"(r[0]), "=r"(r[1]), "=r"(r[2]), "=r"(r[3]) : "r"(addr));
}

__device__ __forceinline__ void mma_f16(float* c, const uint32_t* a,
                                        const uint32_t* b) {
    asm volatile(
        "mma.sync.aligned.m16n8k16.row.col.f32.f16.f16.f32 "
        "{%0,%1,%2,%3}, {%4,%5,%6,%7}, {%8,%9}, {%0,%1,%2,%3};"
        : "+f"(c[0]), "+f"(c[1]), "+f"(c[2]), "+f"(c[3])
        : "r"(a[0]), "r"(a[1]), "r"(a[2]), "r"(a[3]), "r"(b[0]), "r"(b[1]));
}

// Shared tile layout: [rows x 64] fp16, 128-byte rows (8 x 16B chunks),
// chunk' = c ^ (r & 7). Conflict-free for cp.async fill and ldmatrix reads.
__device__ __forceinline__ uint32_t s128(int r, int c) {
    return (uint32_t)(r * 128 + ((c ^ (r & 7)) << 4));
}

// plain fp16 pack of a float pair
__device__ __forceinline__ uint32_t pack2h(float x0, float x1) {
    __half2 h;
    h.x = __float2half_rn(x0);
    h.y = __float2half_rn(x1);
    return *(uint32_t*)&h;
}

// ---------------------------------------------------------------------------
// Kernel 1 (fused preprocessing): one launch covering
//   blocks [0, 4096):          LayerNorm -> fp16 activations
//   blocks [4096, 7168):       w_qkv transpose -> fp16  (96 x 32 tiles)
//   blocks [7168, 8192):       w_out transpose -> fp16  (32 x 32 tiles)
// ---------------------------------------------------------------------------
__device__ __forceinline__ void wtrans_body(float* sh,
                                            const float* __restrict__ W,
                                            __half* __restrict__ o,
                                            int K, int N, int gx, int gy) {
    float (*tile)[33] = (float(*)[33])sh;
    const int bx = gx * 32;        // n base
    const int by = gy * 32;        // k base
    const int tx = threadIdx.x & 31;
    const int ty = threadIdx.x >> 5;

    #pragma unroll
    for (int i = 0; i < 32; i += 8)
        tile[ty + i][tx] = W[(size_t)(by + ty + i) * N + bx + tx];
    __syncthreads();
    #pragma unroll
    for (int i = 0; i < 32; i += 8) {
        float v = tile[tx][ty + i];
        o[(size_t)(bx + ty + i) * K + by + tx] = __float2half_rn(v);
    }
}

__global__ __launch_bounds__(256)
void pre_kernel(const float* __restrict__ x,
                const float* __restrict__ scale,
                __half* __restrict__ a0,
                const float* __restrict__ wqkv,
                __half* __restrict__ wq,
                const float* __restrict__ wout,
                __half* __restrict__ wo) {
    __shared__ float sh[32 * 33];
    const int bid = blockIdx.x;

    if (bid >= NROWS) {
        if (bid < NROWS + 3072) {
            int idx = bid - NROWS;
            wtrans_body(sh, wqkv, wq, E_, Q3_, idx % 96, idx / 96);
        } else {
            int idx = bid - NROWS - 3072;
            wtrans_body(sh, wout, wo, HD_, E_, idx % 32, idx / 32);
        }
        return;
    }

    // ---- LayerNorm -> fp16 ----
    float* red_s  = sh;
    float* red_ss = sh + 8;
    const int row = bid;
    const int t   = threadIdx.x;
    const float* xr = x + (size_t)row * E_;

    float4 v = *(const float4*)&xr[t * 4];
    float s  = v.x + v.y + v.z + v.w;
    float ss = v.x * v.x + v.y * v.y + v.z * v.z + v.w * v.w;

    #pragma unroll
    for (int o = 16; o; o >>= 1) {
        s  += __shfl_xor_sync(0xFFFFFFFFu, s,  o);
        ss += __shfl_xor_sync(0xFFFFFFFFu, ss, o);
    }
    if ((t & 31) == 0) { red_s[t >> 5] = s; red_ss[t >> 5] = ss; }
    __syncthreads();
    if (t < 32) {
        float s2  = (t < 8) ? red_s[t]  : 0.f;
        float ss2 = (t < 8) ? red_ss[t] : 0.f;
        #pragma unroll
        for (int o = 4; o; o >>= 1) {
            s2  += __shfl_xor_sync(0xFFFFFFFFu, s2,  o);
            ss2 += __shfl_xor_sync(0xFFFFFFFFu, ss2, o);
        }
        if (t == 0) { red_s[0] = s2; red_ss[0] = ss2; }
    }
    __syncthreads();

    const float inv_e = 1.f / (float)E_;
    float mu  = red_s[0] * inv_e;
    float var = red_ss[0] * inv_e - mu * mu;
    float r   = rsqrtf(var + 1e-6f);

    float4 sc = *(const float4*)&scale[t * 4];
    const size_t base = (size_t)row * E_ + t * 4;
    *(uint32_t*)&a0[base]     = pack2h((v.x - mu) * r * sc.x,
                                       (v.y - mu) * r * sc.y);
    *(uint32_t*)&a0[base + 2] = pack2h((v.z - mu) * r * sc.z,
                                       (v.w - mu) * r * sc.w);
}

// ---------------------------------------------------------------------------
// Kernel 2: plain fp16 HMMA GEMM: C = A*B  (A [M,K] fp16, B [N,K] K-major).
// GBK=64 K-chunks: 4 ks-iterations (64 MMAs/warp) per single barrier.
// 3-stage cp.async pipeline (2 tiles x 16KB per stage = 96 KB total).
// MODE 0: fp32 C store. MODE 1 (QKV): scatter to single-fp16 attention
// operands — Q/K [bh][s][d], V [bh][d][s] (transposed).
// ---------------------------------------------------------------------------
#define GBM 128
#define GBN 128
#define GBK 64
#define TILE_B   16384                // 128 rows x 64 fp16 (128-B rows)
#define STAGE_B  (2 * TILE_B)         // A | B
#define GSM_TOTAL (3 * STAGE_B)       // 96 KB, 3 stages

template <int MODE>
__global__ __launch_bounds__(256, 2)
void mma_gemm_kernel(const __half* __restrict__ A,
                     const __half* __restrict__ B,
                     float* __restrict__ C,
                     __half* __restrict__ oQ0,
                     __half* __restrict__ oK0, __half* __restrict__ oV0,
                     int N, int K) {
    extern __shared__ char sm[];
    const uint32_t smb = smem_u32(sm);

    const int tid  = threadIdx.x;
    const int lane = tid & 31;
    const int wid  = tid >> 5;
    const int wm   = wid & 3;
    const int wn   = wid >> 2;
    const int blockRow = blockIdx.y * GBM;
    const int blockCol = blockIdx.x * GBN;

    float acc[2][8][4];
    #pragma unroll
    for (int i = 0; i < 2; i++)
        #pragma unroll
        for (int j = 0; j < 8; j++)
            #pragma unroll
            for (int q = 0; q < 4; q++) acc[i][j][q] = 0.f;

    // Per-thread load coords: 4 chunks per tile per stage (1024 chunks/tile)
    const int lr[4] = { (tid + 0) >> 3, (tid + 256) >> 3,
                        (tid + 512) >> 3, (tid + 768) >> 3 };
    const int lc[4] = { (tid + 0) & 7, (tid + 256) & 7,
                        (tid + 512) & 7, (tid + 768) & 7 };
    uint32_t lso[4];
    #pragma unroll
    for (int i = 0; i < 4; i++) lso[i] = s128(lr[i], lc[i]);

    const int NCH = K / GBK;               // 16

    // Prologue: stages 0 and 1 (chunks 0 and 1), separate commit groups
    #pragma unroll
    for (int st = 0; st < 2; st++) {
        const uint32_t sb = smb + st * STAGE_B;
        const int kb = st * GBK;
        #pragma unroll
        for (int i = 0; i < 4; i++) {
            cp16(sb + lso[i],
                 A + (size_t)(blockRow + lr[i]) * K + kb + lc[i] * 8);
            cp16(sb + TILE_B + lso[i],
                 B + (size_t)(blockCol + lr[i]) * K + kb + lc[i] * 8);
        }
        CP_COMMIT();
    }

    const int rA = wm * 32 + (lane & 15);
    const int cAbase = lane >> 4;
    const int rB = wn * 64 + (lane & 7) + ((lane >> 4) << 3);
    const int cBbase = (lane >> 3) & 1;

    for (int ch = 0; ch < NCH; ch++) {
        if (ch + 1 < NCH) { CP_WAIT(1); } else { CP_WAIT(0); }
        __syncthreads();    // publish stage ch + prove compute ch-1 done

        if (ch + 2 < NCH) {
            const uint32_t sb = smb + ((ch + 2) % 3) * STAGE_B;
            const int kb = (ch + 2) * GBK;
            #pragma unroll
            for (int i = 0; i < 4; i++) {
                cp16(sb + lso[i],
                     A + (size_t)(blockRow + lr[i]) * K + kb + lc[i] * 8);
                cp16(sb + TILE_B + lso[i],
                     B + (size_t)(blockCol + lr[i]) * K + kb + lc[i] * 8);
            }
            CP_COMMIT();
        }

        const uint32_t sA = smb + (ch % 3) * STAGE_B;
        const uint32_t sB = sA + TILE_B;

        #pragma unroll
        for (int ks = 0; ks < 4; ks++) {
            const int cA = ks * 2 + cAbase;
            const int cB = ks * 2 + cBbase;
            uint32_t af[2][4];
            #pragma unroll
            for (int fm = 0; fm < 2; fm++)
                ldsm4(af[fm], sA + s128(rA + fm * 16, cA));
            uint32_t bf[4][4];
            #pragma unroll
            for (int p = 0; p < 4; p++)
                ldsm4(bf[p], sB + s128(rB + p * 16, cB));
            #pragma unroll
            for (int fm = 0; fm < 2; fm++)
                #pragma unroll
                for (int fn = 0; fn < 8; fn++)
                    mma_f16(acc[fm][fn], af[fm], &bf[fn >> 1][(fn & 1) * 2]);
        }
        // no trailing barrier: next iteration's barrier protects stage reuse
    }

    if (MODE == 0) {
        // fp32 C store
        #pragma unroll
        for (int fm = 0; fm < 2; fm++) {
            const int rr = blockRow + wm * 32 + fm * 16 + (lane >> 2);
            #pragma unroll
            for (int fn = 0; fn < 8; fn++) {
                const int cc = blockCol + wn * 64 + fn * 8 + (lane & 3) * 2;
                *(float2*)&C[(size_t)rr * N + cc] =
                    make_float2(acc[fm][fn][0], acc[fm][fn][1]);
                *(float2*)&C[(size_t)(rr + 8) * N + cc] =
                    make_float2(acc[fm][fn][2], acc[fm][fn][3]);
            }
        }
    } else {
        // QKV scatter: part uniform per CTA (1024 | 128*gridX boundaries)
        const int part = blockCol >> 10;   // 0=q, 1=k, 2=v
        #pragma unroll
        for (int fm = 0; fm < 2; fm++) {
            const int rbase = blockRow + wm * 32 + fm * 16 + (lane >> 2);
            #pragma unroll
            for (int fn = 0; fn < 8; fn++) {
                const int cc = blockCol + wn * 64 + fn * 8 + (lane & 3) * 2;
                const int h = (cc >> 6) & 15;
                const int d = cc & 63;
                #pragma unroll
                for (int hf = 0; hf < 2; hf++) {
                    const int rr = rbase + hf * 8;
                    const int s = rr >> 1, b = rr & 1;
                    const int bh = b * 16 + h;
                    const float x0 = acc[fm][fn][hf * 2];
                    const float x1 = acc[fm][fn][hf * 2 + 1];
                    if (part == 0) {
                        size_t off = ((size_t)bh * S_ + s) * D_ + d;
                        *(uint32_t*)&oQ0[off] = pack2h(x0, x1);
                    } else if (part == 1) {
                        size_t off = ((size_t)bh * S_ + s) * D_ + d;
                        *(uint32_t*)&oK0[off] = pack2h(x0, x1);
                    } else {
                        size_t offa = ((size_t)bh * D_ + d) * S_ + s;
                        size_t offb = ((size_t)bh * D_ + d + 1) * S_ + s;
                        oV0[offa] = __float2half_rn(x0);
                        oV0[offb] = __float2half_rn(x1);
                    }
                }
            }
        }
    }
}

// ---------------------------------------------------------------------------
// Kernel 3: fp16 tensor-core flash attention, single product per stage.
// Grid (S/128, 32 bh). 256 threads = 8 warps; warp w owns q rows [16w,16w+16).
// QK^T = Q*K.  PV = P*V (P packed from C-frags).
// K/V tiles (16 KB/stage) double-buffered via cp.async; single barrier/tile.
// Epilogue: single-fp16 ctx for the plain-fp16 out-projection.
// ---------------------------------------------------------------------------
#define AQT 128
#define ASM_STAGE 16384     // K | V, each 8 KB
#define ASM_Q 32768
#define ASM_TOTAL 49152     // 48 KB

__global__ __launch_bounds__(256)
void attn_mma_kernel(const __half* __restrict__ Qh,
                     const __half* __restrict__ Kh,
                     const __half* __restrict__ Vh,
                     __half* __restrict__ c0) {
    extern __shared__ char sm[];
    const uint32_t smb = smem_u32(sm);
    const int tid  = threadIdx.x;
    const int lane = tid & 31;
    const int wq   = tid >> 5;               // 0..7
    const int bh   = blockIdx.y;             // b*16 + h
    const int qb   = blockIdx.x * AQT;
    const size_t kbase = (size_t)bh * S_ * D_;   // Q/K [bh][s][d]
    const size_t vbase = (size_t)bh * D_ * S_;   // V  [bh][d][s]

    // Stage Q tile [128][64] fp16 (group 0)
    #pragma unroll
    for (int i = 0; i < 4; i++) {
        int idx = tid + i * 256;             // 0..1023
        int r = idx >> 3, c = idx & 7;
        cp16(smb + ASM_Q + s128(r, c),
             Qh + kbase + (size_t)(qb + r) * D_ + c * 8);
    }
    CP_COMMIT();
    // Key tile 0 (group 1): K [64][64], V [64][64]
    #pragma unroll
    for (int i = 0; i < 2; i++) {
        int idx = tid + i * 256;             // 0..511
        int r = idx >> 3, c = idx & 7;
        uint32_t so = s128(r, c);
        cp16(smb + so,        Kh + kbase + (size_t)r * D_ + c * 8);
        cp16(smb + 8192 + so, Vh + vbase + (size_t)r * S_ + c * 8);
    }
    CP_COMMIT();
    CP_WAIT(1);        // Q resident (tile 0 may still be in flight)
    __syncthreads();

    // Q fragments (held for the whole kernel)
    uint32_t qf[4][4];
    {
        const int rA = wq * 16 + (lane & 15);
        const int cA = lane >> 4;
        #pragma unroll
        for (int t = 0; t < 4; t++)
            ldsm4(qf[t], smb + ASM_Q + s128(rA, t * 2 + cA));
    }

    float acc[8][4];
    #pragma unroll
    for (int j = 0; j < 8; j++)
        #pragma unroll
        for (int q = 0; q < 4; q++) acc[j][q] = 0.f;
    float mrow[2] = {-1e30f, -1e30f};
    float lrow[2] = {0.f, 0.f};

    const int rB = (lane & 7) + ((lane >> 4) << 3);
    const int cB = (lane >> 3) & 1;
    const int NKT = S_ / 64;                 // 32 key tiles

    for (int kc = 0; kc < NKT; kc++) {
        CP_WAIT(0);         // stage kc ready (own groups)
        __syncthreads();    // publish stage kc + prove compute kc-1 done

        if (kc + 1 < NKT) {
            const uint32_t sb = smb + ((kc + 1) & 1) * ASM_STAGE;
            #pragma unroll
            for (int i = 0; i < 2; i++) {
                int idx = tid + i * 256;
                int r = idx >> 3, c = idx & 7;
                uint32_t so = s128(r, c);
                cp16(sb + so,
                     Kh + kbase + (size_t)((kc + 1) * 64 + r) * D_ + c * 8);
                cp16(sb + 8192 + so,
                     Vh + vbase + (size_t)r * S_ + (kc + 1) * 64 + c * 8);
            }
            CP_COMMIT();
        }
        const uint32_t sb = smb + (kc & 1) * ASM_STAGE;

        // ---- Scores: s[16q x 64k] over d=64, single product ----
        float sc[8][4];
        #pragma unroll
        for (int j = 0; j < 8; j++)
            #pragma unroll
            for (int q = 0; q < 4; q++) sc[j][q] = 0.f;

        #pragma unroll
        for (int t = 0; t < 4; t++) {
            #pragma unroll
            for (int jj = 0; jj < 4; jj++) {
                uint32_t k0f[4];
                ldsm4(k0f, sb + s128(jj * 16 + rB, t * 2 + cB));
                mma_f16(sc[2 * jj],     qf[t], &k0f[0]);
                mma_f16(sc[2 * jj + 1], qf[t], &k0f[2]);
            }
        }

        // ---- Online softmax on fragments (rows r=lane>>2 and r+8) ----
        #pragma unroll
        for (int h2 = 0; h2 < 2; h2++) {
            float rm = sc[0][2 * h2];
            #pragma unroll
            for (int j = 0; j < 8; j++) {
                rm = fmaxf(rm, sc[j][2 * h2]);
                rm = fmaxf(rm, sc[j][2 * h2 + 1]);
            }
            rm = fmaxf(rm, __shfl_xor_sync(0xFFFFFFFFu, rm, 1));
            rm = fmaxf(rm, __shfl_xor_sync(0xFFFFFFFFu, rm, 2));
            float mnew = fmaxf(mrow[h2], rm);
            float al   = __expf(mrow[h2] - mnew);
            mrow[h2] = mnew;
            float rs = 0.f;
            #pragma unroll
            for (int j = 0; j < 8; j++) {
                float p0 = __expf(sc[j][2 * h2]     - mnew);
                float p1 = __expf(sc[j][2 * h2 + 1] - mnew);
                sc[j][2 * h2]     = p0;
                sc[j][2 * h2 + 1] = p1;
                rs += p0 + p1;
            }
            rs += __shfl_xor_sync(0xFFFFFFFFu, rs, 1);
            rs += __shfl_xor_sync(0xFFFFFFFFu, rs, 2);
            lrow[h2] = lrow[h2] * al + rs;
            #pragma unroll
            for (int j = 0; j < 8; j++) {
                acc[j][2 * h2]     *= al;
                acc[j][2 * h2 + 1] *= al;
            }
        }

        // ---- PV: ctx += P * V, single product; P packed from C-frags ----
        #pragma unroll
        for (int t2 = 0; t2 < 4; t2++) {
            uint32_t ah[4];
            ah[0] = pack2h(sc[2 * t2][0],     sc[2 * t2][1]);
            ah[1] = pack2h(sc[2 * t2][2],     sc[2 * t2][3]);
            ah[2] = pack2h(sc[2 * t2 + 1][0], sc[2 * t2 + 1][1]);
            ah[3] = pack2h(sc[2 * t2 + 1][2], sc[2 * t2 + 1][3]);
            #pragma unroll
            for (int jj = 0; jj < 4; jj++) {
                uint32_t v0f[4];
                ldsm4(v0f, sb + 8192 + s128(jj * 16 + rB, t2 * 2 + cB));
                mma_f16(acc[2 * jj],     ah, &v0f[0]);
                mma_f16(acc[2 * jj + 1], ah, &v0f[2]);
            }
        }
        // no trailing barrier: next iteration's barrier protects stage reuse
    }

    // ---- Epilogue: normalize, single fp16 into c0 [NROWS][HD] ----
    const int b = bh >> 4, h = bh & 15;
    const float inv0 = 1.f / lrow[0];
    const float inv1 = 1.f / lrow[1];
    const int r  = lane >> 2;
    const int c2 = (lane & 3) * 2;
    #pragma unroll
    for (int j = 0; j < 8; j++) {
        const int d = j * 8 + c2;
        const int qg = qb + wq * 16 + r;
        size_t off0 = (size_t)(qg * 2 + b) * HD_ + h * 64 + d;
        size_t off1 = (size_t)((qg + 8) * 2 + b) * HD_ + h * 64 + d;
        *(uint32_t*)&c0[off0] = pack2h(acc[j][0] * inv0, acc[j][1] * inv0);
        *(uint32_t*)&c0[off1] = pack2h(acc[j][2] * inv1, acc[j][3] * inv1);
    }
}

// ---------------------------------------------------------------------------
// kernel_launch
// ---------------------------------------------------------------------------
extern "C" void kernel_launch(void* const* d_in, const int* in_sizes, int n_in,
                              void* d_out, int out_size) {
    const float* x        = (const float*)d_in[0];   // [S,B,E]
    const float* ln_scale = (const float*)d_in[1];   // [E]
    const float* w_qkv    = (const float*)d_in[2];   // [E, 3*H*D]
    const float* w_out    = (const float*)d_in[3];   // [H*D, E]
    float* out = (float*)d_out;                      // [S,B,E]

    __half *p_a0, *p_wq, *p_wo;
    __half *pQ0, *pK0, *pV0, *p_c0;
    cudaGetSymbolAddress((void**)&p_a0, g_a0);
    cudaGetSymbolAddress((void**)&p_wq, g_wq);
    cudaGetSymbolAddress((void**)&p_wo, g_wo);
    cudaGetSymbolAddress((void**)&pQ0,  g_q0);
    cudaGetSymbolAddress((void**)&pK0,  g_k0);
    cudaGetSymbolAddress((void**)&pV0,  g_v0);
    cudaGetSymbolAddress((void**)&p_c0, g_c0);

    cudaFuncSetAttribute(mma_gemm_kernel<0>,
                         cudaFuncAttributeMaxDynamicSharedMemorySize, GSM_TOTAL);
    cudaFuncSetAttribute(mma_gemm_kernel<1>,
                         cudaFuncAttributeMaxDynamicSharedMemorySize, GSM_TOTAL);
    cudaFuncSetAttribute(attn_mma_kernel,
                         cudaFuncAttributeMaxDynamicSharedMemorySize, ASM_TOTAL);

    // 1. Fused preprocessing: LayerNorm->fp16 and both weight transposes
    pre_kernel<<<NROWS + 3072 + 1024, 256>>>(
        x, ln_scale, p_a0, w_qkv, p_wq, w_out, p_wo);

    // 2. QKV projection -> single-fp16 attention operands (V transposed)
    mma_gemm_kernel<1><<<dim3(Q3_ / GBN, NROWS / GBM), 256, GSM_TOTAL>>>(
        p_a0, p_wq, nullptr, pQ0, pK0, pV0, Q3_, E_);

    // 3. fp16 tensor-core flash attention
    attn_mma_kernel<<<dim3(S_ / AQT, BH_), 256, ASM_TOTAL>>>(
        pQ0, pK0, pV0, p_c0);

    // 4. Output projection (fp32 out)
    mma_gemm_kernel<0><<<dim3(E_ / GBN, NROWS / GBM), 256, GSM_TOTAL>>>(
        p_c0, p_wo, out, nullptr, nullptr, nullptr, E_, HD_);
}